// round 1
// baseline (speedup 1.0000x reference)
#include <cuda_runtime.h>
#include <math.h>

#define BATCH 4
#define CCH   256
#define CI    128
#define NPIX  4096
#define GROUPS 8
#define CPG   32
#define GSIZE (CPG*NPIX)      // 131072 elements per (batch, group)
#define EPSV  1e-5f

// ---------------- scratch (static device globals; no allocation) -------------
__device__ float d_xs   [BATCH*CCH*NPIX];   // conv out -> normalized xs (in place)
__device__ float d_theta[BATCH*CI*NPIX];    // [b][c][n]
__device__ float d_phi  [BATCH*CI*NPIX];    // [b][c][n]
__device__ float d_g    [BATCH*CI*NPIX];    // [b][c][n]
__device__ float d_y    [BATCH*NPIX*CI];    // [b][n][c]
__device__ float d_z    [BATCH*CCH*NPIX];   // [b][c][n]
__device__ float d_wpack[CCH*9*CCH];        // [cin*9+tap][cout]
__device__ float d_st1  [BATCH*GROUPS*2];
__device__ float d_st2  [BATCH*GROUPS*2];

// ---------------- weight repack for conv: [o][c][tap] -> [c*9+tap][o] --------
__global__ void pack_w_kernel(const float* __restrict__ w) {
    int idx = blockIdx.x * blockDim.x + threadIdx.x;   // over 256*9*256
    if (idx >= CCH*9*CCH) return;
    int o = idx & 255;
    int r = idx >> 8;                                  // r = c*9 + tap
    d_wpack[idx] = w[o*(CCH*9) + r];
}

// ---------------- conv3x3 SAME, bias, writes d_xs ----------------------------
// grid (4 oc-tiles, 64 h, 4 b), 256 threads; tile = 64 oc x 64 w (one row)
__global__ void conv3x3_kernel(const float* __restrict__ x,
                               const float* __restrict__ sb) {
    __shared__ float xsm[8*3*66];     // 8 in-ch, 3 rows, 66 (padded) cols
    __shared__ float wsm[72*66];      // [c*9+tap][64 oc] stride 66

    int b   = blockIdx.z;
    int h   = blockIdx.y;
    int oc0 = blockIdx.x * 64;
    int tid = threadIdx.x;
    int to  = tid >> 4;               // 0..15 : oc group (4 oc each)
    int tw  = tid & 15;               // 0..15 : w group (4 px each)

    const float* xb = x + (size_t)b * CCH * NPIX;
    float acc[4][4];
    #pragma unroll
    for (int i = 0; i < 4; i++)
        #pragma unroll
        for (int j = 0; j < 4; j++) acc[i][j] = 0.f;

    for (int c0 = 0; c0 < CCH; c0 += 8) {
        __syncthreads();
        // load x slab: channels c0..c0+7, rows h-1..h+1, cols -1..64
        for (int idx = tid; idx < 8*3*66; idx += 256) {
            int c   = idx / 198;
            int rem = idx - c*198;
            int ry  = rem / 66;
            int wx  = rem - ry*66;
            int hy  = h + ry - 1;
            int wxx = wx - 1;
            float v = 0.f;
            if (hy >= 0 && hy < 64 && wxx >= 0 && wxx < 64)
                v = xb[(c0 + c)*NPIX + hy*64 + wxx];
            xsm[idx] = v;
        }
        // load packed weights: 72 (c,tap) rows x 64 oc
        for (int idx = tid; idx < 72*64; idx += 256) {
            int o = idx & 63;
            int r = idx >> 6;
            wsm[r*66 + o] = d_wpack[(c0*9 + r)*256 + oc0 + o];
        }
        __syncthreads();

        #pragma unroll
        for (int c = 0; c < 8; c++) {
            #pragma unroll
            for (int ky = 0; ky < 3; ky++) {
                const float* xr = &xsm[(c*3 + ky)*66 + (tw << 2)];
                float xv[6];
                #pragma unroll
                for (int l = 0; l < 6; l++) xv[l] = xr[l];
                #pragma unroll
                for (int kx = 0; kx < 3; kx++) {
                    const float* wr = &wsm[(c*9 + ky*3 + kx)*66 + (to << 2)];
                    float2 wa = *(const float2*)wr;
                    float2 wb = *(const float2*)(wr + 2);
                    float w0 = wa.x, w1 = wa.y, w2 = wb.x, w3 = wb.y;
                    #pragma unroll
                    for (int j = 0; j < 4; j++) {
                        float xx = xv[kx + j];
                        acc[0][j] += w0 * xx;
                        acc[1][j] += w1 * xx;
                        acc[2][j] += w2 * xx;
                        acc[3][j] += w3 * xx;
                    }
                }
            }
        }
    }

    #pragma unroll
    for (int i = 0; i < 4; i++) {
        int oc = oc0 + (to << 2) + i;
        float bias = sb[oc];
        float4 v = make_float4(acc[i][0] + bias, acc[i][1] + bias,
                               acc[i][2] + bias, acc[i][3] + bias);
        *(float4*)&d_xs[((size_t)(b*CCH + oc))*NPIX + h*64 + (tw << 2)] = v;
    }
}

// ---------------- GroupNorm stats: one block per (b,g) -----------------------
__global__ void gn_stats_kernel(int which) {
    const float* src = which ? d_z : d_xs;
    float* st        = which ? d_st2 : d_st1;
    int blk = blockIdx.x;  // = b*8 + g (group channels contiguous)
    const float4* p = (const float4*)(src + (size_t)blk * GSIZE);
    float s = 0.f, s2 = 0.f;
    for (int i = threadIdx.x; i < GSIZE/4; i += 256) {
        float4 v = p[i];
        s  += v.x + v.y + v.z + v.w;
        s2 += v.x*v.x + v.y*v.y + v.z*v.z + v.w*v.w;
    }
    #pragma unroll
    for (int off = 16; off > 0; off >>= 1) {
        s  += __shfl_xor_sync(0xffffffffu, s,  off);
        s2 += __shfl_xor_sync(0xffffffffu, s2, off);
    }
    __shared__ float sh[16];
    int wid = threadIdx.x >> 5, lid = threadIdx.x & 31;
    if (lid == 0) { sh[wid] = s; sh[wid + 8] = s2; }
    __syncthreads();
    if (threadIdx.x == 0) {
        float S = 0.f, S2 = 0.f;
        #pragma unroll
        for (int w = 0; w < 8; w++) { S += sh[w]; S2 += sh[w + 8]; }
        float mean = S / (float)GSIZE;
        float var  = S2 / (float)GSIZE - mean * mean;
        st[blk*2]     = mean;
        st[blk*2 + 1] = rsqrtf(var + EPSV);
    }
}

// ---------------- GN1 apply + ReLU (in place on d_xs) ------------------------
__global__ void gn1_apply_kernel(const float* __restrict__ gw,
                                 const float* __restrict__ gb) {
    int i4 = blockIdx.x * blockDim.x + threadIdx.x;   // over 1048576
    if (i4 >= BATCH*CCH*NPIX/4) return;
    int idx = i4 << 2;
    int c   = (idx >> 12) & 255;
    int bg  = idx >> 17;
    float mean = d_st1[bg*2], rstd = d_st1[bg*2 + 1];
    float sc = rstd * gw[c];
    float sh = gb[c] - mean * sc;
    float4 v = ((float4*)d_xs)[i4];
    v.x = fmaxf(v.x*sc + sh, 0.f);
    v.y = fmaxf(v.y*sc + sh, 0.f);
    v.z = fmaxf(v.z*sc + sh, 0.f);
    v.w = fmaxf(v.w*sc + sh, 0.f);
    ((float4*)d_xs)[i4] = v;
}

// ---------------- GEMM: out[b][m][n] = W[m][k] * X[b][k][n] + bias -----------
// MODE 0/1/2: X = d_xs (K=256, [k][n]),  out = theta/phi/g (M=128)
// MODE 3:     X = d_y  (K=128, [n][k]),  out = d_z (M=256)
template<int MODE>
__global__ void gemm64_kernel(const float* __restrict__ W,
                              const float* __restrict__ bias) {
    constexpr int M  = (MODE == 3) ? 256 : 128;
    constexpr int K  = (MODE == 3) ? 128 : 256;
    constexpr bool XT = (MODE == 3);
    const float* X = (MODE == 3) ? d_y : d_xs;
    float* out = (MODE == 0) ? d_theta : (MODE == 1) ? d_phi
               : (MODE == 2) ? d_g : d_z;

    __shared__ float Ws[64*17];
    __shared__ float Xs[16*68];

    int b  = blockIdx.z;
    int n0 = blockIdx.x * 64;
    int m0 = blockIdx.y * 64;
    const float* Xb = X + (size_t)b * K * NPIX;
    float* Ob = out + (size_t)b * M * NPIX;
    int tid = threadIdx.x;
    int tm = tid >> 4, tn = tid & 15;

    float acc[4][4];
    #pragma unroll
    for (int i = 0; i < 4; i++)
        #pragma unroll
        for (int j = 0; j < 4; j++) acc[i][j] = 0.f;

    for (int k0 = 0; k0 < K; k0 += 16) {
        __syncthreads();
        #pragma unroll
        for (int it = 0; it < 4; it++) {
            int idx = tid + it*256;
            int mm = idx >> 4, kk = idx & 15;
            Ws[mm*17 + kk] = W[(m0 + mm)*K + k0 + kk];
        }
        #pragma unroll
        for (int it = 0; it < 4; it++) {
            int idx = tid + it*256;
            if (XT) {
                int nn = idx >> 4, kk = idx & 15;
                Xs[kk*68 + nn] = Xb[(size_t)(n0 + nn)*K + k0 + kk];
            } else {
                int kk = idx >> 6, nn = idx & 63;
                Xs[kk*68 + nn] = Xb[(size_t)(k0 + kk)*NPIX + n0 + nn];
            }
        }
        __syncthreads();
        #pragma unroll
        for (int kk = 0; kk < 16; kk++) {
            float a0 = Ws[((tm<<2)+0)*17 + kk];
            float a1 = Ws[((tm<<2)+1)*17 + kk];
            float a2 = Ws[((tm<<2)+2)*17 + kk];
            float a3 = Ws[((tm<<2)+3)*17 + kk];
            float4 bx = *(const float4*)&Xs[kk*68 + (tn<<2)];
            acc[0][0] += a0*bx.x; acc[0][1] += a0*bx.y; acc[0][2] += a0*bx.z; acc[0][3] += a0*bx.w;
            acc[1][0] += a1*bx.x; acc[1][1] += a1*bx.y; acc[1][2] += a1*bx.z; acc[1][3] += a1*bx.w;
            acc[2][0] += a2*bx.x; acc[2][1] += a2*bx.y; acc[2][2] += a2*bx.z; acc[2][3] += a2*bx.w;
            acc[3][0] += a3*bx.x; acc[3][1] += a3*bx.y; acc[3][2] += a3*bx.z; acc[3][3] += a3*bx.w;
        }
    }
    #pragma unroll
    for (int i = 0; i < 4; i++) {
        int m = m0 + (tm<<2) + i;
        float bv = bias[m];
        float4 v = make_float4(acc[i][0]+bv, acc[i][1]+bv, acc[i][2]+bv, acc[i][3]+bv);
        *(float4*)&Ob[(size_t)m*NPIX + n0 + (tn<<2)] = v;
    }
}

// ---------------- flash attention: y[b][n][c] = softmax(theta^T phi) g^T -----
// grid (64 n-tiles, 4 b), 256 threads. n-tile = 64 rows.
__global__ void attention_kernel() {
    __shared__ float Qs[32*64];     // theta chunk [32c][64n]
    __shared__ float KG[64*68];     // phi chunk [32c][64m] (first 2048) / g [64m][64c+pad]
    __shared__ float Ps[64*65];     // P tile exchange

    int b  = blockIdx.y;
    int n0 = blockIdx.x * 64;
    const float* Tb = d_theta + (size_t)b * CI * NPIX;
    const float* Fb = d_phi   + (size_t)b * CI * NPIX;
    const float* Gb = d_g     + (size_t)b * CI * NPIX;
    float* Yb = d_y + (size_t)b * NPIX * CI;

    int tid = threadIdx.x;
    int tr = tid >> 4, tc = tid & 15;   // rows: tr*4+i (n), cols: tn*4+j (m)

    float O[4][8];
    #pragma unroll
    for (int i = 0; i < 4; i++)
        #pragma unroll
        for (int j = 0; j < 8; j++) O[i][j] = 0.f;
    float Mx[4] = {-1e30f, -1e30f, -1e30f, -1e30f};
    float L [4] = {0.f, 0.f, 0.f, 0.f};

    for (int m0 = 0; m0 < NPIX; m0 += 64) {
        // ---- S = theta^T phi  (64n x 64m), c chunked by 32 ----
        float s[4][4];
        #pragma unroll
        for (int i = 0; i < 4; i++)
            #pragma unroll
            for (int j = 0; j < 4; j++) s[i][j] = 0.f;

        for (int cc = 0; cc < 4; cc++) {
            __syncthreads();
            #pragma unroll
            for (int it = 0; it < 8; it++) {
                int idx = tid + it*256;
                int c = idx >> 6, nn = idx & 63;
                Qs[idx] = Tb[(size_t)(cc*32 + c)*NPIX + n0 + nn];
                KG[idx] = Fb[(size_t)(cc*32 + c)*NPIX + m0 + nn];
            }
            __syncthreads();
            #pragma unroll 8
            for (int c = 0; c < 32; c++) {
                float4 qa = *(const float4*)&Qs[c*64 + (tr << 2)];
                float4 kb = *(const float4*)&KG[c*64 + (tc << 2)];
                s[0][0] += qa.x*kb.x; s[0][1] += qa.x*kb.y; s[0][2] += qa.x*kb.z; s[0][3] += qa.x*kb.w;
                s[1][0] += qa.y*kb.x; s[1][1] += qa.y*kb.y; s[1][2] += qa.y*kb.z; s[1][3] += qa.y*kb.w;
                s[2][0] += qa.z*kb.x; s[2][1] += qa.z*kb.y; s[2][2] += qa.z*kb.z; s[2][3] += qa.z*kb.w;
                s[3][0] += qa.w*kb.x; s[3][1] += qa.w*kb.y; s[3][2] += qa.w*kb.z; s[3][3] += qa.w*kb.w;
            }
        }

        // ---- online softmax (row reductions across the 16 tc lanes) ----
        float p[4][4];
        #pragma unroll
        for (int i = 0; i < 4; i++) {
            float rm = fmaxf(fmaxf(s[i][0], s[i][1]), fmaxf(s[i][2], s[i][3]));
            #pragma unroll
            for (int off = 8; off > 0; off >>= 1)
                rm = fmaxf(rm, __shfl_xor_sync(0xffffffffu, rm, off));
            float nm = fmaxf(Mx[i], rm);
            float scale = __expf(Mx[i] - nm);
            float rs = 0.f;
            #pragma unroll
            for (int j = 0; j < 4; j++) {
                p[i][j] = __expf(s[i][j] - nm);
                rs += p[i][j];
            }
            #pragma unroll
            for (int off = 8; off > 0; off >>= 1)
                rs += __shfl_xor_sync(0xffffffffu, rs, off);
            L[i] = L[i]*scale + rs;
            Mx[i] = nm;
            #pragma unroll
            for (int j = 0; j < 8; j++) O[i][j] *= scale;
        }
        #pragma unroll
        for (int i = 0; i < 4; i++)
            #pragma unroll
            for (int j = 0; j < 4; j++)
                Ps[((tr<<2)+i)*65 + (tc<<2) + j] = p[i][j];
        __syncthreads();

        // ---- O += P g^T, c chunked by 64 ----
        for (int cc2 = 0; cc2 < 2; cc2++) {
            #pragma unroll
            for (int it = 0; it < 16; it++) {
                int idx = tid + it*256;
                int m = idx & 63, cl = idx >> 6;
                KG[m*68 + cl] = Gb[(size_t)(cc2*64 + cl)*NPIX + m0 + m];
            }
            __syncthreads();
            #pragma unroll 4
            for (int m = 0; m < 64; m++) {
                float pv0 = Ps[((tr<<2)+0)*65 + m];
                float pv1 = Ps[((tr<<2)+1)*65 + m];
                float pv2 = Ps[((tr<<2)+2)*65 + m];
                float pv3 = Ps[((tr<<2)+3)*65 + m];
                float4 gv = *(const float4*)&KG[m*68 + (tc << 2)];
                int jb = cc2 << 2;
                O[0][jb+0] += pv0*gv.x; O[0][jb+1] += pv0*gv.y; O[0][jb+2] += pv0*gv.z; O[0][jb+3] += pv0*gv.w;
                O[1][jb+0] += pv1*gv.x; O[1][jb+1] += pv1*gv.y; O[1][jb+2] += pv1*gv.z; O[1][jb+3] += pv1*gv.w;
                O[2][jb+0] += pv2*gv.x; O[2][jb+1] += pv2*gv.y; O[2][jb+2] += pv2*gv.z; O[2][jb+3] += pv2*gv.w;
                O[3][jb+0] += pv3*gv.x; O[3][jb+1] += pv3*gv.y; O[3][jb+2] += pv3*gv.z; O[3][jb+3] += pv3*gv.w;
            }
            __syncthreads();
        }
    }

    // ---- write y[n][c] (c = cc2*64 + tc*4 + jj) ----
    #pragma unroll
    for (int i = 0; i < 4; i++) {
        float inv = 1.0f / L[i];
        int n = n0 + (tr << 2) + i;
        #pragma unroll
        for (int cc2 = 0; cc2 < 2; cc2++) {
            float4 v = make_float4(O[i][cc2*4+0]*inv, O[i][cc2*4+1]*inv,
                                   O[i][cc2*4+2]*inv, O[i][cc2*4+3]*inv);
            *(float4*)&Yb[(size_t)n*CI + cc2*64 + (tc << 2)] = v;
        }
    }
}

// ---------------- final: out = GN2(z)*0.1 + xs -------------------------------
__global__ void final_apply_kernel(const float* __restrict__ gw,
                                   const float* __restrict__ gb,
                                   float* __restrict__ out) {
    int i4 = blockIdx.x * blockDim.x + threadIdx.x;
    if (i4 >= BATCH*CCH*NPIX/4) return;
    int idx = i4 << 2;
    int c   = (idx >> 12) & 255;
    int bg  = idx >> 17;
    float mean = d_st2[bg*2], rstd = d_st2[bg*2 + 1];
    float sc = rstd * gw[c];
    float sh = gb[c] - mean * sc;
    float4 z = ((const float4*)d_z)[i4];
    float4 xs = ((const float4*)d_xs)[i4];
    float4 o;
    o.x = (z.x*sc + sh)*0.1f + xs.x;
    o.y = (z.y*sc + sh)*0.1f + xs.y;
    o.z = (z.z*sc + sh)*0.1f + xs.z;
    o.w = (z.w*sc + sh)*0.1f + xs.w;
    ((float4*)out)[i4] = o;
}

// ---------------- launch ------------------------------------------------------
extern "C" void kernel_launch(void* const* d_in, const int* in_sizes, int n_in,
                              void* d_out, int out_size) {
    const float* x    = (const float*)d_in[0];
    const float* sw   = (const float*)d_in[1];
    const float* sb   = (const float*)d_in[2];
    const float* gn1w = (const float*)d_in[3];
    const float* gn1b = (const float*)d_in[4];
    const float* g_w  = (const float*)d_in[5];
    const float* g_b  = (const float*)d_in[6];
    const float* th_w = (const float*)d_in[7];
    const float* th_b = (const float*)d_in[8];
    const float* ph_w = (const float*)d_in[9];
    const float* ph_b = (const float*)d_in[10];
    const float* w_w  = (const float*)d_in[11];
    const float* w_b  = (const float*)d_in[12];
    const float* gn2w = (const float*)d_in[13];
    const float* gn2b = (const float*)d_in[14];
    float* out = (float*)d_out;

    pack_w_kernel<<<(CCH*9*CCH + 255)/256, 256>>>(sw);
    conv3x3_kernel<<<dim3(4, 64, 4), 256>>>(x, sb);
    gn_stats_kernel<<<32, 256>>>(0);
    gn1_apply_kernel<<<(BATCH*CCH*NPIX/4 + 255)/256, 256>>>(gn1w, gn1b);

    gemm64_kernel<0><<<dim3(64, 2, 4), 256>>>(th_w, th_b);
    gemm64_kernel<1><<<dim3(64, 2, 4), 256>>>(ph_w, ph_b);
    gemm64_kernel<2><<<dim3(64, 2, 4), 256>>>(g_w, g_b);

    attention_kernel<<<dim3(64, 4), 256>>>();

    gemm64_kernel<3><<<dim3(64, 4, 4), 256>>>(w_w, w_b);
    gn_stats_kernel<<<32, 256>>>(1);
    final_apply_kernel<<<(BATCH*CCH*NPIX/4 + 255)/256, 256>>>(gn2w, gn2b, out);

    (void)in_sizes; (void)n_in; (void)out_size;
}

// round 2
// speedup vs baseline: 1.6504x; 1.6504x over previous
#include <cuda_runtime.h>
#include <math.h>

#define BATCH 4
#define CCH   256
#define CI    128
#define NPIX  4096
#define GROUPS 8
#define CPG   32
#define GSIZE (CPG*NPIX)
#define EPSV  1e-5f

// ---------------- scratch ----------------------------------------------------
__device__ float d_xs   [BATCH*CCH*NPIX];   // conv out -> normalized xs (in place)
__device__ float d_theta[BATCH*CI*NPIX];    // [b][c][n]
__device__ float d_phi  [BATCH*CI*NPIX];    // [b][c][n]
__device__ float d_g    [BATCH*CI*NPIX];    // [b][c][n]
__device__ float d_y    [BATCH*CI*NPIX];    // [b][c][n]  (c-major now)
__device__ float d_z    [BATCH*CCH*NPIX];   // [b][c][n]
__device__ float d_wpack[CCH*9*CCH];
__device__ float d_st1  [BATCH*GROUPS*2];
__device__ float d_st2  [BATCH*GROUPS*2];

// ---------------- tf32 helpers -----------------------------------------------
__device__ __forceinline__ unsigned f2tf(float f) {
    unsigned u;
    asm("cvt.rna.tf32.f32 %0, %1;" : "=r"(u) : "f"(f));
    return u;
}

__device__ __forceinline__ void mma_tf32(float* c,
    unsigned a0, unsigned a1, unsigned a2, unsigned a3,
    unsigned b0, unsigned b1) {
    asm volatile(
        "mma.sync.aligned.m16n8k8.row.col.f32.tf32.tf32.f32 "
        "{%0,%1,%2,%3}, {%4,%5,%6,%7}, {%8,%9}, {%0,%1,%2,%3};"
        : "+f"(c[0]), "+f"(c[1]), "+f"(c[2]), "+f"(c[3])
        : "r"(a0), "r"(a1), "r"(a2), "r"(a3), "r"(b0), "r"(b1));
}

// ---------------- weight repack for conv -------------------------------------
__global__ void pack_w_kernel(const float* __restrict__ w) {
    int idx = blockIdx.x * blockDim.x + threadIdx.x;
    if (idx >= CCH*9*CCH) return;
    int o = idx & 255;
    int r = idx >> 8;
    d_wpack[idx] = w[o*(CCH*9) + r];
}

// ---------------- conv3x3 SAME (fp32 SIMT, unchanged) ------------------------
__global__ void conv3x3_kernel(const float* __restrict__ x,
                               const float* __restrict__ sb) {
    __shared__ float xsm[8*3*66];
    __shared__ float wsm[72*66];

    int b   = blockIdx.z;
    int h   = blockIdx.y;
    int oc0 = blockIdx.x * 64;
    int tid = threadIdx.x;
    int to  = tid >> 4;
    int tw  = tid & 15;

    const float* xb = x + (size_t)b * CCH * NPIX;
    float acc[4][4];
    #pragma unroll
    for (int i = 0; i < 4; i++)
        #pragma unroll
        for (int j = 0; j < 4; j++) acc[i][j] = 0.f;

    for (int c0 = 0; c0 < CCH; c0 += 8) {
        __syncthreads();
        for (int idx = tid; idx < 8*3*66; idx += 256) {
            int c   = idx / 198;
            int rem = idx - c*198;
            int ry  = rem / 66;
            int wx  = rem - ry*66;
            int hy  = h + ry - 1;
            int wxx = wx - 1;
            float v = 0.f;
            if (hy >= 0 && hy < 64 && wxx >= 0 && wxx < 64)
                v = xb[(c0 + c)*NPIX + hy*64 + wxx];
            xsm[idx] = v;
        }
        for (int idx = tid; idx < 72*64; idx += 256) {
            int o = idx & 63;
            int r = idx >> 6;
            wsm[r*66 + o] = d_wpack[(c0*9 + r)*256 + oc0 + o];
        }
        __syncthreads();

        #pragma unroll
        for (int c = 0; c < 8; c++) {
            #pragma unroll
            for (int ky = 0; ky < 3; ky++) {
                const float* xr = &xsm[(c*3 + ky)*66 + (tw << 2)];
                float xv[6];
                #pragma unroll
                for (int l = 0; l < 6; l++) xv[l] = xr[l];
                #pragma unroll
                for (int kx = 0; kx < 3; kx++) {
                    const float* wr = &wsm[(c*9 + ky*3 + kx)*66 + (to << 2)];
                    float2 wa = *(const float2*)wr;
                    float2 wb = *(const float2*)(wr + 2);
                    #pragma unroll
                    for (int j = 0; j < 4; j++) {
                        float xx = xv[kx + j];
                        acc[0][j] += wa.x * xx;
                        acc[1][j] += wa.y * xx;
                        acc[2][j] += wb.x * xx;
                        acc[3][j] += wb.y * xx;
                    }
                }
            }
        }
    }

    #pragma unroll
    for (int i = 0; i < 4; i++) {
        int oc = oc0 + (to << 2) + i;
        float bias = sb[oc];
        float4 v = make_float4(acc[i][0] + bias, acc[i][1] + bias,
                               acc[i][2] + bias, acc[i][3] + bias);
        *(float4*)&d_xs[((size_t)(b*CCH + oc))*NPIX + h*64 + (tw << 2)] = v;
    }
}

// ---------------- GroupNorm stats --------------------------------------------
__global__ void gn_stats_kernel(int which) {
    const float* src = which ? d_z : d_xs;
    float* st        = which ? d_st2 : d_st1;
    int blk = blockIdx.x;
    const float4* p = (const float4*)(src + (size_t)blk * GSIZE);
    float s = 0.f, s2 = 0.f;
    for (int i = threadIdx.x; i < GSIZE/4; i += 256) {
        float4 v = p[i];
        s  += v.x + v.y + v.z + v.w;
        s2 += v.x*v.x + v.y*v.y + v.z*v.z + v.w*v.w;
    }
    #pragma unroll
    for (int off = 16; off > 0; off >>= 1) {
        s  += __shfl_xor_sync(0xffffffffu, s,  off);
        s2 += __shfl_xor_sync(0xffffffffu, s2, off);
    }
    __shared__ float sh[16];
    int wid = threadIdx.x >> 5, lid = threadIdx.x & 31;
    if (lid == 0) { sh[wid] = s; sh[wid + 8] = s2; }
    __syncthreads();
    if (threadIdx.x == 0) {
        float S = 0.f, S2 = 0.f;
        #pragma unroll
        for (int w = 0; w < 8; w++) { S += sh[w]; S2 += sh[w + 8]; }
        float mean = S / (float)GSIZE;
        float var  = S2 / (float)GSIZE - mean * mean;
        st[blk*2]     = mean;
        st[blk*2 + 1] = rsqrtf(var + EPSV);
    }
}

// ---------------- GN1 apply + ReLU -------------------------------------------
__global__ void gn1_apply_kernel(const float* __restrict__ gw,
                                 const float* __restrict__ gb) {
    int i4 = blockIdx.x * blockDim.x + threadIdx.x;
    if (i4 >= BATCH*CCH*NPIX/4) return;
    int idx = i4 << 2;
    int c   = (idx >> 12) & 255;
    int bg  = idx >> 17;
    float mean = d_st1[bg*2], rstd = d_st1[bg*2 + 1];
    float sc = rstd * gw[c];
    float sh = gb[c] - mean * sc;
    float4 v = ((float4*)d_xs)[i4];
    v.x = fmaxf(v.x*sc + sh, 0.f);
    v.y = fmaxf(v.y*sc + sh, 0.f);
    v.z = fmaxf(v.z*sc + sh, 0.f);
    v.w = fmaxf(v.w*sc + sh, 0.f);
    ((float4*)d_xs)[i4] = v;
}

// ---------------- tf32 tensor-core GEMM --------------------------------------
// out[b][m][n] = sum_k W[m][k] * X[b][k][n] + bias[m]
// MODE 0/1/2: X=d_xs K=256 M=128 -> theta/phi/g.  MODE 3: X=d_y K=128 M=256 -> z
template<int MODE>
__global__ void __launch_bounds__(256) gemm_tc_kernel(const float* __restrict__ W,
                                                      const float* __restrict__ bias) {
    constexpr int M = (MODE == 3) ? 256 : 128;
    constexpr int K = (MODE == 3) ? 128 : 256;
    const float* X = (MODE == 3) ? d_y : d_xs;
    float* out = (MODE == 0) ? d_theta : (MODE == 1) ? d_phi
               : (MODE == 2) ? d_g : d_z;

    __shared__ unsigned Ws[64*36];    // [m][k] pad 36
    __shared__ unsigned Xs[32*136];   // [k][n] pad 136

    int b  = blockIdx.z;
    int n0 = blockIdx.x * 128;
    int m0 = blockIdx.y * 64;
    const float* Xb = X + (size_t)b * K * NPIX;
    float* Ob = out + (size_t)b * M * NPIX;

    int tid  = threadIdx.x;
    int lane = tid & 31;
    int wid  = tid >> 5;
    int wm = wid >> 2, wn = wid & 3;   // warp tile 32m x 32n

    float C[8][4];
    #pragma unroll
    for (int i = 0; i < 8; i++)
        #pragma unroll
        for (int j = 0; j < 4; j++) C[i][j] = 0.f;

    for (int kc = 0; kc < K; kc += 32) {
        __syncthreads();
        #pragma unroll
        for (int it = 0; it < 8; it++) {
            int i = tid + it*256;
            int m = i >> 5, k = i & 31;
            Ws[m*36 + k] = f2tf(W[(m0 + m)*K + kc + k]);
        }
        #pragma unroll
        for (int it = 0; it < 16; it++) {
            int i = tid + it*256;
            int k = i >> 7, n = i & 127;
            Xs[k*136 + n] = f2tf(Xb[(size_t)(kc + k)*NPIX + n0 + n]);
        }
        __syncthreads();

        #pragma unroll
        for (int k8 = 0; k8 < 4; k8++) {
            unsigned a[2][4];
            #pragma unroll
            for (int mt = 0; mt < 2; mt++) {
                int mr = wm*32 + mt*16 + (lane >> 2);
                int kk = k8*8 + (lane & 3);
                a[mt][0] = Ws[mr*36 + kk];
                a[mt][1] = Ws[(mr+8)*36 + kk];
                a[mt][2] = Ws[mr*36 + kk + 4];
                a[mt][3] = Ws[(mr+8)*36 + kk + 4];
            }
            #pragma unroll
            for (int nt = 0; nt < 4; nt++) {
                int nn = wn*32 + nt*8 + (lane >> 2);
                unsigned b0 = Xs[(k8*8 + (lane & 3))*136 + nn];
                unsigned b1 = Xs[(k8*8 + (lane & 3) + 4)*136 + nn];
                mma_tf32(C[nt],     a[0][0], a[0][1], a[0][2], a[0][3], b0, b1);
                mma_tf32(C[4 + nt], a[1][0], a[1][1], a[1][2], a[1][3], b0, b1);
            }
        }
    }

    #pragma unroll
    for (int mt = 0; mt < 2; mt++) {
        int m = m0 + wm*32 + mt*16 + (lane >> 2);
        float bv0 = bias[m], bv8 = bias[m + 8];
        #pragma unroll
        for (int nt = 0; nt < 4; nt++) {
            int n = n0 + wn*32 + nt*8 + 2*(lane & 3);
            float* cf = C[mt*4 + nt];
            *(float2*)&Ob[(size_t)m*NPIX + n]      = make_float2(cf[0]+bv0, cf[1]+bv0);
            *(float2*)&Ob[(size_t)(m+8)*NPIX + n]  = make_float2(cf[2]+bv8, cf[3]+bv8);
        }
    }
}

// ---------------- tf32 flash attention ---------------------------------------
// y[b][c][n] = (softmax(theta^T phi) g^T)^T  -- y written c-major
// grid (32 q-tiles, 4 b), 256 threads (8 warps x 16 q rows), key tile 64
__global__ void __launch_bounds__(256) attention_tc_kernel() {
    __shared__ unsigned Qs[32*136];   // [c-chunk 32][q 128] pad 136
    __shared__ unsigned Ks[32*72];    // [c-chunk 32][m 64]  pad 72
    __shared__ unsigned Gs[64*68];    // [c-chunk 64][m 64]  pad 68

    int b  = blockIdx.y;
    int n0 = blockIdx.x * 128;
    const float* Tb = d_theta + (size_t)b * CI * NPIX;
    const float* Fb = d_phi   + (size_t)b * CI * NPIX;
    const float* Gb = d_g     + (size_t)b * CI * NPIX;
    float* Yb = d_y + (size_t)b * CI * NPIX;

    int tid  = threadIdx.x;
    int lane = tid & 31;
    int wid  = tid >> 5;
    int qb   = wid * 16;              // warp q-row base within tile
    int r    = lane >> 2;             // row-in-group
    int cq   = lane & 3;              // col group

    float O[16][4];
    #pragma unroll
    for (int i = 0; i < 16; i++)
        #pragma unroll
        for (int j = 0; j < 4; j++) O[i][j] = 0.f;
    float Mx0 = -1e30f, Mx1 = -1e30f, L0 = 0.f, L1 = 0.f;

    const unsigned FULL = 0xffffffffu;
    int src  = (lane & 28) | ((lane >> 1) & 1);
    int src2 = src + 2;
    bool sel = (lane & 1);

    for (int m0 = 0; m0 < NPIX; m0 += 64) {
        float S[8][4];
        #pragma unroll
        for (int i = 0; i < 8; i++)
            #pragma unroll
            for (int j = 0; j < 4; j++) S[i][j] = 0.f;

        // ---- S = theta^T phi over 4 c-chunks of 32 ----
        for (int cc = 0; cc < 4; cc++) {
            __syncthreads();
            #pragma unroll
            for (int it = 0; it < 16; it++) {
                int i = tid + it*256;
                int c = i >> 7, q = i & 127;
                Qs[c*136 + q] = f2tf(Tb[(size_t)(cc*32 + c)*NPIX + n0 + q]);
            }
            #pragma unroll
            for (int it = 0; it < 8; it++) {
                int i = tid + it*256;
                int c = i >> 6, m = i & 63;
                Ks[c*72 + m] = f2tf(Fb[(size_t)(cc*32 + c)*NPIX + m0 + m]);
            }
            __syncthreads();

            #pragma unroll
            for (int k8 = 0; k8 < 4; k8++) {
                int kk = k8*8 + cq;
                unsigned a0 = Qs[kk*136 + qb + r];
                unsigned a1 = Qs[kk*136 + qb + r + 8];
                unsigned a2 = Qs[(kk+4)*136 + qb + r];
                unsigned a3 = Qs[(kk+4)*136 + qb + r + 8];
                #pragma unroll
                for (int nt = 0; nt < 8; nt++) {
                    unsigned b0 = Ks[kk*72 + nt*8 + r];
                    unsigned b1 = Ks[(kk+4)*72 + nt*8 + r];
                    mma_tf32(S[nt], a0, a1, a2, a3, b0, b1);
                }
            }
        }

        // ---- online softmax (rows r, r+8; cols spread over cq lanes) ----
        float rm0 = -1e30f, rm1 = -1e30f;
        #pragma unroll
        for (int nt = 0; nt < 8; nt++) {
            rm0 = fmaxf(rm0, fmaxf(S[nt][0], S[nt][1]));
            rm1 = fmaxf(rm1, fmaxf(S[nt][2], S[nt][3]));
        }
        rm0 = fmaxf(rm0, __shfl_xor_sync(FULL, rm0, 1));
        rm0 = fmaxf(rm0, __shfl_xor_sync(FULL, rm0, 2));
        rm1 = fmaxf(rm1, __shfl_xor_sync(FULL, rm1, 1));
        rm1 = fmaxf(rm1, __shfl_xor_sync(FULL, rm1, 2));

        float nm0 = fmaxf(Mx0, rm0), nm1 = fmaxf(Mx1, rm1);
        float sc0 = __expf(Mx0 - nm0), sc1 = __expf(Mx1 - nm1);
        Mx0 = nm0; Mx1 = nm1;

        float rs0 = 0.f, rs1 = 0.f;
        #pragma unroll
        for (int nt = 0; nt < 8; nt++) {
            float p0 = __expf(S[nt][0] - nm0);
            float p1 = __expf(S[nt][1] - nm0);
            float p2 = __expf(S[nt][2] - nm1);
            float p3 = __expf(S[nt][3] - nm1);
            rs0 += p0 + p1; rs1 += p2 + p3;
            S[nt][0] = __uint_as_float(f2tf(p0));
            S[nt][1] = __uint_as_float(f2tf(p1));
            S[nt][2] = __uint_as_float(f2tf(p2));
            S[nt][3] = __uint_as_float(f2tf(p3));
        }
        rs0 += __shfl_xor_sync(FULL, rs0, 1);
        rs0 += __shfl_xor_sync(FULL, rs0, 2);
        rs1 += __shfl_xor_sync(FULL, rs1, 1);
        rs1 += __shfl_xor_sync(FULL, rs1, 2);
        L0 = L0*sc0 + rs0;
        L1 = L1*sc1 + rs1;

        #pragma unroll
        for (int i = 0; i < 16; i++) {
            O[i][0] *= sc0; O[i][1] *= sc0;
            O[i][2] *= sc1; O[i][3] *= sc1;
        }

        // ---- convert P from C-fragment layout to A-fragment layout ----
        #pragma unroll
        for (int nt = 0; nt < 8; nt++) {
            float c0 = S[nt][0], c1 = S[nt][1], c2 = S[nt][2], c3 = S[nt][3];
            float s0 = __shfl_sync(FULL, c0, src);
            float s1 = __shfl_sync(FULL, c1, src);
            float s2 = __shfl_sync(FULL, c2, src);
            float s3 = __shfl_sync(FULL, c3, src);
            float t0 = __shfl_sync(FULL, c0, src2);
            float t1 = __shfl_sync(FULL, c1, src2);
            float t2 = __shfl_sync(FULL, c2, src2);
            float t3 = __shfl_sync(FULL, c3, src2);
            S[nt][0] = sel ? s1 : s0;
            S[nt][1] = sel ? s3 : s2;
            S[nt][2] = sel ? t1 : t0;
            S[nt][3] = sel ? t3 : t2;
        }

        // ---- O += P g^T over 2 c-chunks of 64 ----
        #pragma unroll
        for (int cc2 = 0; cc2 < 2; cc2++) {
            __syncthreads();
            #pragma unroll
            for (int it = 0; it < 16; it++) {
                int i = tid + it*256;
                int c = i >> 6, m = i & 63;
                Gs[c*68 + m] = f2tf(Gb[(size_t)(cc2*64 + c)*NPIX + m0 + m]);
            }
            __syncthreads();
            #pragma unroll
            for (int k = 0; k < 8; k++) {
                unsigned a0 = __float_as_uint(S[k][0]);
                unsigned a1 = __float_as_uint(S[k][1]);
                unsigned a2 = __float_as_uint(S[k][2]);
                unsigned a3 = __float_as_uint(S[k][3]);
                #pragma unroll
                for (int nt = 0; nt < 8; nt++) {
                    unsigned b0 = Gs[(nt*8 + r)*68 + k*8 + cq];
                    unsigned b1 = Gs[(nt*8 + r)*68 + k*8 + cq + 4];
                    mma_tf32(O[cc2*8 + nt], a0, a1, a2, a3, b0, b1);
                }
            }
        }
    }

    // ---- epilogue: y[c][n] ----
    float inv0 = 1.0f / L0, inv1 = 1.0f / L1;
    int q = n0 + qb + r;
    #pragma unroll
    for (int ct = 0; ct < 16; ct++) {
        int c = ct*8 + 2*cq;
        Yb[(size_t)c*NPIX + q]          = O[ct][0] * inv0;
        Yb[(size_t)(c+1)*NPIX + q]      = O[ct][1] * inv0;
        Yb[(size_t)c*NPIX + q + 8]      = O[ct][2] * inv1;
        Yb[(size_t)(c+1)*NPIX + q + 8]  = O[ct][3] * inv1;
    }
}

// ---------------- final: out = GN2(z)*0.1 + xs --------------------------------
__global__ void final_apply_kernel(const float* __restrict__ gw,
                                   const float* __restrict__ gb,
                                   float* __restrict__ out) {
    int i4 = blockIdx.x * blockDim.x + threadIdx.x;
    if (i4 >= BATCH*CCH*NPIX/4) return;
    int idx = i4 << 2;
    int c   = (idx >> 12) & 255;
    int bg  = idx >> 17;
    float mean = d_st2[bg*2], rstd = d_st2[bg*2 + 1];
    float sc = rstd * gw[c];
    float sh = gb[c] - mean * sc;
    float4 z = ((const float4*)d_z)[i4];
    float4 xs = ((const float4*)d_xs)[i4];
    float4 o;
    o.x = (z.x*sc + sh)*0.1f + xs.x;
    o.y = (z.y*sc + sh)*0.1f + xs.y;
    o.z = (z.z*sc + sh)*0.1f + xs.z;
    o.w = (z.w*sc + sh)*0.1f + xs.w;
    ((float4*)out)[i4] = o;
}

// ---------------- launch ------------------------------------------------------
extern "C" void kernel_launch(void* const* d_in, const int* in_sizes, int n_in,
                              void* d_out, int out_size) {
    const float* x    = (const float*)d_in[0];
    const float* sw   = (const float*)d_in[1];
    const float* sb   = (const float*)d_in[2];
    const float* gn1w = (const float*)d_in[3];
    const float* gn1b = (const float*)d_in[4];
    const float* g_w  = (const float*)d_in[5];
    const float* g_b  = (const float*)d_in[6];
    const float* th_w = (const float*)d_in[7];
    const float* th_b = (const float*)d_in[8];
    const float* ph_w = (const float*)d_in[9];
    const float* ph_b = (const float*)d_in[10];
    const float* w_w  = (const float*)d_in[11];
    const float* w_b  = (const float*)d_in[12];
    const float* gn2w = (const float*)d_in[13];
    const float* gn2b = (const float*)d_in[14];
    float* out = (float*)d_out;

    pack_w_kernel<<<(CCH*9*CCH + 255)/256, 256>>>(sw);
    conv3x3_kernel<<<dim3(4, 64, 4), 256>>>(x, sb);
    gn_stats_kernel<<<32, 256>>>(0);
    gn1_apply_kernel<<<(BATCH*CCH*NPIX/4 + 255)/256, 256>>>(gn1w, gn1b);

    gemm_tc_kernel<0><<<dim3(32, 2, 4), 256>>>(th_w, th_b);
    gemm_tc_kernel<1><<<dim3(32, 2, 4), 256>>>(ph_w, ph_b);
    gemm_tc_kernel<2><<<dim3(32, 2, 4), 256>>>(g_w, g_b);

    attention_tc_kernel<<<dim3(32, 4), 256>>>();

    gemm_tc_kernel<3><<<dim3(32, 4, 4), 256>>>(w_w, w_b);
    gn_stats_kernel<<<32, 256>>>(1);
    final_apply_kernel<<<(BATCH*CCH*NPIX/4 + 255)/256, 256>>>(gn2w, gn2b, out);

    (void)in_sizes; (void)n_in; (void)out_size;
}

// round 3
// speedup vs baseline: 1.8061x; 1.0943x over previous
#include <cuda_runtime.h>
#include <math.h>

#define BATCH 4
#define CCH   256
#define CI    128
#define NPIX  4096
#define GROUPS 8
#define CPG   32
#define GSIZE (CPG*NPIX)
#define EPSV  1e-5f
#define KCONV 2304            // 9 taps * 256 cin, tap-major

// ---------------- scratch ----------------------------------------------------
__device__ float d_xs   [BATCH*CCH*NPIX];
__device__ float d_theta[BATCH*CI*NPIX];
__device__ float d_phi  [BATCH*CI*NPIX];
__device__ float d_g    [BATCH*CI*NPIX];
__device__ float d_y    [BATCH*CI*NPIX];
__device__ float d_z    [BATCH*CCH*NPIX];
__device__ float d_wpack[KCONV*CCH];        // [k = tap*256+c][oc]
__device__ float d_st1  [BATCH*GROUPS*2];
__device__ float d_st2  [BATCH*GROUPS*2];

// ---------------- tf32 helpers -----------------------------------------------
__device__ __forceinline__ unsigned f2tf(float f) {
    unsigned u;
    asm("cvt.rna.tf32.f32 %0, %1;" : "=r"(u) : "f"(f));
    return u;
}

__device__ __forceinline__ void mma_tf32(float* c,
    unsigned a0, unsigned a1, unsigned a2, unsigned a3,
    unsigned b0, unsigned b1) {
    asm volatile(
        "mma.sync.aligned.m16n8k8.row.col.f32.tf32.tf32.f32 "
        "{%0,%1,%2,%3}, {%4,%5,%6,%7}, {%8,%9}, {%0,%1,%2,%3};"
        : "+f"(c[0]), "+f"(c[1]), "+f"(c[2]), "+f"(c[3])
        : "r"(a0), "r"(a1), "r"(a2), "r"(a3), "r"(b0), "r"(b1));
}

// ---------------- weight repack: [o][c][tap] -> [tap*256+c][o] ----------------
__global__ void pack_w_kernel(const float* __restrict__ w) {
    int idx = blockIdx.x * blockDim.x + threadIdx.x;
    if (idx >= KCONV*CCH) return;
    int o   = idx & 255;
    int k   = idx >> 8;
    int c   = k & 255;
    int tap = k >> 8;
    d_wpack[idx] = w[o*(CCH*9) + c*9 + tap];
}

// ---------------- conv3x3 via implicit GEMM, 3-term tf32 ---------------------
// out[b][m][pix] = sum_k W[m][k] * im2col(x)[k][pix] + bias[m]
// block: 128m x 128pix, 8 warps (2m x 4n), warp 64x32, K chunk 32 (one tap)
__global__ void __launch_bounds__(256) conv_tc_kernel(const float* __restrict__ x,
                                                      const float* __restrict__ sb) {
    __shared__ float As[128*36];    // [m][kk] pad 36
    __shared__ float Bs[32*136];    // [kk][n] pad 136

    int b    = blockIdx.z;
    int m0   = blockIdx.y * 128;
    int pix0 = blockIdx.x * 128;
    int h0   = pix0 >> 6;            // two image rows per tile
    const float* xb = x + (size_t)b * CCH * NPIX;

    int tid  = threadIdx.x;
    int lane = tid & 31;
    int wid  = tid >> 5;
    int wm = wid >> 2, wn = wid & 3;
    int r  = lane >> 2, cq = lane & 3;

    float C[16][4];
    #pragma unroll
    for (int i = 0; i < 16; i++)
        #pragma unroll
        for (int j = 0; j < 4; j++) C[i][j] = 0.f;

    for (int kc = 0; kc < KCONV; kc += 32) {
        int tap = kc >> 8;
        int c0  = kc & 255;
        int ky  = tap / 3 - 1;
        int kx  = tap % 3 - 1;
        __syncthreads();
        #pragma unroll
        for (int it = 0; it < 16; it++) {
            int i = tid + it*256;
            int m = i & 127, kk = i >> 7;
            As[m*36 + kk] = d_wpack[(size_t)(kc + kk)*256 + m0 + m];
        }
        #pragma unroll
        for (int it = 0; it < 16; it++) {
            int i = tid + it*256;
            int n = i & 127, kk = i >> 7;
            int h = h0 + (n >> 6) + ky;
            int w = (n & 63) + kx;
            float v = 0.f;
            if ((unsigned)h < 64u && (unsigned)w < 64u)
                v = xb[(size_t)(c0 + kk)*NPIX + (h << 6) + w];
            Bs[kk*136 + n] = v;
        }
        __syncthreads();

        #pragma unroll
        for (int k8 = 0; k8 < 4; k8++) {
            int kk = k8*8 + cq;
            unsigned ab[4][4], as[4][4];
            #pragma unroll
            for (int mt = 0; mt < 4; mt++) {
                int m = wm*64 + mt*16 + r;
                float f0 = As[m*36 + kk];
                float f1 = As[(m+8)*36 + kk];
                float f2 = As[m*36 + kk + 4];
                float f3 = As[(m+8)*36 + kk + 4];
                ab[mt][0] = f2tf(f0); as[mt][0] = f2tf(f0 - __uint_as_float(ab[mt][0]));
                ab[mt][1] = f2tf(f1); as[mt][1] = f2tf(f1 - __uint_as_float(ab[mt][1]));
                ab[mt][2] = f2tf(f2); as[mt][2] = f2tf(f2 - __uint_as_float(ab[mt][2]));
                ab[mt][3] = f2tf(f3); as[mt][3] = f2tf(f3 - __uint_as_float(ab[mt][3]));
            }
            #pragma unroll
            for (int nt = 0; nt < 4; nt++) {
                int n = wn*32 + nt*8 + r;
                float g0 = Bs[kk*136 + n];
                float g1 = Bs[(kk+4)*136 + n];
                unsigned bb0 = f2tf(g0), bb1 = f2tf(g1);
                unsigned bs0 = f2tf(g0 - __uint_as_float(bb0));
                unsigned bs1 = f2tf(g1 - __uint_as_float(bb1));
                #pragma unroll
                for (int mt = 0; mt < 4; mt++) {
                    float* cf = C[mt*4 + nt];
                    mma_tf32(cf, ab[mt][0], ab[mt][1], ab[mt][2], ab[mt][3], bb0, bb1);
                    mma_tf32(cf, ab[mt][0], ab[mt][1], ab[mt][2], ab[mt][3], bs0, bs1);
                    mma_tf32(cf, as[mt][0], as[mt][1], as[mt][2], as[mt][3], bb0, bb1);
                }
            }
        }
    }

    #pragma unroll
    for (int mt = 0; mt < 4; mt++) {
        int m = m0 + wm*64 + mt*16 + r;
        float bv0 = sb[m], bv8 = sb[m + 8];
        #pragma unroll
        for (int nt = 0; nt < 4; nt++) {
            int n = pix0 + wn*32 + nt*8 + 2*cq;
            float* cf = C[mt*4 + nt];
            *(float2*)&d_xs[((size_t)(b*CCH + m))*NPIX + n]     = make_float2(cf[0]+bv0, cf[1]+bv0);
            *(float2*)&d_xs[((size_t)(b*CCH + m + 8))*NPIX + n] = make_float2(cf[2]+bv8, cf[3]+bv8);
        }
    }
}

// ---------------- GroupNorm stats --------------------------------------------
__global__ void gn_stats_kernel(int which) {
    const float* src = which ? d_z : d_xs;
    float* st        = which ? d_st2 : d_st1;
    int blk = blockIdx.x;
    const float4* p = (const float4*)(src + (size_t)blk * GSIZE);
    float s = 0.f, s2 = 0.f;
    for (int i = threadIdx.x; i < GSIZE/4; i += 256) {
        float4 v = p[i];
        s  += v.x + v.y + v.z + v.w;
        s2 += v.x*v.x + v.y*v.y + v.z*v.z + v.w*v.w;
    }
    #pragma unroll
    for (int off = 16; off > 0; off >>= 1) {
        s  += __shfl_xor_sync(0xffffffffu, s,  off);
        s2 += __shfl_xor_sync(0xffffffffu, s2, off);
    }
    __shared__ float sh[16];
    int wid = threadIdx.x >> 5, lid = threadIdx.x & 31;
    if (lid == 0) { sh[wid] = s; sh[wid + 8] = s2; }
    __syncthreads();
    if (threadIdx.x == 0) {
        float S = 0.f, S2 = 0.f;
        #pragma unroll
        for (int w = 0; w < 8; w++) { S += sh[w]; S2 += sh[w + 8]; }
        float mean = S / (float)GSIZE;
        float var  = S2 / (float)GSIZE - mean * mean;
        st[blk*2]     = mean;
        st[blk*2 + 1] = rsqrtf(var + EPSV);
    }
}

// ---------------- GN1 apply + ReLU -------------------------------------------
__global__ void gn1_apply_kernel(const float* __restrict__ gw,
                                 const float* __restrict__ gb) {
    int i4 = blockIdx.x * blockDim.x + threadIdx.x;
    if (i4 >= BATCH*CCH*NPIX/4) return;
    int idx = i4 << 2;
    int c   = (idx >> 12) & 255;
    int bg  = idx >> 17;
    float mean = d_st1[bg*2], rstd = d_st1[bg*2 + 1];
    float sc = rstd * gw[c];
    float sh = gb[c] - mean * sc;
    float4 v = ((float4*)d_xs)[i4];
    v.x = fmaxf(v.x*sc + sh, 0.f);
    v.y = fmaxf(v.y*sc + sh, 0.f);
    v.z = fmaxf(v.z*sc + sh, 0.f);
    v.w = fmaxf(v.w*sc + sh, 0.f);
    ((float4*)d_xs)[i4] = v;
}

// ---------------- tf32 tensor-core 1x1 GEMM ----------------------------------
template<int MODE>
__global__ void __launch_bounds__(256) gemm_tc_kernel(const float* __restrict__ W,
                                                      const float* __restrict__ bias) {
    constexpr int M = (MODE == 3) ? 256 : 128;
    constexpr int K = (MODE == 3) ? 128 : 256;
    const float* X = (MODE == 3) ? d_y : d_xs;
    float* out = (MODE == 0) ? d_theta : (MODE == 1) ? d_phi
               : (MODE == 2) ? d_g : d_z;

    __shared__ unsigned Ws[64*36];
    __shared__ unsigned Xs[32*136];

    int b  = blockIdx.z;
    int n0 = blockIdx.x * 128;
    int m0 = blockIdx.y * 64;
    const float* Xb = X + (size_t)b * K * NPIX;
    float* Ob = out + (size_t)b * M * NPIX;

    int tid  = threadIdx.x;
    int lane = tid & 31;
    int wid  = tid >> 5;
    int wm = wid >> 2, wn = wid & 3;

    float C[8][4];
    #pragma unroll
    for (int i = 0; i < 8; i++)
        #pragma unroll
        for (int j = 0; j < 4; j++) C[i][j] = 0.f;

    for (int kc = 0; kc < K; kc += 32) {
        __syncthreads();
        #pragma unroll
        for (int it = 0; it < 8; it++) {
            int i = tid + it*256;
            int m = i >> 5, k = i & 31;
            Ws[m*36 + k] = f2tf(W[(m0 + m)*K + kc + k]);
        }
        #pragma unroll
        for (int it = 0; it < 16; it++) {
            int i = tid + it*256;
            int k = i >> 7, n = i & 127;
            Xs[k*136 + n] = f2tf(Xb[(size_t)(kc + k)*NPIX + n0 + n]);
        }
        __syncthreads();

        #pragma unroll
        for (int k8 = 0; k8 < 4; k8++) {
            unsigned a[2][4];
            #pragma unroll
            for (int mt = 0; mt < 2; mt++) {
                int mr = wm*32 + mt*16 + (lane >> 2);
                int kk = k8*8 + (lane & 3);
                a[mt][0] = Ws[mr*36 + kk];
                a[mt][1] = Ws[(mr+8)*36 + kk];
                a[mt][2] = Ws[mr*36 + kk + 4];
                a[mt][3] = Ws[(mr+8)*36 + kk + 4];
            }
            #pragma unroll
            for (int nt = 0; nt < 4; nt++) {
                int nn = wn*32 + nt*8 + (lane >> 2);
                unsigned b0 = Xs[(k8*8 + (lane & 3))*136 + nn];
                unsigned b1 = Xs[(k8*8 + (lane & 3) + 4)*136 + nn];
                mma_tf32(C[nt],     a[0][0], a[0][1], a[0][2], a[0][3], b0, b1);
                mma_tf32(C[4 + nt], a[1][0], a[1][1], a[1][2], a[1][3], b0, b1);
            }
        }
    }

    #pragma unroll
    for (int mt = 0; mt < 2; mt++) {
        int m = m0 + wm*32 + mt*16 + (lane >> 2);
        float bv0 = bias[m], bv8 = bias[m + 8];
        #pragma unroll
        for (int nt = 0; nt < 4; nt++) {
            int n = n0 + wn*32 + nt*8 + 2*(lane & 3);
            float* cf = C[mt*4 + nt];
            *(float2*)&Ob[(size_t)m*NPIX + n]      = make_float2(cf[0]+bv0, cf[1]+bv0);
            *(float2*)&Ob[(size_t)(m+8)*NPIX + n]  = make_float2(cf[2]+bv8, cf[3]+bv8);
        }
    }
}

// ---------------- tf32 flash attention ---------------------------------------
__global__ void __launch_bounds__(256) attention_tc_kernel() {
    __shared__ unsigned Qs[32*136];
    __shared__ unsigned Ks[32*72];
    __shared__ unsigned Gs[64*68];

    int b  = blockIdx.y;
    int n0 = blockIdx.x * 128;
    const float* Tb = d_theta + (size_t)b * CI * NPIX;
    const float* Fb = d_phi   + (size_t)b * CI * NPIX;
    const float* Gb = d_g     + (size_t)b * CI * NPIX;
    float* Yb = d_y + (size_t)b * CI * NPIX;

    int tid  = threadIdx.x;
    int lane = tid & 31;
    int wid  = tid >> 5;
    int qb   = wid * 16;
    int r    = lane >> 2;
    int cq   = lane & 3;

    float O[16][4];
    #pragma unroll
    for (int i = 0; i < 16; i++)
        #pragma unroll
        for (int j = 0; j < 4; j++) O[i][j] = 0.f;
    float Mx0 = -1e30f, Mx1 = -1e30f, L0 = 0.f, L1 = 0.f;

    const unsigned FULL = 0xffffffffu;
    int src  = (lane & 28) | ((lane >> 1) & 1);
    int src2 = src + 2;
    bool sel = (lane & 1);

    for (int m0 = 0; m0 < NPIX; m0 += 64) {
        float S[8][4];
        #pragma unroll
        for (int i = 0; i < 8; i++)
            #pragma unroll
            for (int j = 0; j < 4; j++) S[i][j] = 0.f;

        for (int cc = 0; cc < 4; cc++) {
            __syncthreads();
            #pragma unroll
            for (int it = 0; it < 16; it++) {
                int i = tid + it*256;
                int c = i >> 7, q = i & 127;
                Qs[c*136 + q] = f2tf(Tb[(size_t)(cc*32 + c)*NPIX + n0 + q]);
            }
            #pragma unroll
            for (int it = 0; it < 8; it++) {
                int i = tid + it*256;
                int c = i >> 6, m = i & 63;
                Ks[c*72 + m] = f2tf(Fb[(size_t)(cc*32 + c)*NPIX + m0 + m]);
            }
            __syncthreads();

            #pragma unroll
            for (int k8 = 0; k8 < 4; k8++) {
                int kk = k8*8 + cq;
                unsigned a0 = Qs[kk*136 + qb + r];
                unsigned a1 = Qs[kk*136 + qb + r + 8];
                unsigned a2 = Qs[(kk+4)*136 + qb + r];
                unsigned a3 = Qs[(kk+4)*136 + qb + r + 8];
                #pragma unroll
                for (int nt = 0; nt < 8; nt++) {
                    unsigned b0 = Ks[kk*72 + nt*8 + r];
                    unsigned b1 = Ks[(kk+4)*72 + nt*8 + r];
                    mma_tf32(S[nt], a0, a1, a2, a3, b0, b1);
                }
            }
        }

        float rm0 = -1e30f, rm1 = -1e30f;
        #pragma unroll
        for (int nt = 0; nt < 8; nt++) {
            rm0 = fmaxf(rm0, fmaxf(S[nt][0], S[nt][1]));
            rm1 = fmaxf(rm1, fmaxf(S[nt][2], S[nt][3]));
        }
        rm0 = fmaxf(rm0, __shfl_xor_sync(FULL, rm0, 1));
        rm0 = fmaxf(rm0, __shfl_xor_sync(FULL, rm0, 2));
        rm1 = fmaxf(rm1, __shfl_xor_sync(FULL, rm1, 1));
        rm1 = fmaxf(rm1, __shfl_xor_sync(FULL, rm1, 2));

        float nm0 = fmaxf(Mx0, rm0), nm1 = fmaxf(Mx1, rm1);
        float sc0 = __expf(Mx0 - nm0), sc1 = __expf(Mx1 - nm1);
        Mx0 = nm0; Mx1 = nm1;

        float rs0 = 0.f, rs1 = 0.f;
        #pragma unroll
        for (int nt = 0; nt < 8; nt++) {
            float p0 = __expf(S[nt][0] - nm0);
            float p1 = __expf(S[nt][1] - nm0);
            float p2 = __expf(S[nt][2] - nm1);
            float p3 = __expf(S[nt][3] - nm1);
            rs0 += p0 + p1; rs1 += p2 + p3;
            S[nt][0] = __uint_as_float(f2tf(p0));
            S[nt][1] = __uint_as_float(f2tf(p1));
            S[nt][2] = __uint_as_float(f2tf(p2));
            S[nt][3] = __uint_as_float(f2tf(p3));
        }
        rs0 += __shfl_xor_sync(FULL, rs0, 1);
        rs0 += __shfl_xor_sync(FULL, rs0, 2);
        rs1 += __shfl_xor_sync(FULL, rs1, 1);
        rs1 += __shfl_xor_sync(FULL, rs1, 2);
        L0 = L0*sc0 + rs0;
        L1 = L1*sc1 + rs1;

        #pragma unroll
        for (int i = 0; i < 16; i++) {
            O[i][0] *= sc0; O[i][1] *= sc0;
            O[i][2] *= sc1; O[i][3] *= sc1;
        }

        #pragma unroll
        for (int nt = 0; nt < 8; nt++) {
            float c0 = S[nt][0], c1 = S[nt][1], c2 = S[nt][2], c3 = S[nt][3];
            float s0 = __shfl_sync(FULL, c0, src);
            float s1 = __shfl_sync(FULL, c1, src);
            float s2 = __shfl_sync(FULL, c2, src);
            float s3 = __shfl_sync(FULL, c3, src);
            float t0 = __shfl_sync(FULL, c0, src2);
            float t1 = __shfl_sync(FULL, c1, src2);
            float t2 = __shfl_sync(FULL, c2, src2);
            float t3 = __shfl_sync(FULL, c3, src2);
            S[nt][0] = sel ? s1 : s0;
            S[nt][1] = sel ? s3 : s2;
            S[nt][2] = sel ? t1 : t0;
            S[nt][3] = sel ? t3 : t2;
        }

        #pragma unroll
        for (int cc2 = 0; cc2 < 2; cc2++) {
            __syncthreads();
            #pragma unroll
            for (int it = 0; it < 16; it++) {
                int i = tid + it*256;
                int c = i >> 6, m = i & 63;
                Gs[c*68 + m] = f2tf(Gb[(size_t)(cc2*64 + c)*NPIX + m0 + m]);
            }
            __syncthreads();
            #pragma unroll
            for (int k = 0; k < 8; k++) {
                unsigned a0 = __float_as_uint(S[k][0]);
                unsigned a1 = __float_as_uint(S[k][1]);
                unsigned a2 = __float_as_uint(S[k][2]);
                unsigned a3 = __float_as_uint(S[k][3]);
                #pragma unroll
                for (int nt = 0; nt < 8; nt++) {
                    unsigned b0 = Gs[(nt*8 + r)*68 + k*8 + cq];
                    unsigned b1 = Gs[(nt*8 + r)*68 + k*8 + cq + 4];
                    mma_tf32(O[cc2*8 + nt], a0, a1, a2, a3, b0, b1);
                }
            }
        }
    }

    float inv0 = 1.0f / L0, inv1 = 1.0f / L1;
    int q = n0 + qb + r;
    #pragma unroll
    for (int ct = 0; ct < 16; ct++) {
        int c = ct*8 + 2*cq;
        Yb[(size_t)c*NPIX + q]          = O[ct][0] * inv0;
        Yb[(size_t)(c+1)*NPIX + q]      = O[ct][1] * inv0;
        Yb[(size_t)c*NPIX + q + 8]      = O[ct][2] * inv1;
        Yb[(size_t)(c+1)*NPIX + q + 8]  = O[ct][3] * inv1;
    }
}

// ---------------- final: out = GN2(z)*0.1 + xs --------------------------------
__global__ void final_apply_kernel(const float* __restrict__ gw,
                                   const float* __restrict__ gb,
                                   float* __restrict__ out) {
    int i4 = blockIdx.x * blockDim.x + threadIdx.x;
    if (i4 >= BATCH*CCH*NPIX/4) return;
    int idx = i4 << 2;
    int c   = (idx >> 12) & 255;
    int bg  = idx >> 17;
    float mean = d_st2[bg*2], rstd = d_st2[bg*2 + 1];
    float sc = rstd * gw[c];
    float sh = gb[c] - mean * sc;
    float4 z = ((const float4*)d_z)[i4];
    float4 xs = ((const float4*)d_xs)[i4];
    float4 o;
    o.x = (z.x*sc + sh)*0.1f + xs.x;
    o.y = (z.y*sc + sh)*0.1f + xs.y;
    o.z = (z.z*sc + sh)*0.1f + xs.z;
    o.w = (z.w*sc + sh)*0.1f + xs.w;
    ((float4*)out)[i4] = o;
}

// ---------------- launch ------------------------------------------------------
extern "C" void kernel_launch(void* const* d_in, const int* in_sizes, int n_in,
                              void* d_out, int out_size) {
    const float* x    = (const float*)d_in[0];
    const float* sw   = (const float*)d_in[1];
    const float* sb   = (const float*)d_in[2];
    const float* gn1w = (const float*)d_in[3];
    const float* gn1b = (const float*)d_in[4];
    const float* g_w  = (const float*)d_in[5];
    const float* g_b  = (const float*)d_in[6];
    const float* th_w = (const float*)d_in[7];
    const float* th_b = (const float*)d_in[8];
    const float* ph_w = (const float*)d_in[9];
    const float* ph_b = (const float*)d_in[10];
    const float* w_w  = (const float*)d_in[11];
    const float* w_b  = (const float*)d_in[12];
    const float* gn2w = (const float*)d_in[13];
    const float* gn2b = (const float*)d_in[14];
    float* out = (float*)d_out;

    pack_w_kernel<<<(KCONV*CCH + 255)/256, 256>>>(sw);
    conv_tc_kernel<<<dim3(32, 2, 4), 256>>>(x, sb);
    gn_stats_kernel<<<32, 256>>>(0);
    gn1_apply_kernel<<<(BATCH*CCH*NPIX/4 + 255)/256, 256>>>(gn1w, gn1b);

    gemm_tc_kernel<0><<<dim3(32, 2, 4), 256>>>(th_w, th_b);
    gemm_tc_kernel<1><<<dim3(32, 2, 4), 256>>>(ph_w, ph_b);
    gemm_tc_kernel<2><<<dim3(32, 2, 4), 256>>>(g_w, g_b);

    attention_tc_kernel<<<dim3(32, 4), 256>>>();

    gemm_tc_kernel<3><<<dim3(32, 4, 4), 256>>>(w_w, w_b);
    gn_stats_kernel<<<32, 256>>>(1);
    final_apply_kernel<<<(BATCH*CCH*NPIX/4 + 255)/256, 256>>>(gn2w, gn2b, out);

    (void)in_sizes; (void)n_in; (void)out_size;
}

// round 4
// speedup vs baseline: 2.2492x; 1.2453x over previous
#include <cuda_runtime.h>
#include <math.h>
#include <stdint.h>

#define BATCH 4
#define CCH   256
#define CI    128
#define NPIX  4096
#define GROUPS 8
#define CPG   32
#define GSIZE (CPG*NPIX)
#define EPSV  1e-5f
#define KCONV 2304            // 9 taps * 256 cin, tap-major

// ---------------- scratch ----------------------------------------------------
__device__ float d_xs    [BATCH*CCH*NPIX];
__device__ float d_theta [BATCH*CI*NPIX];
__device__ float d_phi   [BATCH*CI*NPIX];
__device__ float d_g     [BATCH*CI*NPIX];
__device__ float d_y     [BATCH*CI*NPIX];
__device__ float d_z     [BATCH*CCH*NPIX];
__device__ float d_wsplit[KCONV*CCH*2];       // [k][m][2] big/small interleaved
__device__ float d_xsplit[BATCH*CCH*NPIX*2];  // [b][c][pix][2]
__device__ float d_st1   [BATCH*GROUPS*2];
__device__ float d_st2   [BATCH*GROUPS*2];

// ---------------- helpers -----------------------------------------------------
__device__ __forceinline__ unsigned f2tf(float f) {
    unsigned u;
    asm("cvt.rna.tf32.f32 %0, %1;" : "=r"(u) : "f"(f));
    return u;
}

__device__ __forceinline__ void mma_tf32(float* c,
    unsigned a0, unsigned a1, unsigned a2, unsigned a3,
    unsigned b0, unsigned b1) {
    asm volatile(
        "mma.sync.aligned.m16n8k8.row.col.f32.tf32.tf32.f32 "
        "{%0,%1,%2,%3}, {%4,%5,%6,%7}, {%8,%9}, {%0,%1,%2,%3};"
        : "+f"(c[0]), "+f"(c[1]), "+f"(c[2]), "+f"(c[3])
        : "r"(a0), "r"(a1), "r"(a2), "r"(a3), "r"(b0), "r"(b1));
}

__device__ __forceinline__ void cp16(uint32_t dst, const void* src) {
    asm volatile("cp.async.cg.shared.global [%0], [%1], 16;" :: "r"(dst), "l"(src));
}
__device__ __forceinline__ void cp8z(uint32_t dst, const void* src, int srcsz) {
    asm volatile("cp.async.ca.shared.global [%0], [%1], 8, %2;"
                 :: "r"(dst), "l"(src), "r"(srcsz));
}
__device__ __forceinline__ void cp_commit() {
    asm volatile("cp.async.commit_group;");
}
template<int N>
__device__ __forceinline__ void cp_wait() {
    asm volatile("cp.async.wait_group %0;" :: "n"(N));
}
__device__ __forceinline__ uint32_t smem_u32(const void* p) {
    return (uint32_t)__cvta_generic_to_shared(p);
}

// ---------------- precompute: weight split [o][c][tap] -> [k][m][2] -----------
__global__ void pack_wsplit_kernel(const float* __restrict__ w) {
    int idx = blockIdx.x * blockDim.x + threadIdx.x;
    if (idx >= KCONV*CCH) return;
    int m   = idx & 255;
    int k   = idx >> 8;
    int c   = k & 255;
    int tap = k >> 8;
    float f = w[m*(CCH*9) + c*9 + tap];
    unsigned big = f2tf(f);
    d_wsplit[idx*2]     = __uint_as_float(big);
    d_wsplit[idx*2 + 1] = f - __uint_as_float(big);
}

// ---------------- precompute: x split [b][c][pix][2] ---------------------------
__global__ void split_x_kernel(const float* __restrict__ x) {
    int idx = blockIdx.x * blockDim.x + threadIdx.x;
    if (idx >= BATCH*CCH*NPIX) return;
    float f = x[idx];
    unsigned big = f2tf(f);
    d_xsplit[idx*2]     = __uint_as_float(big);
    d_xsplit[idx*2 + 1] = f - __uint_as_float(big);
}

// ---------------- conv3x3 implicit GEMM, 3-term tf32, cp.async pipelined ------
// block 128oc x 128pix, 8 warps (2x4), K chunk 32. Dynamic smem double buffered.
#define CONV_ROW 264                       // floats per smem row (256 used + pad)
#define CONV_STAGE (32*CONV_ROW)           // floats per tile stage
#define CONV_SMEM_BYTES (4*CONV_STAGE*4*2/2)  // 2 stages * (A+B) = 4 tiles

__global__ void __launch_bounds__(256) conv_tc_kernel(const float* __restrict__ sb) {
    extern __shared__ float smem[];
    float* sA = smem;                      // [2][32][CONV_ROW]
    float* sB = smem + 2*CONV_STAGE;       // [2][32][CONV_ROW]

    int b    = blockIdx.z;
    int m0   = blockIdx.y * 128;
    int pix0 = blockIdx.x * 128;
    int h0   = pix0 >> 6;

    int tid  = threadIdx.x;
    int lane = tid & 31;
    int wid  = tid >> 5;
    int wm = wid >> 2, wn = wid & 3;
    int r  = lane >> 2, cq = lane & 3;

    // staging thread mappings (fixed)
    int segA = tid & 63;                   // 16B segment within A row
    int kkA  = tid >> 6;                   // A row base (stride 4)
    int nB   = tid & 127;                  // B pixel index (fixed)
    int kkB  = tid >> 7;                   // B row base (stride 2)
    int nh   = nB >> 6;
    int nw   = nB & 63;
    const size_t bC = (size_t)b * CCH;

    uint32_t aBase = smem_u32(sA);
    uint32_t bBase = smem_u32(sB);

    float C[16][4];
    #pragma unroll
    for (int i = 0; i < 16; i++)
        #pragma unroll
        for (int j = 0; j < 4; j++) C[i][j] = 0.f;

    // ---- stage helper (macro-ish via lambda) ----
    auto stage = [&](int s, int kc) {
        // A: weights [k][m][2], 32 rows x 256 floats
        {
            const float* src = d_wsplit + ((size_t)(kc + kkA)*256 + m0)*2 + segA*4;
            uint32_t dst = aBase + (uint32_t)((s*CONV_STAGE + kkA*CONV_ROW + segA*4)*4);
            #pragma unroll
            for (int i = 0; i < 8; i++) {
                cp16(dst, src);
                src += 4*256*2;
                dst += 4*CONV_ROW*4;
            }
        }
        // B: im2col x-split, 32 rows x 128 px x 8B
        {
            int tap = kc >> 8;
            int c0  = kc & 255;
            int ky  = tap/3 - 1;
            int kx  = tap - (tap/3)*3 - 1;
            int h = h0 + nh + ky;
            int w = nw + kx;
            int valid = ((unsigned)h < 64u) & ((unsigned)w < 64u);
            int pix = valid ? (h*64 + w) : 0;
            int srcsz = valid ? 8 : 0;
            const float* src = d_xsplit + ((bC + c0 + kkB)*NPIX + pix)*2;
            uint32_t dst = bBase + (uint32_t)((s*CONV_STAGE + kkB*CONV_ROW + nB*2)*4);
            #pragma unroll
            for (int j = 0; j < 16; j++) {
                cp8z(dst, src, srcsz);
                src += 2*NPIX*2;
                dst += 2*CONV_ROW*4;
            }
        }
    };

    stage(0, 0);
    cp_commit();

    for (int it = 0; it < 72; it++) {
        if (it < 71) {
            stage((it+1) & 1, (it+1)*32);
            cp_commit();
            cp_wait<1>();
        } else {
            cp_wait<0>();
        }
        __syncthreads();

        const float* A = sA + (it & 1)*CONV_STAGE;
        const float* B = sB + (it & 1)*CONV_STAGE;

        #pragma unroll
        for (int k8 = 0; k8 < 4; k8++) {
            int kk = k8*8 + cq;
            float2 pA[4][4];
            #pragma unroll
            for (int mt = 0; mt < 4; mt++) {
                int m = wm*64 + mt*16 + r;
                pA[mt][0] = *(const float2*)&A[kk*CONV_ROW + m*2];
                pA[mt][1] = *(const float2*)&A[kk*CONV_ROW + (m+8)*2];
                pA[mt][2] = *(const float2*)&A[(kk+4)*CONV_ROW + m*2];
                pA[mt][3] = *(const float2*)&A[(kk+4)*CONV_ROW + (m+8)*2];
            }
            #pragma unroll
            for (int nt = 0; nt < 4; nt++) {
                int n = wn*32 + nt*8 + r;
                float2 pB0 = *(const float2*)&B[kk*CONV_ROW + n*2];
                float2 pB1 = *(const float2*)&B[(kk+4)*CONV_ROW + n*2];
                unsigned bb0 = __float_as_uint(pB0.x), bb1 = __float_as_uint(pB1.x);
                unsigned bs0 = __float_as_uint(pB0.y), bs1 = __float_as_uint(pB1.y);
                #pragma unroll
                for (int mt = 0; mt < 4; mt++) {
                    float* cf = C[mt*4 + nt];
                    unsigned ab0 = __float_as_uint(pA[mt][0].x);
                    unsigned ab1 = __float_as_uint(pA[mt][1].x);
                    unsigned ab2 = __float_as_uint(pA[mt][2].x);
                    unsigned ab3 = __float_as_uint(pA[mt][3].x);
                    mma_tf32(cf, ab0, ab1, ab2, ab3, bb0, bb1);
                    mma_tf32(cf, ab0, ab1, ab2, ab3, bs0, bs1);
                    mma_tf32(cf, __float_as_uint(pA[mt][0].y), __float_as_uint(pA[mt][1].y),
                                 __float_as_uint(pA[mt][2].y), __float_as_uint(pA[mt][3].y),
                                 bb0, bb1);
                }
            }
        }
        __syncthreads();
    }

    #pragma unroll
    for (int mt = 0; mt < 4; mt++) {
        int m = m0 + wm*64 + mt*16 + r;
        float bv0 = sb[m], bv8 = sb[m + 8];
        #pragma unroll
        for (int nt = 0; nt < 4; nt++) {
            int n = pix0 + wn*32 + nt*8 + 2*cq;
            float* cf = C[mt*4 + nt];
            *(float2*)&d_xs[((size_t)(b*CCH + m))*NPIX + n]     = make_float2(cf[0]+bv0, cf[1]+bv0);
            *(float2*)&d_xs[((size_t)(b*CCH + m + 8))*NPIX + n] = make_float2(cf[2]+bv8, cf[3]+bv8);
        }
    }
}

// ---------------- GroupNorm stats ----------------------------------------------
__global__ void gn_stats_kernel(int which) {
    const float* src = which ? d_z : d_xs;
    float* st        = which ? d_st2 : d_st1;
    int blk = blockIdx.x;
    const float4* p = (const float4*)(src + (size_t)blk * GSIZE);
    float s = 0.f, s2 = 0.f;
    for (int i = threadIdx.x; i < GSIZE/4; i += 256) {
        float4 v = p[i];
        s  += v.x + v.y + v.z + v.w;
        s2 += v.x*v.x + v.y*v.y + v.z*v.z + v.w*v.w;
    }
    #pragma unroll
    for (int off = 16; off > 0; off >>= 1) {
        s  += __shfl_xor_sync(0xffffffffu, s,  off);
        s2 += __shfl_xor_sync(0xffffffffu, s2, off);
    }
    __shared__ float sh[16];
    int wid = threadIdx.x >> 5, lid = threadIdx.x & 31;
    if (lid == 0) { sh[wid] = s; sh[wid + 8] = s2; }
    __syncthreads();
    if (threadIdx.x == 0) {
        float S = 0.f, S2 = 0.f;
        #pragma unroll
        for (int w = 0; w < 8; w++) { S += sh[w]; S2 += sh[w + 8]; }
        float mean = S / (float)GSIZE;
        float var  = S2 / (float)GSIZE - mean * mean;
        st[blk*2]     = mean;
        st[blk*2 + 1] = rsqrtf(var + EPSV);
    }
}

// ---------------- GN1 apply + ReLU ----------------------------------------------
__global__ void gn1_apply_kernel(const float* __restrict__ gw,
                                 const float* __restrict__ gb) {
    int i4 = blockIdx.x * blockDim.x + threadIdx.x;
    if (i4 >= BATCH*CCH*NPIX/4) return;
    int idx = i4 << 2;
    int c   = (idx >> 12) & 255;
    int bg  = idx >> 17;
    float mean = d_st1[bg*2], rstd = d_st1[bg*2 + 1];
    float sc = rstd * gw[c];
    float sh = gb[c] - mean * sc;
    float4 v = ((float4*)d_xs)[i4];
    v.x = fmaxf(v.x*sc + sh, 0.f);
    v.y = fmaxf(v.y*sc + sh, 0.f);
    v.z = fmaxf(v.z*sc + sh, 0.f);
    v.w = fmaxf(v.w*sc + sh, 0.f);
    ((float4*)d_xs)[i4] = v;
}

// ---------------- tf32 1x1 GEMM, cp.async pipelined, K chunk 16 ----------------
template<int MODE>
__global__ void __launch_bounds__(256) gemm_tc_kernel(const float* __restrict__ W,
                                                      const float* __restrict__ bias) {
    constexpr int K  = (MODE == 3) ? 128 : 256;
    constexpr int NI = K / 16;
    const float* X = (MODE == 3) ? d_y : d_xs;
    float* out = (MODE == 0) ? d_theta : (MODE == 1) ? d_phi
               : (MODE == 2) ? d_g : d_z;

    __shared__ float Ws[2][64*20];
    __shared__ float Xs[2][16*136];

    int b  = blockIdx.z;
    int n0 = blockIdx.x * 128;
    int m0 = blockIdx.y * 64;
    const float* Xb = X + (size_t)b * K * NPIX;
    float* Ob = out + (size_t)b * ((MODE==3)?CCH:CI) * NPIX;

    int tid  = threadIdx.x;
    int lane = tid & 31;
    int wid  = tid >> 5;
    int wm = wid >> 2, wn = wid & 3;
    int r  = lane >> 2, cq = lane & 3;

    // staging maps
    int wRow = tid >> 2, wSeg = tid & 3;    // Ws: 64 rows x 4 segs
    int xRow = tid >> 5, xSeg = tid & 31;   // Xs: rows step 8, 32 segs
    uint32_t wBase = smem_u32(Ws);
    uint32_t xBase = smem_u32(Xs);

    auto stage = [&](int s, int kc) {
        cp16(wBase + (uint32_t)((s*64*20 + wRow*20 + wSeg*4)*4),
             W + (size_t)(m0 + wRow)*K + kc + wSeg*4);
        #pragma unroll
        for (int j = 0; j < 2; j++) {
            int k = xRow + j*8;
            cp16(xBase + (uint32_t)((s*16*136 + k*136 + xSeg*4)*4),
                 Xb + (size_t)(kc + k)*NPIX + n0 + xSeg*4);
        }
    };

    float C[8][4];
    #pragma unroll
    for (int i = 0; i < 8; i++)
        #pragma unroll
        for (int j = 0; j < 4; j++) C[i][j] = 0.f;

    stage(0, 0);
    cp_commit();

    for (int it = 0; it < NI; it++) {
        if (it < NI-1) { stage((it+1)&1, (it+1)*16); cp_commit(); cp_wait<1>(); }
        else cp_wait<0>();
        __syncthreads();

        const float* Wt = Ws[it & 1];
        const float* Xt = Xs[it & 1];

        #pragma unroll
        for (int k8 = 0; k8 < 2; k8++) {
            int kk = k8*8 + cq;
            unsigned a[2][4];
            #pragma unroll
            for (int mt = 0; mt < 2; mt++) {
                int mr = wm*32 + mt*16 + r;
                a[mt][0] = __float_as_uint(Wt[mr*20 + kk]);
                a[mt][1] = __float_as_uint(Wt[(mr+8)*20 + kk]);
                a[mt][2] = __float_as_uint(Wt[mr*20 + kk + 4]);
                a[mt][3] = __float_as_uint(Wt[(mr+8)*20 + kk + 4]);
            }
            #pragma unroll
            for (int nt = 0; nt < 4; nt++) {
                int nn = wn*32 + nt*8 + r;
                unsigned b0 = __float_as_uint(Xt[kk*136 + nn]);
                unsigned b1 = __float_as_uint(Xt[(kk+4)*136 + nn]);
                mma_tf32(C[nt],     a[0][0], a[0][1], a[0][2], a[0][3], b0, b1);
                mma_tf32(C[4 + nt], a[1][0], a[1][1], a[1][2], a[1][3], b0, b1);
            }
        }
        __syncthreads();
    }

    #pragma unroll
    for (int mt = 0; mt < 2; mt++) {
        int m = m0 + wm*32 + mt*16 + r;
        float bv0 = bias[m], bv8 = bias[m + 8];
        #pragma unroll
        for (int nt = 0; nt < 4; nt++) {
            int n = n0 + wn*32 + nt*8 + 2*cq;
            float* cf = C[mt*4 + nt];
            *(float2*)&Ob[(size_t)m*NPIX + n]      = make_float2(cf[0]+bv0, cf[1]+bv0);
            *(float2*)&Ob[(size_t)(m+8)*NPIX + n]  = make_float2(cf[2]+bv8, cf[3]+bv8);
        }
    }
}

// ---------------- tf32 flash attention: Q in registers, cp.async K/G ----------
__global__ void __launch_bounds__(256) attention_tc_kernel() {
    __shared__ float U [2*32*68];    // union: Q stage (32x136) / G chunks [2][32][68]
    __shared__ float Ks[2*32*72];    // K chunks [2][32][72]

    int b  = blockIdx.y;
    int n0 = blockIdx.x * 128;
    const float* Tb = d_theta + (size_t)b * CI * NPIX;
    const float* Fb = d_phi   + (size_t)b * CI * NPIX;
    const float* Gb = d_g     + (size_t)b * CI * NPIX;
    float* Yb = d_y + (size_t)b * CI * NPIX;

    int tid  = threadIdx.x;
    int lane = tid & 31;
    int wid  = tid >> 5;
    int qb   = wid * 16;
    int r    = lane >> 2;
    int cq   = lane & 3;

    // staging map: K/G chunk = 32 rows x 64 floats = 32 x 16 segs
    int sRow = tid >> 4, sSeg = tid & 15;   // rows step 16, 2 per thread
    uint32_t kBase = smem_u32(Ks);
    uint32_t uBase = smem_u32(U);

    auto stageK = [&](int s, int m0k, int cc) {
        #pragma unroll
        for (int j = 0; j < 2; j++) {
            int row = sRow + j*16;
            cp16(kBase + (uint32_t)((s*32*72 + row*72 + sSeg*4)*4),
                 Fb + (size_t)(cc*32 + row)*NPIX + m0k + sSeg*4);
        }
    };
    auto stageG = [&](int s, int m0k, int gc) {
        #pragma unroll
        for (int j = 0; j < 2; j++) {
            int row = sRow + j*16;
            cp16(uBase + (uint32_t)((s*32*68 + row*68 + sSeg*4)*4),
                 Gb + (size_t)(gc*32 + row)*NPIX + m0k + sSeg*4);
        }
    };

    // issue first K chunk early, overlaps Q prologue
    stageK(0, 0, 0);
    cp_commit();

    // ---- Q prologue: load 128q x 128c A-fragments into registers (rna) ----
    unsigned qa[16][4];
    for (int cc = 0; cc < 4; cc++) {
        __syncthreads();
        #pragma unroll
        for (int i = 0; i < 16; i++) {
            int idx = tid + i*256;
            int c = idx >> 7, q = idx & 127;
            U[c*136 + q] = __uint_as_float(f2tf(Tb[(size_t)(cc*32 + c)*NPIX + n0 + q]));
        }
        __syncthreads();
        #pragma unroll
        for (int k8 = 0; k8 < 4; k8++) {
            int kk = k8*8 + cq;
            qa[cc*4+k8][0] = __float_as_uint(U[kk*136 + qb + r]);
            qa[cc*4+k8][1] = __float_as_uint(U[kk*136 + qb + r + 8]);
            qa[cc*4+k8][2] = __float_as_uint(U[(kk+4)*136 + qb + r]);
            qa[cc*4+k8][3] = __float_as_uint(U[(kk+4)*136 + qb + r + 8]);
        }
    }
    __syncthreads();

    float O[16][4];
    #pragma unroll
    for (int i = 0; i < 16; i++)
        #pragma unroll
        for (int j = 0; j < 4; j++) O[i][j] = 0.f;
    float Mx0 = -1e30f, Mx1 = -1e30f, L0 = 0.f, L1 = 0.f;

    const unsigned FULL = 0xffffffffu;
    int src  = (lane & 28) | ((lane >> 1) & 1);
    int src2 = src + 2;
    bool sel = (lane & 1);

    for (int t = 0; t < 64; t++) {
        int m0 = t * 64;
        float S[8][4];
        #pragma unroll
        for (int i = 0; i < 8; i++)
            #pragma unroll
            for (int j = 0; j < 4; j++) S[i][j] = 0.f;

        // ---- S = theta^T phi, 4 c-chunks ----
        for (int cc = 0; cc < 4; cc++) {
            if (cc < 3) stageK((cc+1)&1, m0, cc+1);
            else        stageG(0, m0, 0);
            cp_commit();
            cp_wait<1>();
            __syncthreads();
            const float* Kt = Ks + (cc & 1)*32*72;
            #pragma unroll
            for (int k8 = 0; k8 < 4; k8++) {
                int kk = k8*8 + cq;
                const unsigned* a = qa[cc*4 + k8];
                #pragma unroll
                for (int nt = 0; nt < 8; nt++) {
                    unsigned b0 = __float_as_uint(Kt[kk*72 + nt*8 + r]);
                    unsigned b1 = __float_as_uint(Kt[(kk+4)*72 + nt*8 + r]);
                    mma_tf32(S[nt], a[0], a[1], a[2], a[3], b0, b1);
                }
            }
            __syncthreads();
        }

        // ---- online softmax ----
        float rm0 = -1e30f, rm1 = -1e30f;
        #pragma unroll
        for (int nt = 0; nt < 8; nt++) {
            rm0 = fmaxf(rm0, fmaxf(S[nt][0], S[nt][1]));
            rm1 = fmaxf(rm1, fmaxf(S[nt][2], S[nt][3]));
        }
        rm0 = fmaxf(rm0, __shfl_xor_sync(FULL, rm0, 1));
        rm0 = fmaxf(rm0, __shfl_xor_sync(FULL, rm0, 2));
        rm1 = fmaxf(rm1, __shfl_xor_sync(FULL, rm1, 1));
        rm1 = fmaxf(rm1, __shfl_xor_sync(FULL, rm1, 2));

        float nm0 = fmaxf(Mx0, rm0), nm1 = fmaxf(Mx1, rm1);
        float sc0 = __expf(Mx0 - nm0), sc1 = __expf(Mx1 - nm1);
        Mx0 = nm0; Mx1 = nm1;

        float rs0 = 0.f, rs1 = 0.f;
        #pragma unroll
        for (int nt = 0; nt < 8; nt++) {
            S[nt][0] = __expf(S[nt][0] - nm0);
            S[nt][1] = __expf(S[nt][1] - nm0);
            S[nt][2] = __expf(S[nt][2] - nm1);
            S[nt][3] = __expf(S[nt][3] - nm1);
            rs0 += S[nt][0] + S[nt][1];
            rs1 += S[nt][2] + S[nt][3];
        }
        rs0 += __shfl_xor_sync(FULL, rs0, 1);
        rs0 += __shfl_xor_sync(FULL, rs0, 2);
        rs1 += __shfl_xor_sync(FULL, rs1, 1);
        rs1 += __shfl_xor_sync(FULL, rs1, 2);
        L0 = L0*sc0 + rs0;
        L1 = L1*sc1 + rs1;

        #pragma unroll
        for (int i = 0; i < 16; i++) {
            O[i][0] *= sc0; O[i][1] *= sc0;
            O[i][2] *= sc1; O[i][3] *= sc1;
        }

        // ---- P: C-fragment -> A-fragment layout ----
        #pragma unroll
        for (int nt = 0; nt < 8; nt++) {
            float c0 = S[nt][0], c1 = S[nt][1], c2 = S[nt][2], c3 = S[nt][3];
            float s0 = __shfl_sync(FULL, c0, src);
            float s1 = __shfl_sync(FULL, c1, src);
            float s2 = __shfl_sync(FULL, c2, src);
            float s3 = __shfl_sync(FULL, c3, src);
            float t0 = __shfl_sync(FULL, c0, src2);
            float t1 = __shfl_sync(FULL, c1, src2);
            float t2 = __shfl_sync(FULL, c2, src2);
            float t3 = __shfl_sync(FULL, c3, src2);
            S[nt][0] = sel ? s1 : s0;
            S[nt][1] = sel ? s3 : s2;
            S[nt][2] = sel ? t1 : t0;
            S[nt][3] = sel ? t3 : t2;
        }

        // ---- O += P g^T, 4 c-chunks of 32 ----
        for (int gc = 0; gc < 4; gc++) {
            bool more = true;
            if (gc < 3)       stageG((gc+1)&1, m0, gc+1);
            else if (t < 63)  stageK(0, m0 + 64, 0);
            else              more = false;
            if (more) { cp_commit(); cp_wait<1>(); }
            else      cp_wait<0>();
            __syncthreads();
            const float* Gt = U + (gc & 1)*32*68;
            #pragma unroll
            for (int k = 0; k < 8; k++) {
                unsigned a0 = __float_as_uint(S[k][0]);
                unsigned a1 = __float_as_uint(S[k][1]);
                unsigned a2 = __float_as_uint(S[k][2]);
                unsigned a3 = __float_as_uint(S[k][3]);
                #pragma unroll
                for (int nt = 0; nt < 4; nt++) {
                    unsigned b0 = __float_as_uint(Gt[(nt*8 + r)*68 + k*8 + cq]);
                    unsigned b1 = __float_as_uint(Gt[(nt*8 + r)*68 + k*8 + cq + 4]);
                    mma_tf32(O[gc*4 + nt], a0, a1, a2, a3, b0, b1);
                }
            }
            __syncthreads();
        }
    }

    // ---- epilogue: y[c][n] ----
    float inv0 = 1.0f / L0, inv1 = 1.0f / L1;
    int q = n0 + qb + r;
    #pragma unroll
    for (int ct = 0; ct < 16; ct++) {
        int c = ct*8 + 2*cq;
        Yb[(size_t)c*NPIX + q]          = O[ct][0] * inv0;
        Yb[(size_t)(c+1)*NPIX + q]      = O[ct][1] * inv0;
        Yb[(size_t)c*NPIX + q + 8]      = O[ct][2] * inv1;
        Yb[(size_t)(c+1)*NPIX + q + 8]  = O[ct][3] * inv1;
    }
}

// ---------------- final: out = GN2(z)*0.1 + xs ----------------------------------
__global__ void final_apply_kernel(const float* __restrict__ gw,
                                   const float* __restrict__ gb,
                                   float* __restrict__ out) {
    int i4 = blockIdx.x * blockDim.x + threadIdx.x;
    if (i4 >= BATCH*CCH*NPIX/4) return;
    int idx = i4 << 2;
    int c   = (idx >> 12) & 255;
    int bg  = idx >> 17;
    float mean = d_st2[bg*2], rstd = d_st2[bg*2 + 1];
    float sc = rstd * gw[c];
    float sh = gb[c] - mean * sc;
    float4 z = ((const float4*)d_z)[i4];
    float4 xs = ((const float4*)d_xs)[i4];
    float4 o;
    o.x = (z.x*sc + sh)*0.1f + xs.x;
    o.y = (z.y*sc + sh)*0.1f + xs.y;
    o.z = (z.z*sc + sh)*0.1f + xs.z;
    o.w = (z.w*sc + sh)*0.1f + xs.w;
    ((float4*)out)[i4] = o;
}

// ---------------- launch ---------------------------------------------------------
extern "C" void kernel_launch(void* const* d_in, const int* in_sizes, int n_in,
                              void* d_out, int out_size) {
    const float* x    = (const float*)d_in[0];
    const float* sw   = (const float*)d_in[1];
    const float* sb   = (const float*)d_in[2];
    const float* gn1w = (const float*)d_in[3];
    const float* gn1b = (const float*)d_in[4];
    const float* g_w  = (const float*)d_in[5];
    const float* g_b  = (const float*)d_in[6];
    const float* th_w = (const float*)d_in[7];
    const float* th_b = (const float*)d_in[8];
    const float* ph_w = (const float*)d_in[9];
    const float* ph_b = (const float*)d_in[10];
    const float* w_w  = (const float*)d_in[11];
    const float* w_b  = (const float*)d_in[12];
    const float* gn2w = (const float*)d_in[13];
    const float* gn2b = (const float*)d_in[14];
    float* out = (float*)d_out;

    const int convSmem = 2 * 2 * CONV_STAGE * 4;   // 2 stages * (A+B) * 4B = 135168
    static int attrSet = 0;
    if (!attrSet) {
        cudaFuncSetAttribute(conv_tc_kernel,
                             cudaFuncAttributeMaxDynamicSharedMemorySize, convSmem);
        attrSet = 1;
    }

    pack_wsplit_kernel<<<(KCONV*CCH + 255)/256, 256>>>(sw);
    split_x_kernel<<<(BATCH*CCH*NPIX + 255)/256, 256>>>(x);
    conv_tc_kernel<<<dim3(32, 2, 4), 256, convSmem>>>(sb);
    gn_stats_kernel<<<32, 256>>>(0);
    gn1_apply_kernel<<<(BATCH*CCH*NPIX/4 + 255)/256, 256>>>(gn1w, gn1b);

    gemm_tc_kernel<0><<<dim3(32, 2, 4), 256>>>(th_w, th_b);
    gemm_tc_kernel<1><<<dim3(32, 2, 4), 256>>>(ph_w, ph_b);
    gemm_tc_kernel<2><<<dim3(32, 2, 4), 256>>>(g_w, g_b);

    attention_tc_kernel<<<dim3(32, 4), 256>>>();

    gemm_tc_kernel<3><<<dim3(32, 4, 4), 256>>>(w_w, w_b);
    gn_stats_kernel<<<32, 256>>>(1);
    final_apply_kernel<<<(BATCH*CCH*NPIX/4 + 255)/256, 256>>>(gn2w, gn2b, out);

    (void)in_sizes; (void)n_in; (void)out_size;
}

// round 5
// speedup vs baseline: 2.6975x; 1.1993x over previous
#include <cuda_runtime.h>
#include <math.h>
#include <stdint.h>

#define BATCH 4
#define CCH   256
#define CI    128
#define NPIX  4096
#define GROUPS 8
#define CPG   32
#define GSIZE (CPG*NPIX)
#define EPSV  1e-5f
#define KCONV 2304            // 9 taps * 256 cin, tap-major

// ---------------- scratch ----------------------------------------------------
__device__ float d_xs    [BATCH*CCH*NPIX];
__device__ float d_theta [BATCH*CI*NPIX];
__device__ float d_phi   [BATCH*CI*NPIX];
__device__ float d_g     [BATCH*CI*NPIX];
__device__ float d_y     [BATCH*CI*NPIX];
__device__ float d_z     [BATCH*CCH*NPIX];
__device__ float d_wsplit[KCONV*CCH*2];       // [k][m][2] big/small interleaved
__device__ float d_xsplit[BATCH*CCH*NPIX*2];  // [b][c][pix][2]
__device__ float d_part1 [32*16*2];
__device__ float d_part2 [32*16*2];

// ---------------- helpers -----------------------------------------------------
__device__ __forceinline__ unsigned f2tf(float f) {
    unsigned u;
    asm("cvt.rna.tf32.f32 %0, %1;" : "=r"(u) : "f"(f));
    return u;
}

__device__ __forceinline__ void mma_tf32(float* c,
    unsigned a0, unsigned a1, unsigned a2, unsigned a3,
    unsigned b0, unsigned b1) {
    asm volatile(
        "mma.sync.aligned.m16n8k8.row.col.f32.tf32.tf32.f32 "
        "{%0,%1,%2,%3}, {%4,%5,%6,%7}, {%8,%9}, {%0,%1,%2,%3};"
        : "+f"(c[0]), "+f"(c[1]), "+f"(c[2]), "+f"(c[3])
        : "r"(a0), "r"(a1), "r"(a2), "r"(a3), "r"(b0), "r"(b1));
}

__device__ __forceinline__ void cp16(uint32_t dst, const void* src) {
    asm volatile("cp.async.cg.shared.global [%0], [%1], 16;" :: "r"(dst), "l"(src));
}
__device__ __forceinline__ void cp8z(uint32_t dst, const void* src, int srcsz) {
    asm volatile("cp.async.ca.shared.global [%0], [%1], 8, %2;"
                 :: "r"(dst), "l"(src), "r"(srcsz));
}
__device__ __forceinline__ void cp_commit() {
    asm volatile("cp.async.commit_group;");
}
template<int N>
__device__ __forceinline__ void cp_wait() {
    asm volatile("cp.async.wait_group %0;" :: "n"(N));
}
__device__ __forceinline__ uint32_t smem_u32(const void* p) {
    return (uint32_t)__cvta_generic_to_shared(p);
}

// ---------------- precompute: weight split ------------------------------------
__global__ void pack_wsplit_kernel(const float* __restrict__ w) {
    int idx = blockIdx.x * blockDim.x + threadIdx.x;
    if (idx >= KCONV*CCH) return;
    int m   = idx & 255;
    int k   = idx >> 8;
    int c   = k & 255;
    int tap = k >> 8;
    float f = w[m*(CCH*9) + c*9 + tap];
    unsigned big = f2tf(f);
    d_wsplit[idx*2]     = __uint_as_float(big);
    d_wsplit[idx*2 + 1] = f - __uint_as_float(big);
}

// ---------------- precompute: x split ------------------------------------------
__global__ void split_x_kernel(const float* __restrict__ x) {
    int idx = blockIdx.x * blockDim.x + threadIdx.x;
    if (idx >= BATCH*CCH*NPIX) return;
    float f = x[idx];
    unsigned big = f2tf(f);
    d_xsplit[idx*2]     = __uint_as_float(big);
    d_xsplit[idx*2 + 1] = f - __uint_as_float(big);
}

// ---------------- conv3x3 implicit GEMM (unchanged from R4) --------------------
#define CONV_ROW 264
#define CONV_STAGE (32*CONV_ROW)

__global__ void __launch_bounds__(256) conv_tc_kernel(const float* __restrict__ sb) {
    extern __shared__ float smem[];
    float* sA = smem;
    float* sB = smem + 2*CONV_STAGE;

    int b    = blockIdx.z;
    int m0   = blockIdx.y * 128;
    int pix0 = blockIdx.x * 128;
    int h0   = pix0 >> 6;

    int tid  = threadIdx.x;
    int lane = tid & 31;
    int wid  = tid >> 5;
    int wm = wid >> 2, wn = wid & 3;
    int r  = lane >> 2, cq = lane & 3;

    int segA = tid & 63;
    int kkA  = tid >> 6;
    int nB   = tid & 127;
    int kkB  = tid >> 7;
    int nh   = nB >> 6;
    int nw   = nB & 63;
    const size_t bC = (size_t)b * CCH;

    uint32_t aBase = smem_u32(sA);
    uint32_t bBase = smem_u32(sB);

    float C[16][4];
    #pragma unroll
    for (int i = 0; i < 16; i++)
        #pragma unroll
        for (int j = 0; j < 4; j++) C[i][j] = 0.f;

    auto stage = [&](int s, int kc) {
        {
            const float* src = d_wsplit + ((size_t)(kc + kkA)*256 + m0)*2 + segA*4;
            uint32_t dst = aBase + (uint32_t)((s*CONV_STAGE + kkA*CONV_ROW + segA*4)*4);
            #pragma unroll
            for (int i = 0; i < 8; i++) {
                cp16(dst, src);
                src += 4*256*2;
                dst += 4*CONV_ROW*4;
            }
        }
        {
            int tap = kc >> 8;
            int c0  = kc & 255;
            int ky  = tap/3 - 1;
            int kx  = tap - (tap/3)*3 - 1;
            int h = h0 + nh + ky;
            int w = nw + kx;
            int valid = ((unsigned)h < 64u) & ((unsigned)w < 64u);
            int pix = valid ? (h*64 + w) : 0;
            int srcsz = valid ? 8 : 0;
            const float* src = d_xsplit + ((bC + c0 + kkB)*NPIX + pix)*2;
            uint32_t dst = bBase + (uint32_t)((s*CONV_STAGE + kkB*CONV_ROW + nB*2)*4);
            #pragma unroll
            for (int j = 0; j < 16; j++) {
                cp8z(dst, src, srcsz);
                src += 2*NPIX*2;
                dst += 2*CONV_ROW*4;
            }
        }
    };

    stage(0, 0);
    cp_commit();

    for (int it = 0; it < 72; it++) {
        if (it < 71) {
            stage((it+1) & 1, (it+1)*32);
            cp_commit();
            cp_wait<1>();
        } else {
            cp_wait<0>();
        }
        __syncthreads();

        const float* A = sA + (it & 1)*CONV_STAGE;
        const float* B = sB + (it & 1)*CONV_STAGE;

        #pragma unroll
        for (int k8 = 0; k8 < 4; k8++) {
            int kk = k8*8 + cq;
            float2 pA[4][4];
            #pragma unroll
            for (int mt = 0; mt < 4; mt++) {
                int m = wm*64 + mt*16 + r;
                pA[mt][0] = *(const float2*)&A[kk*CONV_ROW + m*2];
                pA[mt][1] = *(const float2*)&A[kk*CONV_ROW + (m+8)*2];
                pA[mt][2] = *(const float2*)&A[(kk+4)*CONV_ROW + m*2];
                pA[mt][3] = *(const float2*)&A[(kk+4)*CONV_ROW + (m+8)*2];
            }
            #pragma unroll
            for (int nt = 0; nt < 4; nt++) {
                int n = wn*32 + nt*8 + r;
                float2 pB0 = *(const float2*)&B[kk*CONV_ROW + n*2];
                float2 pB1 = *(const float2*)&B[(kk+4)*CONV_ROW + n*2];
                unsigned bb0 = __float_as_uint(pB0.x), bb1 = __float_as_uint(pB1.x);
                unsigned bs0 = __float_as_uint(pB0.y), bs1 = __float_as_uint(pB1.y);
                #pragma unroll
                for (int mt = 0; mt < 4; mt++) {
                    float* cf = C[mt*4 + nt];
                    unsigned ab0 = __float_as_uint(pA[mt][0].x);
                    unsigned ab1 = __float_as_uint(pA[mt][1].x);
                    unsigned ab2 = __float_as_uint(pA[mt][2].x);
                    unsigned ab3 = __float_as_uint(pA[mt][3].x);
                    mma_tf32(cf, ab0, ab1, ab2, ab3, bb0, bb1);
                    mma_tf32(cf, ab0, ab1, ab2, ab3, bs0, bs1);
                    mma_tf32(cf, __float_as_uint(pA[mt][0].y), __float_as_uint(pA[mt][1].y),
                                 __float_as_uint(pA[mt][2].y), __float_as_uint(pA[mt][3].y),
                                 bb0, bb1);
                }
            }
        }
        __syncthreads();
    }

    #pragma unroll
    for (int mt = 0; mt < 4; mt++) {
        int m = m0 + wm*64 + mt*16 + r;
        float bv0 = sb[m], bv8 = sb[m + 8];
        #pragma unroll
        for (int nt = 0; nt < 4; nt++) {
            int n = pix0 + wn*32 + nt*8 + 2*cq;
            float* cf = C[mt*4 + nt];
            *(float2*)&d_xs[((size_t)(b*CCH + m))*NPIX + n]     = make_float2(cf[0]+bv0, cf[1]+bv0);
            *(float2*)&d_xs[((size_t)(b*CCH + m + 8))*NPIX + n] = make_float2(cf[2]+bv8, cf[3]+bv8);
        }
    }
}

// ---------------- GroupNorm partial sums: grid 512 ------------------------------
__global__ void gn_part_kernel(int which) {
    const float* src = which ? d_z : d_xs;
    float* part      = which ? d_part2 : d_part1;
    int blk = blockIdx.x;                       // (b*8+g)*16 + chunk
    int bg = blk >> 4, ch = blk & 15;
    const float4* p = (const float4*)(src + (size_t)bg*GSIZE + ch*(GSIZE/16));
    float s = 0.f, s2 = 0.f;
    #pragma unroll
    for (int i = 0; i < 8; i++) {
        float4 v = p[threadIdx.x + i*256];
        s  += v.x + v.y + v.z + v.w;
        s2 += v.x*v.x + v.y*v.y + v.z*v.z + v.w*v.w;
    }
    #pragma unroll
    for (int off = 16; off > 0; off >>= 1) {
        s  += __shfl_xor_sync(0xffffffffu, s,  off);
        s2 += __shfl_xor_sync(0xffffffffu, s2, off);
    }
    __shared__ float sh[16];
    int wid = threadIdx.x >> 5, lid = threadIdx.x & 31;
    if (lid == 0) { sh[wid] = s; sh[wid + 8] = s2; }
    __syncthreads();
    if (threadIdx.x == 0) {
        float S = 0.f, S2 = 0.f;
        #pragma unroll
        for (int w = 0; w < 8; w++) { S += sh[w]; S2 += sh[w + 8]; }
        part[blk*2]     = S;
        part[blk*2 + 1] = S2;
    }
}

// ---------------- GN1 apply + ReLU (finalize fused) ------------------------------
__global__ void gn1_apply_kernel(const float* __restrict__ gw,
                                 const float* __restrict__ gb) {
    __shared__ float st[2];
    int bg = blockIdx.x >> 7;
    if (threadIdx.x == 0) {
        float S = 0.f, S2 = 0.f;
        #pragma unroll
        for (int i = 0; i < 16; i++) {
            S  += d_part1[(bg*16 + i)*2];
            S2 += d_part1[(bg*16 + i)*2 + 1];
        }
        float mean = S / (float)GSIZE;
        st[0] = mean;
        st[1] = rsqrtf(S2 / (float)GSIZE - mean*mean + EPSV);
    }
    __syncthreads();
    int i4 = blockIdx.x * blockDim.x + threadIdx.x;
    int idx = i4 << 2;
    int c   = (idx >> 12) & 255;
    float sc = st[1] * gw[c];
    float sh = gb[c] - st[0] * sc;
    float4 v = ((float4*)d_xs)[i4];
    v.x = fmaxf(v.x*sc + sh, 0.f);
    v.y = fmaxf(v.y*sc + sh, 0.f);
    v.z = fmaxf(v.z*sc + sh, 0.f);
    v.w = fmaxf(v.w*sc + sh, 0.f);
    ((float4*)d_xs)[i4] = v;
}

// ---------------- tf32 1x1 GEMM (unchanged from R4) ------------------------------
template<int MODE>
__global__ void __launch_bounds__(256) gemm_tc_kernel(const float* __restrict__ W,
                                                      const float* __restrict__ bias) {
    constexpr int K  = (MODE == 3) ? 128 : 256;
    constexpr int NI = K / 16;
    const float* X = (MODE == 3) ? d_y : d_xs;
    float* out = (MODE == 0) ? d_theta : (MODE == 1) ? d_phi
               : (MODE == 2) ? d_g : d_z;

    __shared__ float Ws[2][64*20];
    __shared__ float Xs[2][16*136];

    int b  = blockIdx.z;
    int n0 = blockIdx.x * 128;
    int m0 = blockIdx.y * 64;
    const float* Xb = X + (size_t)b * K * NPIX;
    float* Ob = out + (size_t)b * ((MODE==3)?CCH:CI) * NPIX;

    int tid  = threadIdx.x;
    int lane = tid & 31;
    int wid  = tid >> 5;
    int wm = wid >> 2, wn = wid & 3;
    int r  = lane >> 2, cq = lane & 3;

    int wRow = tid >> 2, wSeg = tid & 3;
    int xRow = tid >> 5, xSeg = tid & 31;
    uint32_t wBase = smem_u32(Ws);
    uint32_t xBase = smem_u32(Xs);

    auto stage = [&](int s, int kc) {
        cp16(wBase + (uint32_t)((s*64*20 + wRow*20 + wSeg*4)*4),
             W + (size_t)(m0 + wRow)*K + kc + wSeg*4);
        #pragma unroll
        for (int j = 0; j < 2; j++) {
            int k = xRow + j*8;
            cp16(xBase + (uint32_t)((s*16*136 + k*136 + xSeg*4)*4),
                 Xb + (size_t)(kc + k)*NPIX + n0 + xSeg*4);
        }
    };

    float C[8][4];
    #pragma unroll
    for (int i = 0; i < 8; i++)
        #pragma unroll
        for (int j = 0; j < 4; j++) C[i][j] = 0.f;

    stage(0, 0);
    cp_commit();

    for (int it = 0; it < NI; it++) {
        if (it < NI-1) { stage((it+1)&1, (it+1)*16); cp_commit(); cp_wait<1>(); }
        else cp_wait<0>();
        __syncthreads();

        const float* Wt = Ws[it & 1];
        const float* Xt = Xs[it & 1];

        #pragma unroll
        for (int k8 = 0; k8 < 2; k8++) {
            int kk = k8*8 + cq;
            unsigned a[2][4];
            #pragma unroll
            for (int mt = 0; mt < 2; mt++) {
                int mr = wm*32 + mt*16 + r;
                a[mt][0] = __float_as_uint(Wt[mr*20 + kk]);
                a[mt][1] = __float_as_uint(Wt[(mr+8)*20 + kk]);
                a[mt][2] = __float_as_uint(Wt[mr*20 + kk + 4]);
                a[mt][3] = __float_as_uint(Wt[(mr+8)*20 + kk + 4]);
            }
            #pragma unroll
            for (int nt = 0; nt < 4; nt++) {
                int nn = wn*32 + nt*8 + r;
                unsigned b0 = __float_as_uint(Xt[kk*136 + nn]);
                unsigned b1 = __float_as_uint(Xt[(kk+4)*136 + nn]);
                mma_tf32(C[nt],     a[0][0], a[0][1], a[0][2], a[0][3], b0, b1);
                mma_tf32(C[4 + nt], a[1][0], a[1][1], a[1][2], a[1][3], b0, b1);
            }
        }
        __syncthreads();
    }

    #pragma unroll
    for (int mt = 0; mt < 2; mt++) {
        int m = m0 + wm*32 + mt*16 + r;
        float bv0 = bias[m], bv8 = bias[m + 8];
        #pragma unroll
        for (int nt = 0; nt < 4; nt++) {
            int n = n0 + wn*32 + nt*8 + 2*cq;
            float* cf = C[mt*4 + nt];
            *(float2*)&Ob[(size_t)m*NPIX + n]      = make_float2(cf[0]+bv0, cf[1]+bv0);
            *(float2*)&Ob[(size_t)(m+8)*NPIX + n]  = make_float2(cf[2]+bv8, cf[3]+bv8);
        }
    }
}

// ---------------- tf32 flash attention: whole-tile double buffering --------------
#define KSTR 72
#define GSTR 68
#define KSTAGE (128*KSTR)          // 9216 floats
#define GSTAGE (128*GSTR)          // 8704 floats
#define ATTN_SMEM ((2*KSTAGE + 2*GSTAGE)*4)   // 143360 bytes

__global__ void __launch_bounds__(256) attention_tc_kernel() {
    extern __shared__ float smem[];
    float* sK = smem;                        // [2][128][KSTR]
    float* sG = smem + 2*KSTAGE;             // [2][128][GSTR]

    int b  = blockIdx.y;
    int n0 = blockIdx.x * 128;
    const float* Tb = d_theta + (size_t)b * CI * NPIX;
    const float* Fb = d_phi   + (size_t)b * CI * NPIX;
    const float* Gb = d_g     + (size_t)b * CI * NPIX;
    float* Yb = d_y + (size_t)b * CI * NPIX;

    int tid  = threadIdx.x;
    int lane = tid & 31;
    int wid  = tid >> 5;
    int qb   = wid * 16;
    int r    = lane >> 2;
    int cq   = lane & 3;

    int sRow = tid >> 4, sSeg = tid & 15;    // tile stage: 128 rows x 16 segs
    uint32_t kBase = smem_u32(sK);
    uint32_t gBase = smem_u32(sG);

    auto stageK = [&](int s, int m0k) {
        const float* src = Fb + (size_t)sRow*NPIX + m0k + sSeg*4;
        uint32_t dst = kBase + (uint32_t)((s*KSTAGE + sRow*KSTR + sSeg*4)*4);
        #pragma unroll
        for (int j = 0; j < 8; j++) {
            cp16(dst, src);
            src += (size_t)16*NPIX;
            dst += 16*KSTR*4;
        }
    };
    auto stageG = [&](int s, int m0k) {
        const float* src = Gb + (size_t)sRow*NPIX + m0k + sSeg*4;
        uint32_t dst = gBase + (uint32_t)((s*GSTAGE + sRow*GSTR + sSeg*4)*4);
        #pragma unroll
        for (int j = 0; j < 8; j++) {
            cp16(dst, src);
            src += (size_t)16*NPIX;
            dst += 16*GSTR*4;
        }
    };

    stageK(0, 0); cp_commit();
    stageG(0, 0); cp_commit();

    // ---- Q prologue into sK stage-1 scratch ----
    float* qscr = sK + KSTAGE;
    unsigned qa[16][4];
    for (int cc = 0; cc < 4; cc++) {
        __syncthreads();
        #pragma unroll
        for (int i = 0; i < 16; i++) {
            int idx = tid + i*256;
            int c = idx >> 7, q = idx & 127;
            qscr[c*136 + q] = __uint_as_float(f2tf(Tb[(size_t)(cc*32 + c)*NPIX + n0 + q]));
        }
        __syncthreads();
        #pragma unroll
        for (int k8 = 0; k8 < 4; k8++) {
            int kk = k8*8 + cq;
            qa[cc*4+k8][0] = __float_as_uint(qscr[kk*136 + qb + r]);
            qa[cc*4+k8][1] = __float_as_uint(qscr[kk*136 + qb + r + 8]);
            qa[cc*4+k8][2] = __float_as_uint(qscr[(kk+4)*136 + qb + r]);
            qa[cc*4+k8][3] = __float_as_uint(qscr[(kk+4)*136 + qb + r + 8]);
        }
    }
    __syncthreads();

    float O[16][4];
    #pragma unroll
    for (int i = 0; i < 16; i++)
        #pragma unroll
        for (int j = 0; j < 4; j++) O[i][j] = 0.f;
    float Mx0 = -1e30f, Mx1 = -1e30f, L0 = 0.f, L1 = 0.f;

    const unsigned FULL = 0xffffffffu;
    int src  = (lane & 28) | ((lane >> 1) & 1);
    int src2 = src + 2;
    bool sel = (lane & 1);

    for (int t = 0; t < 64; t++) {
        int s = t & 1;
        int m0 = t * 64;

        if (t < 63) { stageK(s^1, m0 + 64); cp_commit(); cp_wait<2>(); }
        else        cp_wait<1>();
        __syncthreads();

        // ---- S = theta^T phi over full 128-c K tile ----
        const float* Kt = sK + s*KSTAGE;
        float S[8][4];
        #pragma unroll
        for (int i = 0; i < 8; i++)
            #pragma unroll
            for (int j = 0; j < 4; j++) S[i][j] = 0.f;

        #pragma unroll
        for (int i = 0; i < 16; i++) {
            int kk = i*8 + cq;
            const unsigned* a = qa[i];
            #pragma unroll
            for (int nt = 0; nt < 8; nt++) {
                unsigned b0 = __float_as_uint(Kt[kk*KSTR + nt*8 + r]);
                unsigned b1 = __float_as_uint(Kt[(kk+4)*KSTR + nt*8 + r]);
                mma_tf32(S[nt], a[0], a[1], a[2], a[3], b0, b1);
            }
        }

        // ---- online softmax ----
        float rm0 = -1e30f, rm1 = -1e30f;
        #pragma unroll
        for (int nt = 0; nt < 8; nt++) {
            rm0 = fmaxf(rm0, fmaxf(S[nt][0], S[nt][1]));
            rm1 = fmaxf(rm1, fmaxf(S[nt][2], S[nt][3]));
        }
        rm0 = fmaxf(rm0, __shfl_xor_sync(FULL, rm0, 1));
        rm0 = fmaxf(rm0, __shfl_xor_sync(FULL, rm0, 2));
        rm1 = fmaxf(rm1, __shfl_xor_sync(FULL, rm1, 1));
        rm1 = fmaxf(rm1, __shfl_xor_sync(FULL, rm1, 2));

        float nm0 = fmaxf(Mx0, rm0), nm1 = fmaxf(Mx1, rm1);
        float sc0 = __expf(Mx0 - nm0), sc1 = __expf(Mx1 - nm1);
        Mx0 = nm0; Mx1 = nm1;

        float rs0 = 0.f, rs1 = 0.f;
        #pragma unroll
        for (int nt = 0; nt < 8; nt++) {
            S[nt][0] = __expf(S[nt][0] - nm0);
            S[nt][1] = __expf(S[nt][1] - nm0);
            S[nt][2] = __expf(S[nt][2] - nm1);
            S[nt][3] = __expf(S[nt][3] - nm1);
            rs0 += S[nt][0] + S[nt][1];
            rs1 += S[nt][2] + S[nt][3];
        }
        rs0 += __shfl_xor_sync(FULL, rs0, 1);
        rs0 += __shfl_xor_sync(FULL, rs0, 2);
        rs1 += __shfl_xor_sync(FULL, rs1, 1);
        rs1 += __shfl_xor_sync(FULL, rs1, 2);
        L0 = L0*sc0 + rs0;
        L1 = L1*sc1 + rs1;

        // skip O rescale when max unchanged (warp-uniform in practice per half)
        if (!__all_sync(FULL, (sc0 == 1.f) & (sc1 == 1.f))) {
            #pragma unroll
            for (int i = 0; i < 16; i++) {
                O[i][0] *= sc0; O[i][1] *= sc0;
                O[i][2] *= sc1; O[i][3] *= sc1;
            }
        }

        // ---- P: C-fragment -> A-fragment ----
        #pragma unroll
        for (int nt = 0; nt < 8; nt++) {
            float c0 = S[nt][0], c1 = S[nt][1], c2 = S[nt][2], c3 = S[nt][3];
            float s0 = __shfl_sync(FULL, c0, src);
            float s1 = __shfl_sync(FULL, c1, src);
            float s2 = __shfl_sync(FULL, c2, src);
            float s3 = __shfl_sync(FULL, c3, src);
            float t0 = __shfl_sync(FULL, c0, src2);
            float t1 = __shfl_sync(FULL, c1, src2);
            float t2 = __shfl_sync(FULL, c2, src2);
            float t3 = __shfl_sync(FULL, c3, src2);
            S[nt][0] = sel ? s1 : s0;
            S[nt][1] = sel ? s3 : s2;
            S[nt][2] = sel ? t1 : t0;
            S[nt][3] = sel ? t3 : t2;
        }

        if (t < 63) { stageG(s^1, m0 + 64); cp_commit(); cp_wait<2>(); }
        else        cp_wait<0>();
        __syncthreads();

        // ---- O += P g^T over full 128-c G tile ----
        const float* Gt = sG + s*GSTAGE;
        #pragma unroll
        for (int k = 0; k < 8; k++) {
            unsigned a0 = __float_as_uint(S[k][0]);
            unsigned a1 = __float_as_uint(S[k][1]);
            unsigned a2 = __float_as_uint(S[k][2]);
            unsigned a3 = __float_as_uint(S[k][3]);
            #pragma unroll
            for (int ct = 0; ct < 16; ct++) {
                unsigned b0 = __float_as_uint(Gt[(ct*8 + r)*GSTR + k*8 + cq]);
                unsigned b1 = __float_as_uint(Gt[(ct*8 + r)*GSTR + k*8 + cq + 4]);
                mma_tf32(O[ct], a0, a1, a2, a3, b0, b1);
            }
        }
    }

    // ---- epilogue: y[c][n] ----
    float inv0 = 1.0f / L0, inv1 = 1.0f / L1;
    int q = n0 + qb + r;
    #pragma unroll
    for (int ct = 0; ct < 16; ct++) {
        int c = ct*8 + 2*cq;
        Yb[(size_t)c*NPIX + q]          = O[ct][0] * inv0;
        Yb[(size_t)(c+1)*NPIX + q]      = O[ct][1] * inv0;
        Yb[(size_t)c*NPIX + q + 8]      = O[ct][2] * inv1;
        Yb[(size_t)(c+1)*NPIX + q + 8]  = O[ct][3] * inv1;
    }
}

// ---------------- final: out = GN2(z)*0.1 + xs (finalize fused) ------------------
__global__ void final_apply_kernel(const float* __restrict__ gw,
                                   const float* __restrict__ gb,
                                   float* __restrict__ out) {
    __shared__ float st[2];
    int bg = blockIdx.x >> 7;
    if (threadIdx.x == 0) {
        float S = 0.f, S2 = 0.f;
        #pragma unroll
        for (int i = 0; i < 16; i++) {
            S  += d_part2[(bg*16 + i)*2];
            S2 += d_part2[(bg*16 + i)*2 + 1];
        }
        float mean = S / (float)GSIZE;
        st[0] = mean;
        st[1] = rsqrtf(S2 / (float)GSIZE - mean*mean + EPSV);
    }
    __syncthreads();
    int i4 = blockIdx.x * blockDim.x + threadIdx.x;
    int idx = i4 << 2;
    int c   = (idx >> 12) & 255;
    float sc = st[1] * gw[c];
    float sh = gb[c] - st[0] * sc;
    float4 z = ((const float4*)d_z)[i4];
    float4 xs = ((const float4*)d_xs)[i4];
    float4 o;
    o.x = (z.x*sc + sh)*0.1f + xs.x;
    o.y = (z.y*sc + sh)*0.1f + xs.y;
    o.z = (z.z*sc + sh)*0.1f + xs.z;
    o.w = (z.w*sc + sh)*0.1f + xs.w;
    ((float4*)out)[i4] = o;
}

// ---------------- launch ---------------------------------------------------------
extern "C" void kernel_launch(void* const* d_in, const int* in_sizes, int n_in,
                              void* d_out, int out_size) {
    const float* x    = (const float*)d_in[0];
    const float* sw   = (const float*)d_in[1];
    const float* sb   = (const float*)d_in[2];
    const float* gn1w = (const float*)d_in[3];
    const float* gn1b = (const float*)d_in[4];
    const float* g_w  = (const float*)d_in[5];
    const float* g_b  = (const float*)d_in[6];
    const float* th_w = (const float*)d_in[7];
    const float* th_b = (const float*)d_in[8];
    const float* ph_w = (const float*)d_in[9];
    const float* ph_b = (const float*)d_in[10];
    const float* w_w  = (const float*)d_in[11];
    const float* w_b  = (const float*)d_in[12];
    const float* gn2w = (const float*)d_in[13];
    const float* gn2b = (const float*)d_in[14];
    float* out = (float*)d_out;

    const int convSmem = 2 * 2 * CONV_STAGE * 4;
    static int attrSet = 0;
    if (!attrSet) {
        cudaFuncSetAttribute(conv_tc_kernel,
                             cudaFuncAttributeMaxDynamicSharedMemorySize, convSmem);
        cudaFuncSetAttribute(attention_tc_kernel,
                             cudaFuncAttributeMaxDynamicSharedMemorySize, ATTN_SMEM);
        attrSet = 1;
    }

    pack_wsplit_kernel<<<(KCONV*CCH + 255)/256, 256>>>(sw);
    split_x_kernel<<<(BATCH*CCH*NPIX + 255)/256, 256>>>(x);
    conv_tc_kernel<<<dim3(32, 2, 4), 256, convSmem>>>(sb);
    gn_part_kernel<<<512, 256>>>(0);
    gn1_apply_kernel<<<4096, 256>>>(gn1w, gn1b);

    gemm_tc_kernel<0><<<dim3(32, 2, 4), 256>>>(th_w, th_b);
    gemm_tc_kernel<1><<<dim3(32, 2, 4), 256>>>(ph_w, ph_b);
    gemm_tc_kernel<2><<<dim3(32, 2, 4), 256>>>(g_w, g_b);

    attention_tc_kernel<<<dim3(32, 4), 256, ATTN_SMEM>>>();

    gemm_tc_kernel<3><<<dim3(32, 4, 4), 256>>>(w_w, w_b);
    gn_part_kernel<<<512, 256>>>(1);
    final_apply_kernel<<<4096, 256>>>(gn2w, gn2b, out);

    (void)in_sizes; (void)n_in; (void)out_size;
}

// round 6
// speedup vs baseline: 5.0133x; 1.8585x over previous
#include <cuda_runtime.h>
#include <cuda_bf16.h>
#include <math.h>
#include <stdint.h>

#define BATCH 4
#define CCH   256
#define CI    128
#define NPIX  4096
#define GROUPS 8
#define CPG   32
#define GSIZE (CPG*NPIX)
#define EPSV  1e-5f
#define KCONV 2304            // 9 taps * 256 cin, tap-major

// ---------------- scratch ----------------------------------------------------
__device__ float d_xs   [BATCH*CCH*NPIX];
__device__ float d_theta[BATCH*CI*NPIX];    // [b][c][n] fp32
__device__ float d_phi  [BATCH*CI*NPIX];    // [b][c][n] fp32
__device__ float d_y    [BATCH*CI*NPIX];    // [b][c][n] fp32
__device__ float d_z    [BATCH*CCH*NPIX];
__device__ __nv_bfloat16 d_wb [CCH*KCONV];  // weight big   [m][k]
__device__ __nv_bfloat16 d_ws [CCH*KCONV];  // weight small [m][k]
__device__ __nv_bfloat16 d_xtb[BATCH*NPIX*CCH];  // x big  [b][pix][c]
__device__ __nv_bfloat16 d_xts[BATCH*NPIX*CCH];  // x small
__device__ __nv_bfloat16 d_ttb[BATCH*NPIX*CI];   // thetaT [b][n][c]
__device__ __nv_bfloat16 d_ptb[BATCH*NPIX*CI];   // phiT   [b][n][c]
__device__ __nv_bfloat16 d_gb [BATCH*CI*NPIX];   // g bf16 [b][c][n]
__device__ float d_part1[32*16*2];
__device__ float d_part2[32*16*2];

// ---------------- helpers -----------------------------------------------------
__device__ __forceinline__ void mma_tf32(float* c,
    unsigned a0, unsigned a1, unsigned a2, unsigned a3,
    unsigned b0, unsigned b1) {
    asm volatile(
        "mma.sync.aligned.m16n8k8.row.col.f32.tf32.tf32.f32 "
        "{%0,%1,%2,%3}, {%4,%5,%6,%7}, {%8,%9}, {%0,%1,%2,%3};"
        : "+f"(c[0]), "+f"(c[1]), "+f"(c[2]), "+f"(c[3])
        : "r"(a0), "r"(a1), "r"(a2), "r"(a3), "r"(b0), "r"(b1));
}
__device__ __forceinline__ void mma_bf16(float* c,
    unsigned a0, unsigned a1, unsigned a2, unsigned a3,
    unsigned b0, unsigned b1) {
    asm volatile(
        "mma.sync.aligned.m16n8k16.row.col.f32.bf16.bf16.f32 "
        "{%0,%1,%2,%3}, {%4,%5,%6,%7}, {%8,%9}, {%0,%1,%2,%3};"
        : "+f"(c[0]), "+f"(c[1]), "+f"(c[2]), "+f"(c[3])
        : "r"(a0), "r"(a1), "r"(a2), "r"(a3), "r"(b0), "r"(b1));
}
__device__ __forceinline__ unsigned pack_bf(float hi, float lo) {
    unsigned u;
    asm("cvt.rn.bf16x2.f32 %0, %1, %2;" : "=r"(u) : "f"(hi), "f"(lo));
    return u;
}
__device__ __forceinline__ void cp16(uint32_t dst, const void* src) {
    asm volatile("cp.async.cg.shared.global [%0], [%1], 16;" :: "r"(dst), "l"(src));
}
__device__ __forceinline__ void cp16z(uint32_t dst, const void* src, int srcsz) {
    asm volatile("cp.async.cg.shared.global [%0], [%1], 16, %2;"
                 :: "r"(dst), "l"(src), "r"(srcsz));
}
__device__ __forceinline__ void cp_commit() {
    asm volatile("cp.async.commit_group;");
}
template<int N>
__device__ __forceinline__ void cp_wait() {
    asm volatile("cp.async.wait_group %0;" :: "n"(N));
}
__device__ __forceinline__ uint32_t smem_u32(const void* p) {
    return (uint32_t)__cvta_generic_to_shared(p);
}
__device__ __forceinline__ unsigned ldu(const float* p) {
    return __float_as_uint(*p);
}

// ---------------- precompute: weight 2-term bf16 split [o][c][tap]->[m][k] ----
__global__ void pack_w_bf_kernel(const float* __restrict__ w) {
    int k = blockIdx.x * 256 + threadIdx.x;   // grid (9, 256)
    int m = blockIdx.y;
    int c = k & 255, tap = k >> 8;
    float f = w[m*(CCH*9) + c*9 + tap];
    __nv_bfloat16 big = __float2bfloat16(f);
    d_wb[(size_t)m*KCONV + k] = big;
    d_ws[(size_t)m*KCONV + k] = __float2bfloat16(f - __bfloat162float(big));
}

// ---------------- precompute: x transpose + split -> [b][pix][c] bf16 ---------
__global__ void prep_x_kernel(const float* __restrict__ x) {
    __shared__ float t[32][33];
    int b  = blockIdx.z;
    int p0 = blockIdx.x * 32;
    int c0 = blockIdx.y * 32;
    int tx = threadIdx.x, ty = threadIdx.y;
    #pragma unroll
    for (int i = 0; i < 4; i++)
        t[ty + i*8][tx] = x[(size_t)(b*CCH + c0 + ty + i*8)*NPIX + p0 + tx];
    __syncthreads();
    #pragma unroll
    for (int i = 0; i < 4; i++) {
        int p = ty + i*8;
        float f = t[tx][p];
        __nv_bfloat16 big = __float2bfloat16(f);
        size_t o = (size_t)(b*NPIX + p0 + p)*CCH + c0 + tx;
        d_xtb[o] = big;
        d_xts[o] = __float2bfloat16(f - __bfloat162float(big));
    }
}

// ---------------- prep attention: transpose theta/phi -> [n][c] bf16 ----------
__global__ void prep_attn_kernel() {
    __shared__ float t[32][33];
    int which = blockIdx.z & 1, b = blockIdx.z >> 1;
    const float* src = (which ? d_phi : d_theta) + (size_t)b*CI*NPIX;
    __nv_bfloat16* dst = (which ? d_ptb : d_ttb) + (size_t)b*NPIX*CI;
    int n0 = blockIdx.x * 32, c0 = blockIdx.y * 32;
    int tx = threadIdx.x, ty = threadIdx.y;
    #pragma unroll
    for (int i = 0; i < 4; i++)
        t[ty + i*8][tx] = src[(size_t)(c0 + ty + i*8)*NPIX + n0 + tx];
    __syncthreads();
    #pragma unroll
    for (int i = 0; i < 4; i++) {
        int n = ty + i*8;
        dst[(size_t)(n0 + n)*CI + c0 + tx] = __float2bfloat16(t[tx][n]);
    }
}

// ---------------- conv3x3 implicit GEMM, bf16 2-term (3 mma), pipelined -------
// smem per stage: [Ab | As | Bb | Bs], each 128 rows x 20 floats (40 bf16)
#define CV_ROW 20
#define CV_PLANE (128*CV_ROW)        // 2560 floats
#define CV_STAGE (4*CV_PLANE)        // 10240 floats
#define CONV_SMEM (2*CV_STAGE*4)     // 81920 bytes

__global__ void __launch_bounds__(256) conv_tc_kernel(const float* __restrict__ sb) {
    extern __shared__ float smem[];

    int b    = blockIdx.z;
    int m0   = blockIdx.y * 128;
    int pix0 = blockIdx.x * 128;
    int h0   = pix0 >> 6;

    int tid  = threadIdx.x;
    int lane = tid & 31;
    int wid  = tid >> 5;
    int wm = wid >> 2, wn = wid & 3;
    int r  = lane >> 2, cq = lane & 3;

    uint32_t base = smem_u32(smem);

    // staging maps: 1024 cp16 per tile-pair, 4 per thread
    // A: plane p, row, seg(16B of 4): idx = p*512 + row*4 + seg
    // B: same shape
    float C[16][4];
    #pragma unroll
    for (int i = 0; i < 16; i++)
        #pragma unroll
        for (int j = 0; j < 4; j++) C[i][j] = 0.f;

    auto stage = [&](int st, int kc) {
        int tap = kc >> 8;
        int c0  = kc & 255;
        int ky  = tap/3 - 1;
        int kx  = tap - (tap/3)*3 - 1;
        uint32_t sb0 = base + (uint32_t)(st*CV_STAGE*4);
        #pragma unroll
        for (int j = 0; j < 4; j++) {
            int idx = tid + j*256;          // 0..1023
            int p   = idx >> 9;
            int rem = idx & 511;
            int row = rem >> 2;
            int seg = rem & 3;
            // A
            const __nv_bfloat16* wsrc = (p ? d_ws : d_wb)
                + (size_t)(m0 + row)*KCONV + kc + seg*8;
            cp16(sb0 + (uint32_t)((p*CV_PLANE + row*CV_ROW + seg*4)*4), wsrc);
            // B (im2col)
            int h = h0 + (row >> 6) + ky;
            int w = (row & 63) + kx;
            int valid = ((unsigned)h < 64u) & ((unsigned)w < 64u);
            int pix = valid ? (h*64 + w) : 0;
            const __nv_bfloat16* xsrc = (p ? d_xts : d_xtb)
                + (size_t)(b*NPIX + pix)*CCH + c0 + seg*8;
            cp16z(sb0 + (uint32_t)(((2+p)*CV_PLANE + row*CV_ROW + seg*4)*4),
                  xsrc, valid ? 16 : 0);
        }
    };

    stage(0, 0);
    cp_commit();

    for (int it = 0; it < 72; it++) {
        if (it < 71) { stage((it+1) & 1, (it+1)*32); cp_commit(); cp_wait<1>(); }
        else cp_wait<0>();
        __syncthreads();

        const float* St = smem + (it & 1)*CV_STAGE;
        const float* Ab = St;
        const float* Am = St + CV_PLANE;
        const float* Bb = St + 2*CV_PLANE;
        const float* Bm = St + 3*CV_PLANE;

        #pragma unroll
        for (int ch = 0; ch < 2; ch++) {
            int ko = ch*8 + cq;
            unsigned ab[4][4], as_[4][4];
            #pragma unroll
            for (int mt = 0; mt < 4; mt++) {
                int m = wm*64 + mt*16 + r;
                ab[mt][0] = ldu(&Ab[m*CV_ROW + ko]);
                ab[mt][1] = ldu(&Ab[(m+8)*CV_ROW + ko]);
                ab[mt][2] = ldu(&Ab[m*CV_ROW + ko + 4]);
                ab[mt][3] = ldu(&Ab[(m+8)*CV_ROW + ko + 4]);
                as_[mt][0] = ldu(&Am[m*CV_ROW + ko]);
                as_[mt][1] = ldu(&Am[(m+8)*CV_ROW + ko]);
                as_[mt][2] = ldu(&Am[m*CV_ROW + ko + 4]);
                as_[mt][3] = ldu(&Am[(m+8)*CV_ROW + ko + 4]);
            }
            unsigned bb[4][2], bs[4][2];
            #pragma unroll
            for (int nt = 0; nt < 4; nt++) {
                int n = wn*32 + nt*8 + r;
                bb[nt][0] = ldu(&Bb[n*CV_ROW + ko]);
                bb[nt][1] = ldu(&Bb[n*CV_ROW + ko + 4]);
                bs[nt][0] = ldu(&Bm[n*CV_ROW + ko]);
                bs[nt][1] = ldu(&Bm[n*CV_ROW + ko + 4]);
            }
            #pragma unroll
            for (int mt = 0; mt < 4; mt++)
                #pragma unroll
                for (int nt = 0; nt < 4; nt++)
                    mma_bf16(C[mt*4+nt], ab[mt][0], ab[mt][1], ab[mt][2], ab[mt][3],
                             bb[nt][0], bb[nt][1]);
            #pragma unroll
            for (int mt = 0; mt < 4; mt++)
                #pragma unroll
                for (int nt = 0; nt < 4; nt++)
                    mma_bf16(C[mt*4+nt], ab[mt][0], ab[mt][1], ab[mt][2], ab[mt][3],
                             bs[nt][0], bs[nt][1]);
            #pragma unroll
            for (int mt = 0; mt < 4; mt++)
                #pragma unroll
                for (int nt = 0; nt < 4; nt++)
                    mma_bf16(C[mt*4+nt], as_[mt][0], as_[mt][1], as_[mt][2], as_[mt][3],
                             bb[nt][0], bb[nt][1]);
        }
        __syncthreads();
    }

    #pragma unroll
    for (int mt = 0; mt < 4; mt++) {
        int m = m0 + wm*64 + mt*16 + r;
        float bv0 = sb[m], bv8 = sb[m + 8];
        #pragma unroll
        for (int nt = 0; nt < 4; nt++) {
            int n = pix0 + wn*32 + nt*8 + 2*cq;
            float* cf = C[mt*4 + nt];
            *(float2*)&d_xs[((size_t)(b*CCH + m))*NPIX + n]     = make_float2(cf[0]+bv0, cf[1]+bv0);
            *(float2*)&d_xs[((size_t)(b*CCH + m + 8))*NPIX + n] = make_float2(cf[2]+bv8, cf[3]+bv8);
        }
    }
}

// ---------------- GroupNorm partial sums ----------------------------------------
__global__ void gn_part_kernel(int which) {
    const float* src = which ? d_z : d_xs;
    float* part      = which ? d_part2 : d_part1;
    int blk = blockIdx.x;
    int bg = blk >> 4, ch = blk & 15;
    const float4* p = (const float4*)(src + (size_t)bg*GSIZE + ch*(GSIZE/16));
    float s = 0.f, s2 = 0.f;
    #pragma unroll
    for (int i = 0; i < 8; i++) {
        float4 v = p[threadIdx.x + i*256];
        s  += v.x + v.y + v.z + v.w;
        s2 += v.x*v.x + v.y*v.y + v.z*v.z + v.w*v.w;
    }
    #pragma unroll
    for (int off = 16; off > 0; off >>= 1) {
        s  += __shfl_xor_sync(0xffffffffu, s,  off);
        s2 += __shfl_xor_sync(0xffffffffu, s2, off);
    }
    __shared__ float sh[16];
    int wid = threadIdx.x >> 5, lid = threadIdx.x & 31;
    if (lid == 0) { sh[wid] = s; sh[wid + 8] = s2; }
    __syncthreads();
    if (threadIdx.x == 0) {
        float S = 0.f, S2 = 0.f;
        #pragma unroll
        for (int w = 0; w < 8; w++) { S += sh[w]; S2 += sh[w + 8]; }
        part[blk*2]     = S;
        part[blk*2 + 1] = S2;
    }
}

// ---------------- GN1 apply + ReLU ----------------------------------------------
__global__ void gn1_apply_kernel(const float* __restrict__ gw,
                                 const float* __restrict__ gb) {
    __shared__ float st[2];
    int bg = blockIdx.x >> 7;
    if (threadIdx.x == 0) {
        float S = 0.f, S2 = 0.f;
        #pragma unroll
        for (int i = 0; i < 16; i++) {
            S  += d_part1[(bg*16 + i)*2];
            S2 += d_part1[(bg*16 + i)*2 + 1];
        }
        float mean = S / (float)GSIZE;
        st[0] = mean;
        st[1] = rsqrtf(S2 / (float)GSIZE - mean*mean + EPSV);
    }
    __syncthreads();
    int i4 = blockIdx.x * blockDim.x + threadIdx.x;
    int idx = i4 << 2;
    int c   = (idx >> 12) & 255;
    float sc = st[1] * gw[c];
    float sh = gb[c] - st[0] * sc;
    float4 v = ((float4*)d_xs)[i4];
    v.x = fmaxf(v.x*sc + sh, 0.f);
    v.y = fmaxf(v.y*sc + sh, 0.f);
    v.z = fmaxf(v.z*sc + sh, 0.f);
    v.w = fmaxf(v.w*sc + sh, 0.f);
    ((float4*)d_xs)[i4] = v;
}

// ---------------- tf32 1x1 GEMM (MODE2 writes bf16 g) ---------------------------
template<int MODE>
__global__ void __launch_bounds__(256) gemm_tc_kernel(const float* __restrict__ W,
                                                      const float* __restrict__ bias) {
    constexpr int K  = (MODE == 3) ? 128 : 256;
    constexpr int NI = K / 16;
    const float* X = (MODE == 3) ? d_y : d_xs;
    float* out = (MODE == 0) ? d_theta : (MODE == 1) ? d_phi : d_z;

    __shared__ float Ws[2][64*20];
    __shared__ float Xs[2][16*136];

    int b  = blockIdx.z;
    int n0 = blockIdx.x * 128;
    int m0 = blockIdx.y * 64;
    const float* Xb = X + (size_t)b * K * NPIX;
    float* Ob = out + (size_t)b * ((MODE==3)?CCH:CI) * NPIX;

    int tid  = threadIdx.x;
    int lane = tid & 31;
    int wid  = tid >> 5;
    int wm = wid >> 2, wn = wid & 3;
    int r  = lane >> 2, cq = lane & 3;

    int wRow = tid >> 2, wSeg = tid & 3;
    int xRow = tid >> 5, xSeg = tid & 31;
    uint32_t wBase = smem_u32(Ws);
    uint32_t xBase = smem_u32(Xs);

    auto stage = [&](int s, int kc) {
        cp16(wBase + (uint32_t)((s*64*20 + wRow*20 + wSeg*4)*4),
             W + (size_t)(m0 + wRow)*K + kc + wSeg*4);
        #pragma unroll
        for (int j = 0; j < 2; j++) {
            int k = xRow + j*8;
            cp16(xBase + (uint32_t)((s*16*136 + k*136 + xSeg*4)*4),
                 Xb + (size_t)(kc + k)*NPIX + n0 + xSeg*4);
        }
    };

    float C[8][4];
    #pragma unroll
    for (int i = 0; i < 8; i++)
        #pragma unroll
        for (int j = 0; j < 4; j++) C[i][j] = 0.f;

    stage(0, 0);
    cp_commit();

    for (int it = 0; it < NI; it++) {
        if (it < NI-1) { stage((it+1)&1, (it+1)*16); cp_commit(); cp_wait<1>(); }
        else cp_wait<0>();
        __syncthreads();

        const float* Wt = Ws[it & 1];
        const float* Xt = Xs[it & 1];

        #pragma unroll
        for (int k8 = 0; k8 < 2; k8++) {
            int kk = k8*8 + cq;
            unsigned a[2][4];
            #pragma unroll
            for (int mt = 0; mt < 2; mt++) {
                int mr = wm*32 + mt*16 + r;
                a[mt][0] = __float_as_uint(Wt[mr*20 + kk]);
                a[mt][1] = __float_as_uint(Wt[(mr+8)*20 + kk]);
                a[mt][2] = __float_as_uint(Wt[mr*20 + kk + 4]);
                a[mt][3] = __float_as_uint(Wt[(mr+8)*20 + kk + 4]);
            }
            #pragma unroll
            for (int nt = 0; nt < 4; nt++) {
                int nn = wn*32 + nt*8 + r;
                unsigned b0 = __float_as_uint(Xt[kk*136 + nn]);
                unsigned b1 = __float_as_uint(Xt[(kk+4)*136 + nn]);
                mma_tf32(C[nt],     a[0][0], a[0][1], a[0][2], a[0][3], b0, b1);
                mma_tf32(C[4 + nt], a[1][0], a[1][1], a[1][2], a[1][3], b0, b1);
            }
        }
        __syncthreads();
    }

    #pragma unroll
    for (int mt = 0; mt < 2; mt++) {
        int m = m0 + wm*32 + mt*16 + r;
        float bv0 = bias[m], bv8 = bias[m + 8];
        #pragma unroll
        for (int nt = 0; nt < 4; nt++) {
            int n = n0 + wn*32 + nt*8 + 2*cq;
            float* cf = C[mt*4 + nt];
            if (MODE == 2) {
                *(unsigned*)&d_gb[((size_t)(b*CI + m))*NPIX + n] =
                    pack_bf(cf[1]+bv0, cf[0]+bv0);
                *(unsigned*)&d_gb[((size_t)(b*CI + m + 8))*NPIX + n] =
                    pack_bf(cf[3]+bv8, cf[2]+bv8);
            } else {
                *(float2*)&Ob[(size_t)m*NPIX + n]      = make_float2(cf[0]+bv0, cf[1]+bv0);
                *(float2*)&Ob[(size_t)(m+8)*NPIX + n]  = make_float2(cf[2]+bv8, cf[3]+bv8);
            }
        }
    }
}

// ---------------- bf16 flash attention ------------------------------------------
// smem: [K0 | K1 | G0 | G1]; K stage 64x68f, G stage 128x36f; Q scratch = K0+K1
#define KS_STR 68
#define KS_STAGE (64*KS_STR)      // 4352 floats
#define GS_STR 36
#define GS_STAGE (128*GS_STR)     // 4608 floats
#define ATTN_SMEM ((2*KS_STAGE + 2*GS_STAGE)*4)   // 71680 bytes

__global__ void __launch_bounds__(256) attention_tc_kernel() {
    extern __shared__ float smem[];
    float* sK = smem;
    float* sG = smem + 2*KS_STAGE;

    int b  = blockIdx.y;
    int n0 = blockIdx.x * 128;
    const __nv_bfloat16* Tt = d_ttb + (size_t)b * NPIX * CI;  // [n][c]
    const __nv_bfloat16* Pt = d_ptb + (size_t)b * NPIX * CI;  // [n][c]
    const __nv_bfloat16* Gp = d_gb  + (size_t)b * CI * NPIX;  // [c][n]
    float* Yb = d_y + (size_t)b * CI * NPIX;

    int tid  = threadIdx.x;
    int lane = tid & 31;
    int wid  = tid >> 5;
    int qb   = wid * 16;
    int r    = lane >> 2;
    int cq   = lane & 3;

    uint32_t kBase = smem_u32(sK);
    uint32_t gBase = smem_u32(sG);

    auto stageK = [&](int s, int m0k) {
        #pragma unroll
        for (int j = 0; j < 4; j++) {
            int idx = tid + j*256;          // 64 rows x 16 segs
            int row = idx >> 4, seg = idx & 15;
            cp16(kBase + (uint32_t)((s*KS_STAGE + row*KS_STR + seg*4)*4),
                 Pt + (size_t)(m0k + row)*CI + seg*8);
        }
    };
    auto stageG = [&](int s, int m0k) {
        #pragma unroll
        for (int j = 0; j < 4; j++) {
            int idx = tid + j*256;          // 128 rows x 8 segs
            int row = idx >> 3, seg = idx & 7;
            cp16(gBase + (uint32_t)((s*GS_STAGE + row*GS_STR + seg*4)*4),
                 Gp + (size_t)row*NPIX + m0k + seg*8);
        }
    };

    // ---- Q prologue: stage 128q x 128c bf16 into K buffers, extract frags ----
    #pragma unroll
    for (int j = 0; j < 8; j++) {
        int idx = tid + j*256;              // 128 rows x 16 segs
        int row = idx >> 4, seg = idx & 15;
        cp16(kBase + (uint32_t)((row*KS_STR + seg*4)*4),
             Tt + (size_t)(n0 + row)*CI + seg*8);
    }
    cp_commit();
    cp_wait<0>();
    __syncthreads();

    unsigned qa[8][4];
    #pragma unroll
    for (int ch = 0; ch < 8; ch++) {
        int ko = ch*8 + cq;
        qa[ch][0] = ldu(&sK[(qb + r)*KS_STR + ko]);
        qa[ch][1] = ldu(&sK[(qb + r + 8)*KS_STR + ko]);
        qa[ch][2] = ldu(&sK[(qb + r)*KS_STR + ko + 4]);
        qa[ch][3] = ldu(&sK[(qb + r + 8)*KS_STR + ko + 4]);
    }
    __syncthreads();

    stageK(0, 0); cp_commit();
    stageG(0, 0); cp_commit();

    float O[16][4];
    #pragma unroll
    for (int i = 0; i < 16; i++)
        #pragma unroll
        for (int j = 0; j < 4; j++) O[i][j] = 0.f;
    float Mx0 = -1e30f, Mx1 = -1e30f, L0 = 0.f, L1 = 0.f;
    const unsigned FULL = 0xffffffffu;

    for (int t = 0; t < 64; t++) {
        int s = t & 1;
        int m0 = t * 64;

        if (t < 63) { stageK(s^1, m0 + 64); cp_commit(); cp_wait<2>(); }
        else        cp_wait<1>();
        __syncthreads();

        // ---- S = Q K^T : 8 k16-chunks x 8 nt ----
        const float* Kt = sK + s*KS_STAGE;
        float S[8][4];
        #pragma unroll
        for (int i = 0; i < 8; i++)
            #pragma unroll
            for (int j = 0; j < 4; j++) S[i][j] = 0.f;

        #pragma unroll
        for (int ch = 0; ch < 8; ch++) {
            int ko = ch*8 + cq;
            #pragma unroll
            for (int nt = 0; nt < 8; nt++) {
                unsigned b0 = ldu(&Kt[(nt*8 + r)*KS_STR + ko]);
                unsigned b1 = ldu(&Kt[(nt*8 + r)*KS_STR + ko + 4]);
                mma_bf16(S[nt], qa[ch][0], qa[ch][1], qa[ch][2], qa[ch][3], b0, b1);
            }
        }

        // ---- online softmax ----
        float rm0 = -1e30f, rm1 = -1e30f;
        #pragma unroll
        for (int nt = 0; nt < 8; nt++) {
            rm0 = fmaxf(rm0, fmaxf(S[nt][0], S[nt][1]));
            rm1 = fmaxf(rm1, fmaxf(S[nt][2], S[nt][3]));
        }
        rm0 = fmaxf(rm0, __shfl_xor_sync(FULL, rm0, 1));
        rm0 = fmaxf(rm0, __shfl_xor_sync(FULL, rm0, 2));
        rm1 = fmaxf(rm1, __shfl_xor_sync(FULL, rm1, 1));
        rm1 = fmaxf(rm1, __shfl_xor_sync(FULL, rm1, 2));

        float nm0 = fmaxf(Mx0, rm0), nm1 = fmaxf(Mx1, rm1);
        float sc0 = __expf(Mx0 - nm0), sc1 = __expf(Mx1 - nm1);
        Mx0 = nm0; Mx1 = nm1;

        float rs0 = 0.f, rs1 = 0.f;
        #pragma unroll
        for (int nt = 0; nt < 8; nt++) {
            S[nt][0] = __expf(S[nt][0] - nm0);
            S[nt][1] = __expf(S[nt][1] - nm0);
            S[nt][2] = __expf(S[nt][2] - nm1);
            S[nt][3] = __expf(S[nt][3] - nm1);
            rs0 += S[nt][0] + S[nt][1];
            rs1 += S[nt][2] + S[nt][3];
        }
        rs0 += __shfl_xor_sync(FULL, rs0, 1);
        rs0 += __shfl_xor_sync(FULL, rs0, 2);
        rs1 += __shfl_xor_sync(FULL, rs1, 1);
        rs1 += __shfl_xor_sync(FULL, rs1, 2);
        L0 = L0*sc0 + rs0;
        L1 = L1*sc1 + rs1;

        if (!__all_sync(FULL, (sc0 == 1.f) & (sc1 == 1.f))) {
            #pragma unroll
            for (int i = 0; i < 16; i++) {
                O[i][0] *= sc0; O[i][1] *= sc0;
                O[i][2] *= sc1; O[i][3] *= sc1;
            }
        }

        // ---- P: pack C-fragments into bf16 A-fragments (no shuffles) ----
        unsigned pa[4][4];
        #pragma unroll
        for (int kc = 0; kc < 4; kc++) {
            pa[kc][0] = pack_bf(S[2*kc][1],   S[2*kc][0]);
            pa[kc][1] = pack_bf(S[2*kc][3],   S[2*kc][2]);
            pa[kc][2] = pack_bf(S[2*kc+1][1], S[2*kc+1][0]);
            pa[kc][3] = pack_bf(S[2*kc+1][3], S[2*kc+1][2]);
        }

        if (t < 63) { stageG(s^1, m0 + 64); cp_commit(); cp_wait<2>(); }
        else        cp_wait<0>();
        __syncthreads();

        // ---- O += P G^T : 4 k16-chunks x 16 ct ----
        const float* Gt = sG + s*GS_STAGE;
        #pragma unroll
        for (int kc = 0; kc < 4; kc++) {
            int ko = kc*8 + cq;
            #pragma unroll
            for (int ct = 0; ct < 16; ct++) {
                unsigned b0 = ldu(&Gt[(ct*8 + r)*GS_STR + ko]);
                unsigned b1 = ldu(&Gt[(ct*8 + r)*GS_STR + ko + 4]);
                mma_bf16(O[ct], pa[kc][0], pa[kc][1], pa[kc][2], pa[kc][3], b0, b1);
            }
        }
    }

    // ---- epilogue: y[c][n] fp32 ----
    float inv0 = 1.0f / L0, inv1 = 1.0f / L1;
    int q = n0 + qb + r;
    #pragma unroll
    for (int ct = 0; ct < 16; ct++) {
        int c = ct*8 + 2*cq;
        Yb[(size_t)c*NPIX + q]          = O[ct][0] * inv0;
        Yb[(size_t)(c+1)*NPIX + q]      = O[ct][1] * inv0;
        Yb[(size_t)c*NPIX + q + 8]      = O[ct][2] * inv1;
        Yb[(size_t)(c+1)*NPIX + q + 8]  = O[ct][3] * inv1;
    }
}

// ---------------- final: out = GN2(z)*0.1 + xs ----------------------------------
__global__ void final_apply_kernel(const float* __restrict__ gw,
                                   const float* __restrict__ gb,
                                   float* __restrict__ out) {
    __shared__ float st[2];
    int bg = blockIdx.x >> 7;
    if (threadIdx.x == 0) {
        float S = 0.f, S2 = 0.f;
        #pragma unroll
        for (int i = 0; i < 16; i++) {
            S  += d_part2[(bg*16 + i)*2];
            S2 += d_part2[(bg*16 + i)*2 + 1];
        }
        float mean = S / (float)GSIZE;
        st[0] = mean;
        st[1] = rsqrtf(S2 / (float)GSIZE - mean*mean + EPSV);
    }
    __syncthreads();
    int i4 = blockIdx.x * blockDim.x + threadIdx.x;
    int idx = i4 << 2;
    int c   = (idx >> 12) & 255;
    float sc = st[1] * gw[c];
    float sh = gb[c] - st[0] * sc;
    float4 z = ((const float4*)d_z)[i4];
    float4 xs = ((const float4*)d_xs)[i4];
    float4 o;
    o.x = (z.x*sc + sh)*0.1f + xs.x;
    o.y = (z.y*sc + sh)*0.1f + xs.y;
    o.z = (z.z*sc + sh)*0.1f + xs.z;
    o.w = (z.w*sc + sh)*0.1f + xs.w;
    ((float4*)out)[i4] = o;
}

// ---------------- launch ---------------------------------------------------------
extern "C" void kernel_launch(void* const* d_in, const int* in_sizes, int n_in,
                              void* d_out, int out_size) {
    const float* x    = (const float*)d_in[0];
    const float* sw   = (const float*)d_in[1];
    const float* sb   = (const float*)d_in[2];
    const float* gn1w = (const float*)d_in[3];
    const float* gn1b = (const float*)d_in[4];
    const float* g_w  = (const float*)d_in[5];
    const float* g_b  = (const float*)d_in[6];
    const float* th_w = (const float*)d_in[7];
    const float* th_b = (const float*)d_in[8];
    const float* ph_w = (const float*)d_in[9];
    const float* ph_b = (const float*)d_in[10];
    const float* w_w  = (const float*)d_in[11];
    const float* w_b  = (const float*)d_in[12];
    const float* gn2w = (const float*)d_in[13];
    const float* gn2b = (const float*)d_in[14];
    float* out = (float*)d_out;

    static int attrSet = 0;
    if (!attrSet) {
        cudaFuncSetAttribute(conv_tc_kernel,
                             cudaFuncAttributeMaxDynamicSharedMemorySize, CONV_SMEM);
        cudaFuncSetAttribute(attention_tc_kernel,
                             cudaFuncAttributeMaxDynamicSharedMemorySize, ATTN_SMEM);
        attrSet = 1;
    }

    pack_w_bf_kernel<<<dim3(9, 256), 256>>>(sw);
    prep_x_kernel<<<dim3(128, 8, 4), dim3(32, 8)>>>(x);
    conv_tc_kernel<<<dim3(32, 2, 4), 256, CONV_SMEM>>>(sb);
    gn_part_kernel<<<512, 256>>>(0);
    gn1_apply_kernel<<<4096, 256>>>(gn1w, gn1b);

    gemm_tc_kernel<0><<<dim3(32, 2, 4), 256>>>(th_w, th_b);
    gemm_tc_kernel<1><<<dim3(32, 2, 4), 256>>>(ph_w, ph_b);
    gemm_tc_kernel<2><<<dim3(32, 2, 4), 256>>>(g_w, g_b);
    prep_attn_kernel<<<dim3(128, 4, 8), dim3(32, 8)>>>();

    attention_tc_kernel<<<dim3(32, 4), 256, ATTN_SMEM>>>();

    gemm_tc_kernel<3><<<dim3(32, 4, 4), 256>>>(w_w, w_b);
    gn_part_kernel<<<512, 256>>>(1);
    final_apply_kernel<<<4096, 256>>>(gn2w, gn2b, out);

    (void)in_sizes; (void)n_in; (void)out_size;
}

// round 7
// speedup vs baseline: 5.1758x; 1.0324x over previous
#include <cuda_runtime.h>
#include <cuda_bf16.h>
#include <math.h>
#include <stdint.h>

#define BATCH 4
#define CCH   256
#define CI    128
#define NPIX  4096
#define GROUPS 8
#define CPG   32
#define GSIZE (CPG*NPIX)
#define EPSV  1e-5f
#define KCONV 2304            // 9 taps * 256 cin, tap-major

// ---------------- scratch ----------------------------------------------------
__device__ float d_xs   [BATCH*CCH*NPIX];        // conv out / normalized (fp32)
__device__ float d_z    [BATCH*CCH*NPIX];
__device__ unsigned d_xsb[BATCH*128*NPIX];       // xs bf16 k-pair packed [b][kp][n]
__device__ unsigned d_yb [BATCH*64*NPIX];        // y  bf16 k-pair packed [b][kp][n]
__device__ unsigned d_wpk[65536];                // packed qkv+w weights [m][kp]
__device__ __nv_bfloat16 d_wb [CCH*KCONV];       // conv weight big   [m][k]
__device__ __nv_bfloat16 d_ws [CCH*KCONV];       // conv weight small [m][k]
__device__ __nv_bfloat16 d_xtb[BATCH*NPIX*CCH];  // x big  [b][pix][c]
__device__ __nv_bfloat16 d_xts[BATCH*NPIX*CCH];  // x small
__device__ __nv_bfloat16 d_thb[BATCH*CI*NPIX];   // theta bf16 [b][c][n]
__device__ __nv_bfloat16 d_phb[BATCH*CI*NPIX];   // phi   bf16 [b][c][n]
__device__ __nv_bfloat16 d_ttb[BATCH*NPIX*CI];   // thetaT [b][n][c]
__device__ __nv_bfloat16 d_ptb[BATCH*NPIX*CI];   // phiT   [b][n][c]
__device__ __nv_bfloat16 d_gb [BATCH*CI*NPIX];   // g bf16 [b][c][n]
__device__ float d_part1[32*16*2];
__device__ float d_part2[32*16*2];

// ---------------- helpers -----------------------------------------------------
__device__ __forceinline__ void mma_bf16(float* c,
    unsigned a0, unsigned a1, unsigned a2, unsigned a3,
    unsigned b0, unsigned b1) {
    asm volatile(
        "mma.sync.aligned.m16n8k16.row.col.f32.bf16.bf16.f32 "
        "{%0,%1,%2,%3}, {%4,%5,%6,%7}, {%8,%9}, {%0,%1,%2,%3};"
        : "+f"(c[0]), "+f"(c[1]), "+f"(c[2]), "+f"(c[3])
        : "r"(a0), "r"(a1), "r"(a2), "r"(a3), "r"(b0), "r"(b1));
}
__device__ __forceinline__ unsigned pack_bf(float hi, float lo) {
    unsigned u;
    asm("cvt.rn.bf16x2.f32 %0, %1, %2;" : "=r"(u) : "f"(hi), "f"(lo));
    return u;
}
__device__ __forceinline__ void cp16(uint32_t dst, const void* src) {
    asm volatile("cp.async.cg.shared.global [%0], [%1], 16;" :: "r"(dst), "l"(src));
}
__device__ __forceinline__ void cp16z(uint32_t dst, const void* src, int srcsz) {
    asm volatile("cp.async.cg.shared.global [%0], [%1], 16, %2;"
                 :: "r"(dst), "l"(src), "r"(srcsz));
}
__device__ __forceinline__ void cp_commit() {
    asm volatile("cp.async.commit_group;");
}
template<int N>
__device__ __forceinline__ void cp_wait() {
    asm volatile("cp.async.wait_group %0;" :: "n"(N));
}
__device__ __forceinline__ uint32_t smem_u32(const void* p) {
    return (uint32_t)__cvta_generic_to_shared(p);
}
__device__ __forceinline__ unsigned ldu(const float* p) {
    return __float_as_uint(*p);
}

// ---------------- precompute: conv weight 2-term bf16 split --------------------
__global__ void pack_w_bf_kernel(const float* __restrict__ w) {
    int k = blockIdx.x * 256 + threadIdx.x;   // grid (9, 256)
    int m = blockIdx.y;
    int c = k & 255, tap = k >> 8;
    float f = w[m*(CCH*9) + c*9 + tap];
    __nv_bfloat16 big = __float2bfloat16(f);
    d_wb[(size_t)m*KCONV + k] = big;
    d_ws[(size_t)m*KCONV + k] = __float2bfloat16(f - __bfloat162float(big));
}

// ---------------- precompute: x transpose + split -> [b][pix][c] bf16 ---------
__global__ void prep_x_kernel(const float* __restrict__ x) {
    __shared__ float t[32][33];
    int b  = blockIdx.z;
    int p0 = blockIdx.x * 32;
    int c0 = blockIdx.y * 32;
    int tx = threadIdx.x, ty = threadIdx.y;
    #pragma unroll
    for (int i = 0; i < 4; i++)
        t[ty + i*8][tx] = x[(size_t)(b*CCH + c0 + ty + i*8)*NPIX + p0 + tx];
    __syncthreads();
    #pragma unroll
    for (int i = 0; i < 4; i++) {
        int p = ty + i*8;
        float f = t[tx][p];
        __nv_bfloat16 big = __float2bfloat16(f);
        size_t o = (size_t)(b*NPIX + p0 + p)*CCH + c0 + tx;
        d_xtb[o] = big;
        d_xts[o] = __float2bfloat16(f - __bfloat162float(big));
    }
}

// ---------------- precompute: pack qkv+w weights to bf16x2 k-pairs -------------
// layout: theta @0, phi @16384, g @32768 (each [128][128] u32), w @49152 ([256][64])
__global__ void pack_qkvw_kernel(const float* __restrict__ thw,
                                 const float* __restrict__ phw,
                                 const float* __restrict__ gw_,
                                 const float* __restrict__ ww) {
    int idx = blockIdx.x * 256 + threadIdx.x;   // grid 256 -> 65536
    const float* src;
    int off, loc, K;
    if (idx < 16384)      { src = thw; off = 0;     loc = idx;         K = 256; }
    else if (idx < 32768) { src = phw; off = 16384; loc = idx - 16384; K = 256; }
    else if (idx < 49152) { src = gw_; off = 32768; loc = idx - 32768; K = 256; }
    else                  { src = ww;  off = 49152; loc = idx - 49152; K = 128; }
    int kp = loc & (K/2 - 1);
    int m  = loc / (K/2);
    d_wpk[off + loc] = pack_bf(src[m*K + kp*2 + 1], src[m*K + kp*2]);
}

// ---------------- prep attention: transpose theta/phi bf16 -> [n][c] -----------
__global__ void prep_attn_kernel() {
    __shared__ __nv_bfloat16 t[32][34];
    int which = blockIdx.z & 1, b = blockIdx.z >> 1;
    const __nv_bfloat16* src = (which ? d_phb : d_thb) + (size_t)b*CI*NPIX;
    __nv_bfloat16* dst = (which ? d_ptb : d_ttb) + (size_t)b*NPIX*CI;
    int n0 = blockIdx.x * 32, c0 = blockIdx.y * 32;
    int tx = threadIdx.x, ty = threadIdx.y;
    #pragma unroll
    for (int i = 0; i < 4; i++)
        t[ty + i*8][tx] = src[(size_t)(c0 + ty + i*8)*NPIX + n0 + tx];
    __syncthreads();
    #pragma unroll
    for (int i = 0; i < 4; i++) {
        int n = ty + i*8;
        dst[(size_t)(n0 + n)*CI + c0 + tx] = t[tx][n];
    }
}

// ---------------- conv3x3 implicit GEMM, bf16 2-term (unchanged R6) ------------
#define CV_ROW 20
#define CV_PLANE (128*CV_ROW)
#define CV_STAGE (4*CV_PLANE)
#define CONV_SMEM (2*CV_STAGE*4)

__global__ void __launch_bounds__(256) conv_tc_kernel(const float* __restrict__ sb) {
    extern __shared__ float smem[];

    int b    = blockIdx.z;
    int m0   = blockIdx.y * 128;
    int pix0 = blockIdx.x * 128;
    int h0   = pix0 >> 6;

    int tid  = threadIdx.x;
    int lane = tid & 31;
    int wid  = tid >> 5;
    int wm = wid >> 2, wn = wid & 3;
    int r  = lane >> 2, cq = lane & 3;

    uint32_t base = smem_u32(smem);

    float C[16][4];
    #pragma unroll
    for (int i = 0; i < 16; i++)
        #pragma unroll
        for (int j = 0; j < 4; j++) C[i][j] = 0.f;

    auto stage = [&](int st, int kc) {
        int tap = kc >> 8;
        int c0  = kc & 255;
        int ky  = tap/3 - 1;
        int kx  = tap - (tap/3)*3 - 1;
        uint32_t sb0 = base + (uint32_t)(st*CV_STAGE*4);
        #pragma unroll
        for (int j = 0; j < 4; j++) {
            int idx = tid + j*256;
            int p   = idx >> 9;
            int rem = idx & 511;
            int row = rem >> 2;
            int seg = rem & 3;
            const __nv_bfloat16* wsrc = (p ? d_ws : d_wb)
                + (size_t)(m0 + row)*KCONV + kc + seg*8;
            cp16(sb0 + (uint32_t)((p*CV_PLANE + row*CV_ROW + seg*4)*4), wsrc);
            int h = h0 + (row >> 6) + ky;
            int w = (row & 63) + kx;
            int valid = ((unsigned)h < 64u) & ((unsigned)w < 64u);
            int pix = valid ? (h*64 + w) : 0;
            const __nv_bfloat16* xsrc = (p ? d_xts : d_xtb)
                + (size_t)(b*NPIX + pix)*CCH + c0 + seg*8;
            cp16z(sb0 + (uint32_t)(((2+p)*CV_PLANE + row*CV_ROW + seg*4)*4),
                  xsrc, valid ? 16 : 0);
        }
    };

    stage(0, 0);
    cp_commit();

    for (int it = 0; it < 72; it++) {
        if (it < 71) { stage((it+1) & 1, (it+1)*32); cp_commit(); cp_wait<1>(); }
        else cp_wait<0>();
        __syncthreads();

        const float* St = smem + (it & 1)*CV_STAGE;
        const float* Ab = St;
        const float* Am = St + CV_PLANE;
        const float* Bb = St + 2*CV_PLANE;
        const float* Bm = St + 3*CV_PLANE;

        #pragma unroll
        for (int ch = 0; ch < 2; ch++) {
            int ko = ch*8 + cq;
            unsigned ab[4][4], as_[4][4];
            #pragma unroll
            for (int mt = 0; mt < 4; mt++) {
                int m = wm*64 + mt*16 + r;
                ab[mt][0] = ldu(&Ab[m*CV_ROW + ko]);
                ab[mt][1] = ldu(&Ab[(m+8)*CV_ROW + ko]);
                ab[mt][2] = ldu(&Ab[m*CV_ROW + ko + 4]);
                ab[mt][3] = ldu(&Ab[(m+8)*CV_ROW + ko + 4]);
                as_[mt][0] = ldu(&Am[m*CV_ROW + ko]);
                as_[mt][1] = ldu(&Am[(m+8)*CV_ROW + ko]);
                as_[mt][2] = ldu(&Am[m*CV_ROW + ko + 4]);
                as_[mt][3] = ldu(&Am[(m+8)*CV_ROW + ko + 4]);
            }
            unsigned bb[4][2], bs[4][2];
            #pragma unroll
            for (int nt = 0; nt < 4; nt++) {
                int n = wn*32 + nt*8 + r;
                bb[nt][0] = ldu(&Bb[n*CV_ROW + ko]);
                bb[nt][1] = ldu(&Bb[n*CV_ROW + ko + 4]);
                bs[nt][0] = ldu(&Bm[n*CV_ROW + ko]);
                bs[nt][1] = ldu(&Bm[n*CV_ROW + ko + 4]);
            }
            #pragma unroll
            for (int mt = 0; mt < 4; mt++)
                #pragma unroll
                for (int nt = 0; nt < 4; nt++)
                    mma_bf16(C[mt*4+nt], ab[mt][0], ab[mt][1], ab[mt][2], ab[mt][3],
                             bb[nt][0], bb[nt][1]);
            #pragma unroll
            for (int mt = 0; mt < 4; mt++)
                #pragma unroll
                for (int nt = 0; nt < 4; nt++)
                    mma_bf16(C[mt*4+nt], ab[mt][0], ab[mt][1], ab[mt][2], ab[mt][3],
                             bs[nt][0], bs[nt][1]);
            #pragma unroll
            for (int mt = 0; mt < 4; mt++)
                #pragma unroll
                for (int nt = 0; nt < 4; nt++)
                    mma_bf16(C[mt*4+nt], as_[mt][0], as_[mt][1], as_[mt][2], as_[mt][3],
                             bb[nt][0], bb[nt][1]);
        }
        __syncthreads();
    }

    #pragma unroll
    for (int mt = 0; mt < 4; mt++) {
        int m = m0 + wm*64 + mt*16 + r;
        float bv0 = sb[m], bv8 = sb[m + 8];
        #pragma unroll
        for (int nt = 0; nt < 4; nt++) {
            int n = pix0 + wn*32 + nt*8 + 2*cq;
            float* cf = C[mt*4 + nt];
            *(float2*)&d_xs[((size_t)(b*CCH + m))*NPIX + n]     = make_float2(cf[0]+bv0, cf[1]+bv0);
            *(float2*)&d_xs[((size_t)(b*CCH + m + 8))*NPIX + n] = make_float2(cf[2]+bv8, cf[3]+bv8);
        }
    }
}

// ---------------- GroupNorm partial sums ----------------------------------------
__global__ void gn_part_kernel(int which) {
    const float* src = which ? d_z : d_xs;
    float* part      = which ? d_part2 : d_part1;
    int blk = blockIdx.x;
    int bg = blk >> 4, ch = blk & 15;
    const float4* p = (const float4*)(src + (size_t)bg*GSIZE + ch*(GSIZE/16));
    float s = 0.f, s2 = 0.f;
    #pragma unroll
    for (int i = 0; i < 8; i++) {
        float4 v = p[threadIdx.x + i*256];
        s  += v.x + v.y + v.z + v.w;
        s2 += v.x*v.x + v.y*v.y + v.z*v.z + v.w*v.w;
    }
    #pragma unroll
    for (int off = 16; off > 0; off >>= 1) {
        s  += __shfl_xor_sync(0xffffffffu, s,  off);
        s2 += __shfl_xor_sync(0xffffffffu, s2, off);
    }
    __shared__ float sh[16];
    int wid = threadIdx.x >> 5, lid = threadIdx.x & 31;
    if (lid == 0) { sh[wid] = s; sh[wid + 8] = s2; }
    __syncthreads();
    if (threadIdx.x == 0) {
        float S = 0.f, S2 = 0.f;
        #pragma unroll
        for (int w = 0; w < 8; w++) { S += sh[w]; S2 += sh[w + 8]; }
        part[blk*2]     = S;
        part[blk*2 + 1] = S2;
    }
}

// ---------------- GN1 apply + ReLU; writes fp32 xs AND bf16 k-pair xsb ----------
// grid (4, 128, 4): x = n-quarter, y = channel pair, z = batch
__global__ void gn1_apply_kernel(const float* __restrict__ gw,
                                 const float* __restrict__ gb) {
    __shared__ float st[2];
    int b  = blockIdx.z;
    int kp = blockIdx.y;
    int c  = kp << 1;
    int bg = b*8 + (kp >> 4);
    if (threadIdx.x == 0) {
        float S = 0.f, S2 = 0.f;
        #pragma unroll
        for (int i = 0; i < 16; i++) {
            S  += d_part1[(bg*16 + i)*2];
            S2 += d_part1[(bg*16 + i)*2 + 1];
        }
        float mean = S / (float)GSIZE;
        st[0] = mean;
        st[1] = rsqrtf(S2 / (float)GSIZE - mean*mean + EPSV);
    }
    __syncthreads();
    float sc0 = st[1] * gw[c],   sh0 = gb[c]   - st[0]*sc0;
    float sc1 = st[1] * gw[c+1], sh1 = gb[c+1] - st[0]*sc1;
    int n = blockIdx.x*1024 + threadIdx.x*4;
    size_t base = ((size_t)(b*CCH + c))*NPIX + n;
    float4 v0 = *(float4*)&d_xs[base];
    float4 v1 = *(float4*)&d_xs[base + NPIX];
    v0.x = fmaxf(v0.x*sc0 + sh0, 0.f); v0.y = fmaxf(v0.y*sc0 + sh0, 0.f);
    v0.z = fmaxf(v0.z*sc0 + sh0, 0.f); v0.w = fmaxf(v0.w*sc0 + sh0, 0.f);
    v1.x = fmaxf(v1.x*sc1 + sh1, 0.f); v1.y = fmaxf(v1.y*sc1 + sh1, 0.f);
    v1.z = fmaxf(v1.z*sc1 + sh1, 0.f); v1.w = fmaxf(v1.w*sc1 + sh1, 0.f);
    *(float4*)&d_xs[base]        = v0;
    *(float4*)&d_xs[base + NPIX] = v1;
    uint4 pk;
    pk.x = pack_bf(v1.x, v0.x);
    pk.y = pack_bf(v1.y, v0.y);
    pk.z = pack_bf(v1.z, v0.z);
    pk.w = pack_bf(v1.w, v0.w);
    *(uint4*)&d_xsb[((size_t)(b*128 + kp))*NPIX + n] = pk;
}

// ---------------- bf16 1x1 GEMM, cp.async pipelined, K chunk 32 ------------------
// MODE 0/1/2: X=d_xsb K=256 M=128 -> thb/phb/gb (bf16). MODE 3: X=d_yb K=128 -> z
template<int MODE>
__global__ void __launch_bounds__(256) gemm_bf_kernel(const float* __restrict__ bias) {
    constexpr int K  = (MODE == 3) ? 128 : 256;
    constexpr int KP = K / 2;
    constexpr int NI = K / 32;
    const unsigned* Wp = d_wpk + (MODE == 0 ? 0 : MODE == 1 ? 16384
                                : MODE == 2 ? 32768 : 49152);
    const unsigned* Xall = (MODE == 3) ? d_yb : d_xsb;

    __shared__ unsigned Ws[2][64*20];     // [m][kp] pad 20
    __shared__ unsigned Xs[2][16*132];    // [kp][n] pad 132

    int b  = blockIdx.z;
    int n0 = blockIdx.x * 128;
    int m0 = blockIdx.y * 64;
    const unsigned* Xb = Xall + (size_t)b * KP * NPIX;

    int tid  = threadIdx.x;
    int lane = tid & 31;
    int wid  = tid >> 5;
    int wm = wid >> 2, wn = wid & 3;
    int r  = lane >> 2, cq = lane & 3;

    int wRow = tid >> 2, wSeg = tid & 3;
    int xRow = tid >> 5, xSeg = tid & 31;
    uint32_t wBase = smem_u32(Ws);
    uint32_t xBase = smem_u32(Xs);

    auto stage = [&](int s, int it) {
        int kp0 = it * 16;
        cp16(wBase + (uint32_t)((s*64*20 + wRow*20 + wSeg*4)*4),
             Wp + (size_t)(m0 + wRow)*KP + kp0 + wSeg*4);
        #pragma unroll
        for (int j = 0; j < 2; j++) {
            int k = xRow + j*8;
            cp16(xBase + (uint32_t)((s*16*132 + k*132 + xSeg*4)*4),
                 Xb + (size_t)(kp0 + k)*NPIX + n0 + xSeg*4);
        }
    };

    float C[8][4];
    #pragma unroll
    for (int i = 0; i < 8; i++)
        #pragma unroll
        for (int j = 0; j < 4; j++) C[i][j] = 0.f;

    stage(0, 0);
    cp_commit();

    for (int it = 0; it < NI; it++) {
        if (it < NI-1) { stage((it+1)&1, it+1); cp_commit(); cp_wait<1>(); }
        else cp_wait<0>();
        __syncthreads();

        const unsigned* Wt = Ws[it & 1];
        const unsigned* Xt = Xs[it & 1];

        #pragma unroll
        for (int ch = 0; ch < 2; ch++) {
            int ko = ch*8 + cq;
            unsigned a[2][4];
            #pragma unroll
            for (int mt = 0; mt < 2; mt++) {
                int mr = wm*32 + mt*16 + r;
                a[mt][0] = Wt[mr*20 + ko];
                a[mt][1] = Wt[(mr+8)*20 + ko];
                a[mt][2] = Wt[mr*20 + ko + 4];
                a[mt][3] = Wt[(mr+8)*20 + ko + 4];
            }
            #pragma unroll
            for (int nt = 0; nt < 4; nt++) {
                int nn = wn*32 + nt*8 + r;
                unsigned b0 = Xt[ko*132 + nn];
                unsigned b1 = Xt[(ko+4)*132 + nn];
                mma_bf16(C[nt],     a[0][0], a[0][1], a[0][2], a[0][3], b0, b1);
                mma_bf16(C[4 + nt], a[1][0], a[1][1], a[1][2], a[1][3], b0, b1);
            }
        }
        __syncthreads();
    }

    #pragma unroll
    for (int mt = 0; mt < 2; mt++) {
        int m = m0 + wm*32 + mt*16 + r;
        float bv0 = bias[m], bv8 = bias[m + 8];
        #pragma unroll
        for (int nt = 0; nt < 4; nt++) {
            int n = n0 + wn*32 + nt*8 + 2*cq;
            float* cf = C[mt*4 + nt];
            if (MODE == 3) {
                float* Ob = d_z + (size_t)b * CCH * NPIX;
                *(float2*)&Ob[(size_t)m*NPIX + n]     = make_float2(cf[0]+bv0, cf[1]+bv0);
                *(float2*)&Ob[(size_t)(m+8)*NPIX + n] = make_float2(cf[2]+bv8, cf[3]+bv8);
            } else {
                __nv_bfloat16* Ob = (MODE == 0 ? d_thb : MODE == 1 ? d_phb : d_gb)
                                    + (size_t)b * CI * NPIX;
                *(unsigned*)&Ob[(size_t)m*NPIX + n]     = pack_bf(cf[1]+bv0, cf[0]+bv0);
                *(unsigned*)&Ob[(size_t)(m+8)*NPIX + n] = pack_bf(cf[3]+bv8, cf[2]+bv8);
            }
        }
    }
}

// ---------------- bf16 flash attention (epilogue -> packed yb) -------------------
#define KS_STR 68
#define KS_STAGE (64*KS_STR)
#define GS_STR 36
#define GS_STAGE (128*GS_STR)
#define ATTN_SMEM ((2*KS_STAGE + 2*GS_STAGE)*4)

__global__ void __launch_bounds__(256) attention_tc_kernel() {
    extern __shared__ float smem[];
    float* sK = smem;
    float* sG = smem + 2*KS_STAGE;

    int b  = blockIdx.y;
    int n0 = blockIdx.x * 128;
    const __nv_bfloat16* Tt = d_ttb + (size_t)b * NPIX * CI;
    const __nv_bfloat16* Pt = d_ptb + (size_t)b * NPIX * CI;
    const __nv_bfloat16* Gp = d_gb  + (size_t)b * CI * NPIX;
    unsigned* Ybu = d_yb + (size_t)b * 64 * NPIX;

    int tid  = threadIdx.x;
    int lane = tid & 31;
    int wid  = tid >> 5;
    int qb   = wid * 16;
    int r    = lane >> 2;
    int cq   = lane & 3;

    uint32_t kBase = smem_u32(sK);
    uint32_t gBase = smem_u32(sG);

    auto stageK = [&](int s, int m0k) {
        #pragma unroll
        for (int j = 0; j < 4; j++) {
            int idx = tid + j*256;
            int row = idx >> 4, seg = idx & 15;
            cp16(kBase + (uint32_t)((s*KS_STAGE + row*KS_STR + seg*4)*4),
                 Pt + (size_t)(m0k + row)*CI + seg*8);
        }
    };
    auto stageG = [&](int s, int m0k) {
        #pragma unroll
        for (int j = 0; j < 4; j++) {
            int idx = tid + j*256;
            int row = idx >> 3, seg = idx & 7;
            cp16(gBase + (uint32_t)((s*GS_STAGE + row*GS_STR + seg*4)*4),
                 Gp + (size_t)row*NPIX + m0k + seg*8);
        }
    };

    // ---- Q prologue ----
    #pragma unroll
    for (int j = 0; j < 8; j++) {
        int idx = tid + j*256;
        int row = idx >> 4, seg = idx & 15;
        cp16(kBase + (uint32_t)((row*KS_STR + seg*4)*4),
             Tt + (size_t)(n0 + row)*CI + seg*8);
    }
    cp_commit();
    cp_wait<0>();
    __syncthreads();

    unsigned qa[8][4];
    #pragma unroll
    for (int ch = 0; ch < 8; ch++) {
        int ko = ch*8 + cq;
        qa[ch][0] = ldu(&sK[(qb + r)*KS_STR + ko]);
        qa[ch][1] = ldu(&sK[(qb + r + 8)*KS_STR + ko]);
        qa[ch][2] = ldu(&sK[(qb + r)*KS_STR + ko + 4]);
        qa[ch][3] = ldu(&sK[(qb + r + 8)*KS_STR + ko + 4]);
    }
    __syncthreads();

    stageK(0, 0); cp_commit();
    stageG(0, 0); cp_commit();

    float O[16][4];
    #pragma unroll
    for (int i = 0; i < 16; i++)
        #pragma unroll
        for (int j = 0; j < 4; j++) O[i][j] = 0.f;
    float Mx0 = -1e30f, Mx1 = -1e30f, L0 = 0.f, L1 = 0.f;
    const unsigned FULL = 0xffffffffu;

    for (int t = 0; t < 64; t++) {
        int s = t & 1;
        int m0 = t * 64;

        if (t < 63) { stageK(s^1, m0 + 64); cp_commit(); cp_wait<2>(); }
        else        cp_wait<1>();
        __syncthreads();

        const float* Kt = sK + s*KS_STAGE;
        float S[8][4];
        #pragma unroll
        for (int i = 0; i < 8; i++)
            #pragma unroll
            for (int j = 0; j < 4; j++) S[i][j] = 0.f;

        #pragma unroll
        for (int ch = 0; ch < 8; ch++) {
            int ko = ch*8 + cq;
            #pragma unroll
            for (int nt = 0; nt < 8; nt++) {
                unsigned b0 = ldu(&Kt[(nt*8 + r)*KS_STR + ko]);
                unsigned b1 = ldu(&Kt[(nt*8 + r)*KS_STR + ko + 4]);
                mma_bf16(S[nt], qa[ch][0], qa[ch][1], qa[ch][2], qa[ch][3], b0, b1);
            }
        }

        float rm0 = -1e30f, rm1 = -1e30f;
        #pragma unroll
        for (int nt = 0; nt < 8; nt++) {
            rm0 = fmaxf(rm0, fmaxf(S[nt][0], S[nt][1]));
            rm1 = fmaxf(rm1, fmaxf(S[nt][2], S[nt][3]));
        }
        rm0 = fmaxf(rm0, __shfl_xor_sync(FULL, rm0, 1));
        rm0 = fmaxf(rm0, __shfl_xor_sync(FULL, rm0, 2));
        rm1 = fmaxf(rm1, __shfl_xor_sync(FULL, rm1, 1));
        rm1 = fmaxf(rm1, __shfl_xor_sync(FULL, rm1, 2));

        float nm0 = fmaxf(Mx0, rm0), nm1 = fmaxf(Mx1, rm1);
        float sc0 = __expf(Mx0 - nm0), sc1 = __expf(Mx1 - nm1);
        Mx0 = nm0; Mx1 = nm1;

        float rs0 = 0.f, rs1 = 0.f;
        #pragma unroll
        for (int nt = 0; nt < 8; nt++) {
            S[nt][0] = __expf(S[nt][0] - nm0);
            S[nt][1] = __expf(S[nt][1] - nm0);
            S[nt][2] = __expf(S[nt][2] - nm1);
            S[nt][3] = __expf(S[nt][3] - nm1);
            rs0 += S[nt][0] + S[nt][1];
            rs1 += S[nt][2] + S[nt][3];
        }
        rs0 += __shfl_xor_sync(FULL, rs0, 1);
        rs0 += __shfl_xor_sync(FULL, rs0, 2);
        rs1 += __shfl_xor_sync(FULL, rs1, 1);
        rs1 += __shfl_xor_sync(FULL, rs1, 2);
        L0 = L0*sc0 + rs0;
        L1 = L1*sc1 + rs1;

        if (!__all_sync(FULL, (sc0 == 1.f) & (sc1 == 1.f))) {
            #pragma unroll
            for (int i = 0; i < 16; i++) {
                O[i][0] *= sc0; O[i][1] *= sc0;
                O[i][2] *= sc1; O[i][3] *= sc1;
            }
        }

        unsigned pa[4][4];
        #pragma unroll
        for (int kc = 0; kc < 4; kc++) {
            pa[kc][0] = pack_bf(S[2*kc][1],   S[2*kc][0]);
            pa[kc][1] = pack_bf(S[2*kc][3],   S[2*kc][2]);
            pa[kc][2] = pack_bf(S[2*kc+1][1], S[2*kc+1][0]);
            pa[kc][3] = pack_bf(S[2*kc+1][3], S[2*kc+1][2]);
        }

        if (t < 63) { stageG(s^1, m0 + 64); cp_commit(); cp_wait<2>(); }
        else        cp_wait<0>();
        __syncthreads();

        const float* Gt = sG + s*GS_STAGE;
        #pragma unroll
        for (int kc = 0; kc < 4; kc++) {
            int ko = kc*8 + cq;
            #pragma unroll
            for (int ct = 0; ct < 16; ct++) {
                unsigned b0 = ldu(&Gt[(ct*8 + r)*GS_STR + ko]);
                unsigned b1 = ldu(&Gt[(ct*8 + r)*GS_STR + ko + 4]);
                mma_bf16(O[ct], pa[kc][0], pa[kc][1], pa[kc][2], pa[kc][3], b0, b1);
            }
        }
    }

    // ---- epilogue: y as bf16 k-pair packed [kp][n] ----
    float inv0 = 1.0f / L0, inv1 = 1.0f / L1;
    int q = n0 + qb + r;
    #pragma unroll
    for (int ct = 0; ct < 16; ct++) {
        int kp = ct*4 + cq;
        Ybu[(size_t)kp*NPIX + q]     = pack_bf(O[ct][1]*inv0, O[ct][0]*inv0);
        Ybu[(size_t)kp*NPIX + q + 8] = pack_bf(O[ct][3]*inv1, O[ct][2]*inv1);
    }
}

// ---------------- final: out = GN2(z)*0.1 + xs ----------------------------------
__global__ void final_apply_kernel(const float* __restrict__ gw,
                                   const float* __restrict__ gb,
                                   float* __restrict__ out) {
    __shared__ float st[2];
    int bg = blockIdx.x >> 7;
    if (threadIdx.x == 0) {
        float S = 0.f, S2 = 0.f;
        #pragma unroll
        for (int i = 0; i < 16; i++) {
            S  += d_part2[(bg*16 + i)*2];
            S2 += d_part2[(bg*16 + i)*2 + 1];
        }
        float mean = S / (float)GSIZE;
        st[0] = mean;
        st[1] = rsqrtf(S2 / (float)GSIZE - mean*mean + EPSV);
    }
    __syncthreads();
    int i4 = blockIdx.x * blockDim.x + threadIdx.x;
    int idx = i4 << 2;
    int c   = (idx >> 12) & 255;
    float sc = st[1] * gw[c];
    float sh = gb[c] - st[0] * sc;
    float4 z = ((const float4*)d_z)[i4];
    float4 xs = ((const float4*)d_xs)[i4];
    float4 o;
    o.x = (z.x*sc + sh)*0.1f + xs.x;
    o.y = (z.y*sc + sh)*0.1f + xs.y;
    o.z = (z.z*sc + sh)*0.1f + xs.z;
    o.w = (z.w*sc + sh)*0.1f + xs.w;
    ((float4*)out)[i4] = o;
}

// ---------------- launch ---------------------------------------------------------
extern "C" void kernel_launch(void* const* d_in, const int* in_sizes, int n_in,
                              void* d_out, int out_size) {
    const float* x    = (const float*)d_in[0];
    const float* sw   = (const float*)d_in[1];
    const float* sb   = (const float*)d_in[2];
    const float* gn1w = (const float*)d_in[3];
    const float* gn1b = (const float*)d_in[4];
    const float* g_w  = (const float*)d_in[5];
    const float* g_b  = (const float*)d_in[6];
    const float* th_w = (const float*)d_in[7];
    const float* th_b = (const float*)d_in[8];
    const float* ph_w = (const float*)d_in[9];
    const float* ph_b = (const float*)d_in[10];
    const float* w_w  = (const float*)d_in[11];
    const float* w_b  = (const float*)d_in[12];
    const float* gn2w = (const float*)d_in[13];
    const float* gn2b = (const float*)d_in[14];
    float* out = (float*)d_out;

    static int attrSet = 0;
    if (!attrSet) {
        cudaFuncSetAttribute(conv_tc_kernel,
                             cudaFuncAttributeMaxDynamicSharedMemorySize, CONV_SMEM);
        cudaFuncSetAttribute(attention_tc_kernel,
                             cudaFuncAttributeMaxDynamicSharedMemorySize, ATTN_SMEM);
        attrSet = 1;
    }

    pack_w_bf_kernel<<<dim3(9, 256), 256>>>(sw);
    prep_x_kernel<<<dim3(128, 8, 4), dim3(32, 8)>>>(x);
    pack_qkvw_kernel<<<256, 256>>>(th_w, ph_w, g_w, w_w);
    conv_tc_kernel<<<dim3(32, 2, 4), 256, CONV_SMEM>>>(sb);
    gn_part_kernel<<<512, 256>>>(0);
    gn1_apply_kernel<<<dim3(4, 128, 4), 256>>>(gn1w, gn1b);

    gemm_bf_kernel<0><<<dim3(32, 2, 4), 256>>>(th_b);
    gemm_bf_kernel<1><<<dim3(32, 2, 4), 256>>>(ph_b);
    gemm_bf_kernel<2><<<dim3(32, 2, 4), 256>>>(g_b);
    prep_attn_kernel<<<dim3(128, 4, 8), dim3(32, 8)>>>();

    attention_tc_kernel<<<dim3(32, 4), 256, ATTN_SMEM>>>();

    gemm_bf_kernel<3><<<dim3(32, 4, 4), 256>>>(w_b);
    gn_part_kernel<<<512, 256>>>(1);
    final_apply_kernel<<<4096, 256>>>(gn2w, gn2b, out);

    (void)in_sizes; (void)n_in; (void)out_size;
}

// round 8
// speedup vs baseline: 5.2059x; 1.0058x over previous
#include <cuda_runtime.h>
#include <cuda_bf16.h>
#include <math.h>
#include <stdint.h>

#define BATCH 4
#define CCH   256
#define CI    128
#define NPIX  4096
#define GROUPS 8
#define CPG   32
#define GSIZE (CPG*NPIX)
#define EPSV  1e-5f
#define KCONV 2304            // 9 taps * 256 cin, tap-major

// ---------------- scratch ----------------------------------------------------
__device__ float d_xs   [BATCH*CCH*NPIX];        // conv out / normalized (fp32)
__device__ float d_z    [BATCH*CCH*NPIX];
__device__ unsigned d_xsb[BATCH*128*NPIX];       // xs bf16 k-pair packed [b][kp][n]
__device__ unsigned d_yb [BATCH*64*NPIX];        // y  bf16 k-pair packed [b][kp][n]
__device__ unsigned d_wpk[65536];                // packed qkv+w weights [m][kp]
__device__ __nv_bfloat16 d_wb [CCH*KCONV];       // conv weight big   [m][k]
__device__ __nv_bfloat16 d_ws [CCH*KCONV];       // conv weight small [m][k]
__device__ __nv_bfloat16 d_xtb[BATCH*NPIX*CCH];  // x big  [b][pix][c]
__device__ __nv_bfloat16 d_xts[BATCH*NPIX*CCH];  // x small
__device__ __nv_bfloat16 d_thb[BATCH*CI*NPIX];   // theta bf16 [b][c][n]
__device__ __nv_bfloat16 d_phb[BATCH*CI*NPIX];   // phi   bf16 [b][c][n]
__device__ __nv_bfloat16 d_ttb[BATCH*NPIX*CI];   // thetaT [b][n][c]
__device__ __nv_bfloat16 d_ptb[BATCH*NPIX*CI];   // phiT   [b][n][c]
__device__ __nv_bfloat16 d_gb [BATCH*CI*NPIX];   // g bf16 [b][c][n]
__device__ float d_part1[32*16*2];
__device__ float d_part2[32*16*2];

// ---------------- helpers -----------------------------------------------------
__device__ __forceinline__ void mma_bf16(float* c,
    unsigned a0, unsigned a1, unsigned a2, unsigned a3,
    unsigned b0, unsigned b1) {
    asm volatile(
        "mma.sync.aligned.m16n8k16.row.col.f32.bf16.bf16.f32 "
        "{%0,%1,%2,%3}, {%4,%5,%6,%7}, {%8,%9}, {%0,%1,%2,%3};"
        : "+f"(c[0]), "+f"(c[1]), "+f"(c[2]), "+f"(c[3])
        : "r"(a0), "r"(a1), "r"(a2), "r"(a3), "r"(b0), "r"(b1));
}
__device__ __forceinline__ unsigned pack_bf(float hi, float lo) {
    unsigned u;
    asm("cvt.rn.bf16x2.f32 %0, %1, %2;" : "=r"(u) : "f"(hi), "f"(lo));
    return u;
}
__device__ __forceinline__ void cp16(uint32_t dst, const void* src) {
    asm volatile("cp.async.cg.shared.global [%0], [%1], 16;" :: "r"(dst), "l"(src));
}
__device__ __forceinline__ void cp16z(uint32_t dst, const void* src, int srcsz) {
    asm volatile("cp.async.cg.shared.global [%0], [%1], 16, %2;"
                 :: "r"(dst), "l"(src), "r"(srcsz));
}
__device__ __forceinline__ void cp_commit() {
    asm volatile("cp.async.commit_group;");
}
template<int N>
__device__ __forceinline__ void cp_wait() {
    asm volatile("cp.async.wait_group %0;" :: "n"(N));
}
__device__ __forceinline__ uint32_t smem_u32(const void* p) {
    return (uint32_t)__cvta_generic_to_shared(p);
}
__device__ __forceinline__ unsigned ldu(const float* p) {
    return __float_as_uint(*p);
}

// ---------------- precompute: conv weight 2-term bf16 split --------------------
__global__ void pack_w_bf_kernel(const float* __restrict__ w) {
    int k = blockIdx.x * 256 + threadIdx.x;   // grid (9, 256)
    int m = blockIdx.y;
    int c = k & 255, tap = k >> 8;
    float f = w[m*(CCH*9) + c*9 + tap];
    __nv_bfloat16 big = __float2bfloat16(f);
    d_wb[(size_t)m*KCONV + k] = big;
    d_ws[(size_t)m*KCONV + k] = __float2bfloat16(f - __bfloat162float(big));
}

// ---------------- precompute: x transpose + split -> [b][pix][c] bf16 ---------
__global__ void prep_x_kernel(const float* __restrict__ x) {
    __shared__ float t[32][33];
    int b  = blockIdx.z;
    int p0 = blockIdx.x * 32;
    int c0 = blockIdx.y * 32;
    int tx = threadIdx.x, ty = threadIdx.y;
    #pragma unroll
    for (int i = 0; i < 4; i++)
        t[ty + i*8][tx] = x[(size_t)(b*CCH + c0 + ty + i*8)*NPIX + p0 + tx];
    __syncthreads();
    #pragma unroll
    for (int i = 0; i < 4; i++) {
        int p = ty + i*8;
        float f = t[tx][p];
        __nv_bfloat16 big = __float2bfloat16(f);
        size_t o = (size_t)(b*NPIX + p0 + p)*CCH + c0 + tx;
        d_xtb[o] = big;
        d_xts[o] = __float2bfloat16(f - __bfloat162float(big));
    }
}

// ---------------- precompute: pack qkv+w weights to bf16x2 k-pairs -------------
// layout: theta @0, phi @16384, g @32768 (each [128][128] u32), w @49152 ([256][64])
__global__ void pack_qkvw_kernel(const float* __restrict__ thw,
                                 const float* __restrict__ phw,
                                 const float* __restrict__ gw_,
                                 const float* __restrict__ ww) {
    int idx = blockIdx.x * 256 + threadIdx.x;   // grid 256 -> 65536
    const float* src;
    int off, loc, K;
    if (idx < 16384)      { src = thw; off = 0;     loc = idx;         K = 256; }
    else if (idx < 32768) { src = phw; off = 16384; loc = idx - 16384; K = 256; }
    else if (idx < 49152) { src = gw_; off = 32768; loc = idx - 32768; K = 256; }
    else                  { src = ww;  off = 49152; loc = idx - 49152; K = 128; }
    int kp = loc & (K/2 - 1);
    int m  = loc / (K/2);
    d_wpk[off + loc] = pack_bf(src[m*K + kp*2 + 1], src[m*K + kp*2]);
}

// ---------------- prep attention: transpose theta/phi bf16 -> [n][c] -----------
__global__ void prep_attn_kernel() {
    __shared__ __nv_bfloat16 t[32][34];
    int which = blockIdx.z & 1, b = blockIdx.z >> 1;
    const __nv_bfloat16* src = (which ? d_phb : d_thb) + (size_t)b*CI*NPIX;
    __nv_bfloat16* dst = (which ? d_ptb : d_ttb) + (size_t)b*NPIX*CI;
    int n0 = blockIdx.x * 32, c0 = blockIdx.y * 32;
    int tx = threadIdx.x, ty = threadIdx.y;
    #pragma unroll
    for (int i = 0; i < 4; i++)
        t[ty + i*8][tx] = src[(size_t)(c0 + ty + i*8)*NPIX + n0 + tx];
    __syncthreads();
    #pragma unroll
    for (int i = 0; i < 4; i++) {
        int n = ty + i*8;
        dst[(size_t)(n0 + n)*CI + c0 + tx] = t[tx][n];
    }
}

// ---------------- conv3x3 implicit GEMM, bf16 2-term, 2 blocks/SM ---------------
#define CV_ROW 20
#define CV_PLANE (128*CV_ROW)
#define CV_STAGE (4*CV_PLANE)
#define CONV_SMEM (2*CV_STAGE*4)     // 81920 bytes; 2 blocks = 160KB/SM

__global__ void __launch_bounds__(256, 2) conv_tc_kernel(const float* __restrict__ sb) {
    extern __shared__ float smem[];

    int b    = blockIdx.z;
    int m0   = blockIdx.y * 128;
    int pix0 = blockIdx.x * 128;
    int h0   = pix0 >> 6;

    int tid  = threadIdx.x;
    int lane = tid & 31;
    int wid  = tid >> 5;
    int wm = wid >> 2, wn = wid & 3;
    int r  = lane >> 2, cq = lane & 3;

    uint32_t base = smem_u32(smem);

    float C[16][4];
    #pragma unroll
    for (int i = 0; i < 16; i++)
        #pragma unroll
        for (int j = 0; j < 4; j++) C[i][j] = 0.f;

    auto stage = [&](int st, int kc) {
        int tap = kc >> 8;
        int c0  = kc & 255;
        int ky  = tap/3 - 1;
        int kx  = tap - (tap/3)*3 - 1;
        uint32_t sb0 = base + (uint32_t)(st*CV_STAGE*4);
        #pragma unroll
        for (int j = 0; j < 4; j++) {
            int idx = tid + j*256;
            int p   = idx >> 9;
            int rem = idx & 511;
            int row = rem >> 2;
            int seg = rem & 3;
            const __nv_bfloat16* wsrc = (p ? d_ws : d_wb)
                + (size_t)(m0 + row)*KCONV + kc + seg*8;
            cp16(sb0 + (uint32_t)((p*CV_PLANE + row*CV_ROW + seg*4)*4), wsrc);
            int h = h0 + (row >> 6) + ky;
            int w = (row & 63) + kx;
            int valid = ((unsigned)h < 64u) & ((unsigned)w < 64u);
            int pix = valid ? (h*64 + w) : 0;
            const __nv_bfloat16* xsrc = (p ? d_xts : d_xtb)
                + (size_t)(b*NPIX + pix)*CCH + c0 + seg*8;
            cp16z(sb0 + (uint32_t)(((2+p)*CV_PLANE + row*CV_ROW + seg*4)*4),
                  xsrc, valid ? 16 : 0);
        }
    };

    stage(0, 0);
    cp_commit();

    for (int it = 0; it < 72; it++) {
        if (it < 71) { stage((it+1) & 1, (it+1)*32); cp_commit(); cp_wait<1>(); }
        else cp_wait<0>();
        __syncthreads();

        const float* St = smem + (it & 1)*CV_STAGE;
        const float* Ab = St;
        const float* Am = St + CV_PLANE;
        const float* Bb = St + 2*CV_PLANE;
        const float* Bm = St + 3*CV_PLANE;

        #pragma unroll
        for (int ch = 0; ch < 2; ch++) {
            int ko = ch*8 + cq;
            unsigned ab[4][4], as_[4][4];
            #pragma unroll
            for (int mt = 0; mt < 4; mt++) {
                int m = wm*64 + mt*16 + r;
                ab[mt][0] = ldu(&Ab[m*CV_ROW + ko]);
                ab[mt][1] = ldu(&Ab[(m+8)*CV_ROW + ko]);
                ab[mt][2] = ldu(&Ab[m*CV_ROW + ko + 4]);
                ab[mt][3] = ldu(&Ab[(m+8)*CV_ROW + ko + 4]);
                as_[mt][0] = ldu(&Am[m*CV_ROW + ko]);
                as_[mt][1] = ldu(&Am[(m+8)*CV_ROW + ko]);
                as_[mt][2] = ldu(&Am[m*CV_ROW + ko + 4]);
                as_[mt][3] = ldu(&Am[(m+8)*CV_ROW + ko + 4]);
            }
            unsigned bb[4][2], bs[4][2];
            #pragma unroll
            for (int nt = 0; nt < 4; nt++) {
                int n = wn*32 + nt*8 + r;
                bb[nt][0] = ldu(&Bb[n*CV_ROW + ko]);
                bb[nt][1] = ldu(&Bb[n*CV_ROW + ko + 4]);
                bs[nt][0] = ldu(&Bm[n*CV_ROW + ko]);
                bs[nt][1] = ldu(&Bm[n*CV_ROW + ko + 4]);
            }
            #pragma unroll
            for (int mt = 0; mt < 4; mt++)
                #pragma unroll
                for (int nt = 0; nt < 4; nt++)
                    mma_bf16(C[mt*4+nt], ab[mt][0], ab[mt][1], ab[mt][2], ab[mt][3],
                             bb[nt][0], bb[nt][1]);
            #pragma unroll
            for (int mt = 0; mt < 4; mt++)
                #pragma unroll
                for (int nt = 0; nt < 4; nt++)
                    mma_bf16(C[mt*4+nt], ab[mt][0], ab[mt][1], ab[mt][2], ab[mt][3],
                             bs[nt][0], bs[nt][1]);
            #pragma unroll
            for (int mt = 0; mt < 4; mt++)
                #pragma unroll
                for (int nt = 0; nt < 4; nt++)
                    mma_bf16(C[mt*4+nt], as_[mt][0], as_[mt][1], as_[mt][2], as_[mt][3],
                             bb[nt][0], bb[nt][1]);
        }
        __syncthreads();
    }

    #pragma unroll
    for (int mt = 0; mt < 4; mt++) {
        int m = m0 + wm*64 + mt*16 + r;
        float bv0 = sb[m], bv8 = sb[m + 8];
        #pragma unroll
        for (int nt = 0; nt < 4; nt++) {
            int n = pix0 + wn*32 + nt*8 + 2*cq;
            float* cf = C[mt*4 + nt];
            *(float2*)&d_xs[((size_t)(b*CCH + m))*NPIX + n]     = make_float2(cf[0]+bv0, cf[1]+bv0);
            *(float2*)&d_xs[((size_t)(b*CCH + m + 8))*NPIX + n] = make_float2(cf[2]+bv8, cf[3]+bv8);
        }
    }
}

// ---------------- GroupNorm partial sums ----------------------------------------
__global__ void gn_part_kernel(int which) {
    const float* src = which ? d_z : d_xs;
    float* part      = which ? d_part2 : d_part1;
    int blk = blockIdx.x;
    int bg = blk >> 4, ch = blk & 15;
    const float4* p = (const float4*)(src + (size_t)bg*GSIZE + ch*(GSIZE/16));
    float s = 0.f, s2 = 0.f;
    #pragma unroll
    for (int i = 0; i < 8; i++) {
        float4 v = p[threadIdx.x + i*256];
        s  += v.x + v.y + v.z + v.w;
        s2 += v.x*v.x + v.y*v.y + v.z*v.z + v.w*v.w;
    }
    #pragma unroll
    for (int off = 16; off > 0; off >>= 1) {
        s  += __shfl_xor_sync(0xffffffffu, s,  off);
        s2 += __shfl_xor_sync(0xffffffffu, s2, off);
    }
    __shared__ float sh[16];
    int wid = threadIdx.x >> 5, lid = threadIdx.x & 31;
    if (lid == 0) { sh[wid] = s; sh[wid + 8] = s2; }
    __syncthreads();
    if (threadIdx.x == 0) {
        float S = 0.f, S2 = 0.f;
        #pragma unroll
        for (int w = 0; w < 8; w++) { S += sh[w]; S2 += sh[w + 8]; }
        part[blk*2]     = S;
        part[blk*2 + 1] = S2;
    }
}

// ---------------- GN1 apply + ReLU; writes fp32 xs AND bf16 k-pair xsb ----------
__global__ void gn1_apply_kernel(const float* __restrict__ gw,
                                 const float* __restrict__ gb) {
    __shared__ float st[2];
    int b  = blockIdx.z;
    int kp = blockIdx.y;
    int c  = kp << 1;
    int bg = b*8 + (kp >> 4);
    if (threadIdx.x == 0) {
        float S = 0.f, S2 = 0.f;
        #pragma unroll
        for (int i = 0; i < 16; i++) {
            S  += d_part1[(bg*16 + i)*2];
            S2 += d_part1[(bg*16 + i)*2 + 1];
        }
        float mean = S / (float)GSIZE;
        st[0] = mean;
        st[1] = rsqrtf(S2 / (float)GSIZE - mean*mean + EPSV);
    }
    __syncthreads();
    float sc0 = st[1] * gw[c],   sh0 = gb[c]   - st[0]*sc0;
    float sc1 = st[1] * gw[c+1], sh1 = gb[c+1] - st[0]*sc1;
    int n = blockIdx.x*1024 + threadIdx.x*4;
    size_t base = ((size_t)(b*CCH + c))*NPIX + n;
    float4 v0 = *(float4*)&d_xs[base];
    float4 v1 = *(float4*)&d_xs[base + NPIX];
    v0.x = fmaxf(v0.x*sc0 + sh0, 0.f); v0.y = fmaxf(v0.y*sc0 + sh0, 0.f);
    v0.z = fmaxf(v0.z*sc0 + sh0, 0.f); v0.w = fmaxf(v0.w*sc0 + sh0, 0.f);
    v1.x = fmaxf(v1.x*sc1 + sh1, 0.f); v1.y = fmaxf(v1.y*sc1 + sh1, 0.f);
    v1.z = fmaxf(v1.z*sc1 + sh1, 0.f); v1.w = fmaxf(v1.w*sc1 + sh1, 0.f);
    *(float4*)&d_xs[base]        = v0;
    *(float4*)&d_xs[base + NPIX] = v1;
    uint4 pk;
    pk.x = pack_bf(v1.x, v0.x);
    pk.y = pack_bf(v1.y, v0.y);
    pk.z = pack_bf(v1.z, v0.z);
    pk.w = pack_bf(v1.w, v0.w);
    *(uint4*)&d_xsb[((size_t)(b*128 + kp))*NPIX + n] = pk;
}

// ---------------- bf16 1x1 GEMM -------------------------------------------------
// MODE 0: merged QKV, M=384 rows of d_wpk (theta|phi|g), X=d_xsb K=256, bf16 out
// MODE 3: w, M=256 @49152, X=d_yb K=128, fp32 out to d_z
template<int MODE>
__global__ void __launch_bounds__(256) gemm_bf_kernel(const float* __restrict__ bias0,
                                                      const float* __restrict__ bias1,
                                                      const float* __restrict__ bias2) {
    constexpr int K  = (MODE == 3) ? 128 : 256;
    constexpr int KP = K / 2;
    constexpr int NI = K / 32;
    const unsigned* Wp = d_wpk + (MODE == 3 ? 49152 : 0);
    const unsigned* Xall = (MODE == 3) ? d_yb : d_xsb;

    __shared__ unsigned Ws[2][64*20];
    __shared__ unsigned Xs[2][16*132];

    int b  = blockIdx.z;
    int n0 = blockIdx.x * 128;
    int m0 = blockIdx.y * 64;
    const unsigned* Xb = Xall + (size_t)b * KP * NPIX;

    int tid  = threadIdx.x;
    int lane = tid & 31;
    int wid  = tid >> 5;
    int wm = wid >> 2, wn = wid & 3;
    int r  = lane >> 2, cq = lane & 3;

    int wRow = tid >> 2, wSeg = tid & 3;
    int xRow = tid >> 5, xSeg = tid & 31;
    uint32_t wBase = smem_u32(Ws);
    uint32_t xBase = smem_u32(Xs);

    auto stage = [&](int s, int it) {
        int kp0 = it * 16;
        cp16(wBase + (uint32_t)((s*64*20 + wRow*20 + wSeg*4)*4),
             Wp + (size_t)(m0 + wRow)*KP + kp0 + wSeg*4);
        #pragma unroll
        for (int j = 0; j < 2; j++) {
            int k = xRow + j*8;
            cp16(xBase + (uint32_t)((s*16*132 + k*132 + xSeg*4)*4),
                 Xb + (size_t)(kp0 + k)*NPIX + n0 + xSeg*4);
        }
    };

    float C[8][4];
    #pragma unroll
    for (int i = 0; i < 8; i++)
        #pragma unroll
        for (int j = 0; j < 4; j++) C[i][j] = 0.f;

    stage(0, 0);
    cp_commit();

    for (int it = 0; it < NI; it++) {
        if (it < NI-1) { stage((it+1)&1, it+1); cp_commit(); cp_wait<1>(); }
        else cp_wait<0>();
        __syncthreads();

        const unsigned* Wt = Ws[it & 1];
        const unsigned* Xt = Xs[it & 1];

        #pragma unroll
        for (int ch = 0; ch < 2; ch++) {
            int ko = ch*8 + cq;
            unsigned a[2][4];
            #pragma unroll
            for (int mt = 0; mt < 2; mt++) {
                int mr = wm*32 + mt*16 + r;
                a[mt][0] = Wt[mr*20 + ko];
                a[mt][1] = Wt[(mr+8)*20 + ko];
                a[mt][2] = Wt[mr*20 + ko + 4];
                a[mt][3] = Wt[(mr+8)*20 + ko + 4];
            }
            #pragma unroll
            for (int nt = 0; nt < 4; nt++) {
                int nn = wn*32 + nt*8 + r;
                unsigned b0 = Xt[ko*132 + nn];
                unsigned b1 = Xt[(ko+4)*132 + nn];
                mma_bf16(C[nt],     a[0][0], a[0][1], a[0][2], a[0][3], b0, b1);
                mma_bf16(C[4 + nt], a[1][0], a[1][1], a[1][2], a[1][3], b0, b1);
            }
        }
        __syncthreads();
    }

    // ---- epilogue ----
    const float* bias = (MODE == 3) ? bias0
                      : (m0 < 128 ? bias0 : m0 < 256 ? bias1 : bias2);
    int mbase = (MODE == 3) ? m0 : (m0 & 127);
    __nv_bfloat16* Obf = nullptr;
    if (MODE != 3)
        Obf = (m0 < 128 ? d_thb : m0 < 256 ? d_phb : d_gb) + (size_t)b * CI * NPIX;

    #pragma unroll
    for (int mt = 0; mt < 2; mt++) {
        int ml = mbase + wm*32 + mt*16 + r;
        float bv0 = bias[ml], bv8 = bias[ml + 8];
        #pragma unroll
        for (int nt = 0; nt < 4; nt++) {
            int n = n0 + wn*32 + nt*8 + 2*cq;
            float* cf = C[mt*4 + nt];
            if (MODE == 3) {
                float* Ob = d_z + (size_t)b * CCH * NPIX;
                *(float2*)&Ob[(size_t)ml*NPIX + n]     = make_float2(cf[0]+bv0, cf[1]+bv0);
                *(float2*)&Ob[(size_t)(ml+8)*NPIX + n] = make_float2(cf[2]+bv8, cf[3]+bv8);
            } else {
                *(unsigned*)&Obf[(size_t)ml*NPIX + n]     = pack_bf(cf[1]+bv0, cf[0]+bv0);
                *(unsigned*)&Obf[(size_t)(ml+8)*NPIX + n] = pack_bf(cf[3]+bv8, cf[2]+bv8);
            }
        }
    }
}

// ---------------- bf16 flash attention (unchanged R7) ----------------------------
#define KS_STR 68
#define KS_STAGE (64*KS_STR)
#define GS_STR 36
#define GS_STAGE (128*GS_STR)
#define ATTN_SMEM ((2*KS_STAGE + 2*GS_STAGE)*4)

__global__ void __launch_bounds__(256) attention_tc_kernel() {
    extern __shared__ float smem[];
    float* sK = smem;
    float* sG = smem + 2*KS_STAGE;

    int b  = blockIdx.y;
    int n0 = blockIdx.x * 128;
    const __nv_bfloat16* Tt = d_ttb + (size_t)b * NPIX * CI;
    const __nv_bfloat16* Pt = d_ptb + (size_t)b * NPIX * CI;
    const __nv_bfloat16* Gp = d_gb  + (size_t)b * CI * NPIX;
    unsigned* Ybu = d_yb + (size_t)b * 64 * NPIX;

    int tid  = threadIdx.x;
    int lane = tid & 31;
    int wid  = tid >> 5;
    int qb   = wid * 16;
    int r    = lane >> 2;
    int cq   = lane & 3;

    uint32_t kBase = smem_u32(sK);
    uint32_t gBase = smem_u32(sG);

    auto stageK = [&](int s, int m0k) {
        #pragma unroll
        for (int j = 0; j < 4; j++) {
            int idx = tid + j*256;
            int row = idx >> 4, seg = idx & 15;
            cp16(kBase + (uint32_t)((s*KS_STAGE + row*KS_STR + seg*4)*4),
                 Pt + (size_t)(m0k + row)*CI + seg*8);
        }
    };
    auto stageG = [&](int s, int m0k) {
        #pragma unroll
        for (int j = 0; j < 4; j++) {
            int idx = tid + j*256;
            int row = idx >> 3, seg = idx & 7;
            cp16(gBase + (uint32_t)((s*GS_STAGE + row*GS_STR + seg*4)*4),
                 Gp + (size_t)row*NPIX + m0k + seg*8);
        }
    };

    // ---- Q prologue ----
    #pragma unroll
    for (int j = 0; j < 8; j++) {
        int idx = tid + j*256;
        int row = idx >> 4, seg = idx & 15;
        cp16(kBase + (uint32_t)((row*KS_STR + seg*4)*4),
             Tt + (size_t)(n0 + row)*CI + seg*8);
    }
    cp_commit();
    cp_wait<0>();
    __syncthreads();

    unsigned qa[8][4];
    #pragma unroll
    for (int ch = 0; ch < 8; ch++) {
        int ko = ch*8 + cq;
        qa[ch][0] = ldu(&sK[(qb + r)*KS_STR + ko]);
        qa[ch][1] = ldu(&sK[(qb + r + 8)*KS_STR + ko]);
        qa[ch][2] = ldu(&sK[(qb + r)*KS_STR + ko + 4]);
        qa[ch][3] = ldu(&sK[(qb + r + 8)*KS_STR + ko + 4]);
    }
    __syncthreads();

    stageK(0, 0); cp_commit();
    stageG(0, 0); cp_commit();

    float O[16][4];
    #pragma unroll
    for (int i = 0; i < 16; i++)
        #pragma unroll
        for (int j = 0; j < 4; j++) O[i][j] = 0.f;
    float Mx0 = -1e30f, Mx1 = -1e30f, L0 = 0.f, L1 = 0.f;
    const unsigned FULL = 0xffffffffu;

    for (int t = 0; t < 64; t++) {
        int s = t & 1;
        int m0 = t * 64;

        if (t < 63) { stageK(s^1, m0 + 64); cp_commit(); cp_wait<2>(); }
        else        cp_wait<1>();
        __syncthreads();

        const float* Kt = sK + s*KS_STAGE;
        float S[8][4];
        #pragma unroll
        for (int i = 0; i < 8; i++)
            #pragma unroll
            for (int j = 0; j < 4; j++) S[i][j] = 0.f;

        #pragma unroll
        for (int ch = 0; ch < 8; ch++) {
            int ko = ch*8 + cq;
            #pragma unroll
            for (int nt = 0; nt < 8; nt++) {
                unsigned b0 = ldu(&Kt[(nt*8 + r)*KS_STR + ko]);
                unsigned b1 = ldu(&Kt[(nt*8 + r)*KS_STR + ko + 4]);
                mma_bf16(S[nt], qa[ch][0], qa[ch][1], qa[ch][2], qa[ch][3], b0, b1);
            }
        }

        float rm0 = -1e30f, rm1 = -1e30f;
        #pragma unroll
        for (int nt = 0; nt < 8; nt++) {
            rm0 = fmaxf(rm0, fmaxf(S[nt][0], S[nt][1]));
            rm1 = fmaxf(rm1, fmaxf(S[nt][2], S[nt][3]));
        }
        rm0 = fmaxf(rm0, __shfl_xor_sync(FULL, rm0, 1));
        rm0 = fmaxf(rm0, __shfl_xor_sync(FULL, rm0, 2));
        rm1 = fmaxf(rm1, __shfl_xor_sync(FULL, rm1, 1));
        rm1 = fmaxf(rm1, __shfl_xor_sync(FULL, rm1, 2));

        float nm0 = fmaxf(Mx0, rm0), nm1 = fmaxf(Mx1, rm1);
        float sc0 = __expf(Mx0 - nm0), sc1 = __expf(Mx1 - nm1);
        Mx0 = nm0; Mx1 = nm1;

        float rs0 = 0.f, rs1 = 0.f;
        #pragma unroll
        for (int nt = 0; nt < 8; nt++) {
            S[nt][0] = __expf(S[nt][0] - nm0);
            S[nt][1] = __expf(S[nt][1] - nm0);
            S[nt][2] = __expf(S[nt][2] - nm1);
            S[nt][3] = __expf(S[nt][3] - nm1);
            rs0 += S[nt][0] + S[nt][1];
            rs1 += S[nt][2] + S[nt][3];
        }
        rs0 += __shfl_xor_sync(FULL, rs0, 1);
        rs0 += __shfl_xor_sync(FULL, rs0, 2);
        rs1 += __shfl_xor_sync(FULL, rs1, 1);
        rs1 += __shfl_xor_sync(FULL, rs1, 2);
        L0 = L0*sc0 + rs0;
        L1 = L1*sc1 + rs1;

        if (!__all_sync(FULL, (sc0 == 1.f) & (sc1 == 1.f))) {
            #pragma unroll
            for (int i = 0; i < 16; i++) {
                O[i][0] *= sc0; O[i][1] *= sc0;
                O[i][2] *= sc1; O[i][3] *= sc1;
            }
        }

        unsigned pa[4][4];
        #pragma unroll
        for (int kc = 0; kc < 4; kc++) {
            pa[kc][0] = pack_bf(S[2*kc][1],   S[2*kc][0]);
            pa[kc][1] = pack_bf(S[2*kc][3],   S[2*kc][2]);
            pa[kc][2] = pack_bf(S[2*kc+1][1], S[2*kc+1][0]);
            pa[kc][3] = pack_bf(S[2*kc+1][3], S[2*kc+1][2]);
        }

        if (t < 63) { stageG(s^1, m0 + 64); cp_commit(); cp_wait<2>(); }
        else        cp_wait<0>();
        __syncthreads();

        const float* Gt = sG + s*GS_STAGE;
        #pragma unroll
        for (int kc = 0; kc < 4; kc++) {
            int ko = kc*8 + cq;
            #pragma unroll
            for (int ct = 0; ct < 16; ct++) {
                unsigned b0 = ldu(&Gt[(ct*8 + r)*GS_STR + ko]);
                unsigned b1 = ldu(&Gt[(ct*8 + r)*GS_STR + ko + 4]);
                mma_bf16(O[ct], pa[kc][0], pa[kc][1], pa[kc][2], pa[kc][3], b0, b1);
            }
        }
    }

    float inv0 = 1.0f / L0, inv1 = 1.0f / L1;
    int q = n0 + qb + r;
    #pragma unroll
    for (int ct = 0; ct < 16; ct++) {
        int kp = ct*4 + cq;
        Ybu[(size_t)kp*NPIX + q]     = pack_bf(O[ct][1]*inv0, O[ct][0]*inv0);
        Ybu[(size_t)kp*NPIX + q + 8] = pack_bf(O[ct][3]*inv1, O[ct][2]*inv1);
    }
}

// ---------------- final: out = GN2(z)*0.1 + xs ----------------------------------
__global__ void final_apply_kernel(const float* __restrict__ gw,
                                   const float* __restrict__ gb,
                                   float* __restrict__ out) {
    __shared__ float st[2];
    int bg = blockIdx.x >> 7;
    if (threadIdx.x == 0) {
        float S = 0.f, S2 = 0.f;
        #pragma unroll
        for (int i = 0; i < 16; i++) {
            S  += d_part2[(bg*16 + i)*2];
            S2 += d_part2[(bg*16 + i)*2 + 1];
        }
        float mean = S / (float)GSIZE;
        st[0] = mean;
        st[1] = rsqrtf(S2 / (float)GSIZE - mean*mean + EPSV);
    }
    __syncthreads();
    int i4 = blockIdx.x * blockDim.x + threadIdx.x;
    int idx = i4 << 2;
    int c   = (idx >> 12) & 255;
    float sc = st[1] * gw[c];
    float sh = gb[c] - st[0] * sc;
    float4 z = ((const float4*)d_z)[i4];
    float4 xs = ((const float4*)d_xs)[i4];
    float4 o;
    o.x = (z.x*sc + sh)*0.1f + xs.x;
    o.y = (z.y*sc + sh)*0.1f + xs.y;
    o.z = (z.z*sc + sh)*0.1f + xs.z;
    o.w = (z.w*sc + sh)*0.1f + xs.w;
    ((float4*)out)[i4] = o;
}

// ---------------- launch ---------------------------------------------------------
extern "C" void kernel_launch(void* const* d_in, const int* in_sizes, int n_in,
                              void* d_out, int out_size) {
    const float* x    = (const float*)d_in[0];
    const float* sw   = (const float*)d_in[1];
    const float* sb   = (const float*)d_in[2];
    const float* gn1w = (const float*)d_in[3];
    const float* gn1b = (const float*)d_in[4];
    const float* g_w  = (const float*)d_in[5];
    const float* g_b  = (const float*)d_in[6];
    const float* th_w = (const float*)d_in[7];
    const float* th_b = (const float*)d_in[8];
    const float* ph_w = (const float*)d_in[9];
    const float* ph_b = (const float*)d_in[10];
    const float* w_w  = (const float*)d_in[11];
    const float* w_b  = (const float*)d_in[12];
    const float* gn2w = (const float*)d_in[13];
    const float* gn2b = (const float*)d_in[14];
    float* out = (float*)d_out;

    static int attrSet = 0;
    if (!attrSet) {
        cudaFuncSetAttribute(conv_tc_kernel,
                             cudaFuncAttributeMaxDynamicSharedMemorySize, CONV_SMEM);
        cudaFuncSetAttribute(attention_tc_kernel,
                             cudaFuncAttributeMaxDynamicSharedMemorySize, ATTN_SMEM);
        attrSet = 1;
    }

    pack_w_bf_kernel<<<dim3(9, 256), 256>>>(sw);
    prep_x_kernel<<<dim3(128, 8, 4), dim3(32, 8)>>>(x);
    pack_qkvw_kernel<<<256, 256>>>(th_w, ph_w, g_w, w_w);
    conv_tc_kernel<<<dim3(32, 2, 4), 256, CONV_SMEM>>>(sb);
    gn_part_kernel<<<512, 256>>>(0);
    gn1_apply_kernel<<<dim3(4, 128, 4), 256>>>(gn1w, gn1b);

    gemm_bf_kernel<0><<<dim3(32, 6, 4), 256>>>(th_b, ph_b, g_b);
    prep_attn_kernel<<<dim3(128, 4, 8), dim3(32, 8)>>>();

    attention_tc_kernel<<<dim3(32, 4), 256, ATTN_SMEM>>>();

    gemm_bf_kernel<3><<<dim3(32, 4, 4), 256>>>(w_b, nullptr, nullptr);
    gn_part_kernel<<<512, 256>>>(1);
    final_apply_kernel<<<4096, 256>>>(gn2w, gn2b, out);

    (void)in_sizes; (void)n_in; (void)out_size;
}

// round 9
// speedup vs baseline: 5.5068x; 1.0578x over previous
#include <cuda_runtime.h>
#include <cuda_bf16.h>
#include <math.h>
#include <stdint.h>

#define BATCH 4
#define CCH   256
#define CI    128
#define NPIX  4096
#define GROUPS 8
#define CPG   32
#define GSIZE (CPG*NPIX)
#define EPSV  1e-5f
#define KCONV 2304            // 9 taps * 256 cin, tap-major

// ---------------- scratch ----------------------------------------------------
__device__ float d_xs   [BATCH*CCH*NPIX];        // conv out / normalized (fp32)
__device__ float d_z    [BATCH*CCH*NPIX];
__device__ unsigned d_xsb[BATCH*128*NPIX];       // xs bf16 k-pair packed [b][kp][n]
__device__ unsigned d_yb [BATCH*64*NPIX];        // y  bf16 k-pair packed [b][kp][n]
__device__ unsigned d_wpk[65536];                // packed qkv+w weights [m][kp]
__device__ __nv_bfloat16 d_wb [CCH*KCONV];       // conv weight big   [m][k]
__device__ __nv_bfloat16 d_ws [CCH*KCONV];       // conv weight small [m][k]
__device__ __nv_bfloat16 d_xtb[BATCH*NPIX*CCH];  // x big  [b][pix][c]
__device__ __nv_bfloat16 d_xts[BATCH*NPIX*CCH];  // x small
__device__ __nv_bfloat16 d_thb[BATCH*CI*NPIX];   // theta bf16 [b][c][n]
__device__ __nv_bfloat16 d_phb[BATCH*CI*NPIX];   // phi   bf16 [b][c][n]
__device__ __nv_bfloat16 d_ttb[BATCH*NPIX*CI];   // thetaT [b][n][c]
__device__ __nv_bfloat16 d_ptb[BATCH*NPIX*CI];   // phiT   [b][n][c]
__device__ __nv_bfloat16 d_gb [BATCH*CI*NPIX];   // g bf16 [b][c][n]
__device__ float d_part1[32*16*2];
__device__ float d_part2[32*16*2];

// ---------------- helpers -----------------------------------------------------
__device__ __forceinline__ void mma_bf16(float* c,
    unsigned a0, unsigned a1, unsigned a2, unsigned a3,
    unsigned b0, unsigned b1) {
    asm volatile(
        "mma.sync.aligned.m16n8k16.row.col.f32.bf16.bf16.f32 "
        "{%0,%1,%2,%3}, {%4,%5,%6,%7}, {%8,%9}, {%0,%1,%2,%3};"
        : "+f"(c[0]), "+f"(c[1]), "+f"(c[2]), "+f"(c[3])
        : "r"(a0), "r"(a1), "r"(a2), "r"(a3), "r"(b0), "r"(b1));
}
__device__ __forceinline__ unsigned pack_bf(float hi, float lo) {
    unsigned u;
    asm("cvt.rn.bf16x2.f32 %0, %1, %2;" : "=r"(u) : "f"(hi), "f"(lo));
    return u;
}
__device__ __forceinline__ void cp16(uint32_t dst, const void* src) {
    asm volatile("cp.async.cg.shared.global [%0], [%1], 16;" :: "r"(dst), "l"(src));
}
__device__ __forceinline__ void cp16z(uint32_t dst, const void* src, int srcsz) {
    asm volatile("cp.async.cg.shared.global [%0], [%1], 16, %2;"
                 :: "r"(dst), "l"(src), "r"(srcsz));
}
__device__ __forceinline__ void cp_commit() {
    asm volatile("cp.async.commit_group;");
}
template<int N>
__device__ __forceinline__ void cp_wait() {
    asm volatile("cp.async.wait_group %0;" :: "n"(N));
}
__device__ __forceinline__ uint32_t smem_u32(const void* p) {
    return (uint32_t)__cvta_generic_to_shared(p);
}
__device__ __forceinline__ unsigned ldu(const float* p) {
    return __float_as_uint(*p);
}

// ---------------- precompute: conv weight 2-term bf16 split --------------------
__global__ void pack_w_bf_kernel(const float* __restrict__ w) {
    int k = blockIdx.x * 256 + threadIdx.x;   // grid (9, 256)
    int m = blockIdx.y;
    int c = k & 255, tap = k >> 8;
    float f = w[m*(CCH*9) + c*9 + tap];
    __nv_bfloat16 big = __float2bfloat16(f);
    d_wb[(size_t)m*KCONV + k] = big;
    d_ws[(size_t)m*KCONV + k] = __float2bfloat16(f - __bfloat162float(big));
}

// ---------------- precompute: x transpose + split -> [b][pix][c] bf16 ---------
__global__ void prep_x_kernel(const float* __restrict__ x) {
    __shared__ float t[32][33];
    int b  = blockIdx.z;
    int p0 = blockIdx.x * 32;
    int c0 = blockIdx.y * 32;
    int tx = threadIdx.x, ty = threadIdx.y;
    #pragma unroll
    for (int i = 0; i < 4; i++)
        t[ty + i*8][tx] = x[(size_t)(b*CCH + c0 + ty + i*8)*NPIX + p0 + tx];
    __syncthreads();
    #pragma unroll
    for (int i = 0; i < 4; i++) {
        int p = ty + i*8;
        float f = t[tx][p];
        __nv_bfloat16 big = __float2bfloat16(f);
        size_t o = (size_t)(b*NPIX + p0 + p)*CCH + c0 + tx;
        d_xtb[o] = big;
        d_xts[o] = __float2bfloat16(f - __bfloat162float(big));
    }
}

// ---------------- precompute: pack qkv+w weights to bf16x2 k-pairs -------------
__global__ void pack_qkvw_kernel(const float* __restrict__ thw,
                                 const float* __restrict__ phw,
                                 const float* __restrict__ gw_,
                                 const float* __restrict__ ww) {
    int idx = blockIdx.x * 256 + threadIdx.x;   // grid 256 -> 65536
    const float* src;
    int off, loc, K;
    if (idx < 16384)      { src = thw; off = 0;     loc = idx;         K = 256; }
    else if (idx < 32768) { src = phw; off = 16384; loc = idx - 16384; K = 256; }
    else if (idx < 49152) { src = gw_; off = 32768; loc = idx - 32768; K = 256; }
    else                  { src = ww;  off = 49152; loc = idx - 49152; K = 128; }
    int kp = loc & (K/2 - 1);
    int m  = loc / (K/2);
    d_wpk[off + loc] = pack_bf(src[m*K + kp*2 + 1], src[m*K + kp*2]);
}

// ---------------- prep attention: transpose theta/phi bf16 -> [n][c] -----------
__global__ void prep_attn_kernel() {
    __shared__ __nv_bfloat16 t[32][34];
    int which = blockIdx.z & 1, b = blockIdx.z >> 1;
    const __nv_bfloat16* src = (which ? d_phb : d_thb) + (size_t)b*CI*NPIX;
    __nv_bfloat16* dst = (which ? d_ptb : d_ttb) + (size_t)b*NPIX*CI;
    int n0 = blockIdx.x * 32, c0 = blockIdx.y * 32;
    int tx = threadIdx.x, ty = threadIdx.y;
    #pragma unroll
    for (int i = 0; i < 4; i++)
        t[ty + i*8][tx] = src[(size_t)(c0 + ty + i*8)*NPIX + n0 + tx];
    __syncthreads();
    #pragma unroll
    for (int i = 0; i < 4; i++) {
        int n = ty + i*8;
        dst[(size_t)(n0 + n)*CI + c0 + tx] = t[tx][n];
    }
}

// ---------------- conv3x3 implicit GEMM, bf16 2-term, 256m x 128n block --------
// 8 warps as 4m x 2n; warp tile 64m x 64n. Grid (32 pix-tiles, 4 b) = 128 blocks.
#define CV_ROW 20
#define CA_PLANE (256*CV_ROW)          // 5120 floats
#define CB_PLANE (128*CV_ROW)          // 2560 floats
#define CV_STAGE (2*CA_PLANE + 2*CB_PLANE)   // 15360 floats
#define CONV_SMEM (2*CV_STAGE*4)       // 122880 bytes

__global__ void __launch_bounds__(256, 1) conv_tc_kernel(const float* __restrict__ sb) {
    extern __shared__ float smem[];

    int b    = blockIdx.y;
    int pix0 = blockIdx.x * 128;
    int h0   = pix0 >> 6;

    int tid  = threadIdx.x;
    int lane = tid & 31;
    int wid  = tid >> 5;
    int wm = wid >> 1, wn = wid & 1;     // 4m x 2n warps
    int r  = lane >> 2, cq = lane & 3;

    uint32_t base = smem_u32(smem);

    float C[32][4];                       // [mt*8+nt][4]
    #pragma unroll
    for (int i = 0; i < 32; i++)
        #pragma unroll
        for (int j = 0; j < 4; j++) C[i][j] = 0.f;

    auto stage = [&](int st, int kc) {
        int tap = kc >> 8;
        int c0  = kc & 255;
        int ky  = tap/3 - 1;
        int kx  = tap - (tap/3)*3 - 1;
        uint32_t sb0 = base + (uint32_t)(st*CV_STAGE*4);
        // A: 2 planes x 256 rows x 4 segs = 2048 cp16 (8/thread)
        #pragma unroll
        for (int j = 0; j < 8; j++) {
            int idx = tid + j*256;
            int p   = idx >> 10;
            int rem = idx & 1023;
            int row = rem >> 2;
            int seg = rem & 3;
            const __nv_bfloat16* wsrc = (p ? d_ws : d_wb)
                + (size_t)row*KCONV + kc + seg*8;
            cp16(sb0 + (uint32_t)((p*CA_PLANE + row*CV_ROW + seg*4)*4), wsrc);
        }
        // B: 2 planes x 128 rows x 4 segs = 1024 cp16 (4/thread)
        #pragma unroll
        for (int j = 0; j < 4; j++) {
            int idx = tid + j*256;
            int p   = idx >> 9;
            int rem = idx & 511;
            int row = rem >> 2;
            int seg = rem & 3;
            int h = h0 + (row >> 6) + ky;
            int w = (row & 63) + kx;
            int valid = ((unsigned)h < 64u) & ((unsigned)w < 64u);
            int pix = valid ? (h*64 + w) : 0;
            const __nv_bfloat16* xsrc = (p ? d_xts : d_xtb)
                + (size_t)(b*NPIX + pix)*CCH + c0 + seg*8;
            cp16z(sb0 + (uint32_t)((2*CA_PLANE + p*CB_PLANE + row*CV_ROW + seg*4)*4),
                  xsrc, valid ? 16 : 0);
        }
    };

    stage(0, 0);
    cp_commit();

    for (int it = 0; it < 72; it++) {
        if (it < 71) { stage((it+1) & 1, (it+1)*32); cp_commit(); cp_wait<1>(); }
        else cp_wait<0>();
        __syncthreads();

        const float* St = smem + (it & 1)*CV_STAGE;
        const float* Ab = St;
        const float* Am = St + CA_PLANE;
        const float* Bb = St + 2*CA_PLANE;
        const float* Bm = St + 2*CA_PLANE + CB_PLANE;

        #pragma unroll
        for (int ch = 0; ch < 2; ch++) {
            int ko = ch*8 + cq;
            unsigned ab[4][4], as_[4][4];
            #pragma unroll
            for (int mt = 0; mt < 4; mt++) {
                int m = wm*64 + mt*16 + r;
                ab[mt][0] = ldu(&Ab[m*CV_ROW + ko]);
                ab[mt][1] = ldu(&Ab[(m+8)*CV_ROW + ko]);
                ab[mt][2] = ldu(&Ab[m*CV_ROW + ko + 4]);
                ab[mt][3] = ldu(&Ab[(m+8)*CV_ROW + ko + 4]);
                as_[mt][0] = ldu(&Am[m*CV_ROW + ko]);
                as_[mt][1] = ldu(&Am[(m+8)*CV_ROW + ko]);
                as_[mt][2] = ldu(&Am[m*CV_ROW + ko + 4]);
                as_[mt][3] = ldu(&Am[(m+8)*CV_ROW + ko + 4]);
            }
            #pragma unroll
            for (int nt = 0; nt < 8; nt++) {
                int n = wn*64 + nt*8 + r;
                unsigned bb0 = ldu(&Bb[n*CV_ROW + ko]);
                unsigned bb1 = ldu(&Bb[n*CV_ROW + ko + 4]);
                unsigned bs0 = ldu(&Bm[n*CV_ROW + ko]);
                unsigned bs1 = ldu(&Bm[n*CV_ROW + ko + 4]);
                #pragma unroll
                for (int mt = 0; mt < 4; mt++) {
                    float* cf = C[mt*8 + nt];
                    mma_bf16(cf, ab[mt][0], ab[mt][1], ab[mt][2], ab[mt][3], bb0, bb1);
                    mma_bf16(cf, ab[mt][0], ab[mt][1], ab[mt][2], ab[mt][3], bs0, bs1);
                    mma_bf16(cf, as_[mt][0], as_[mt][1], as_[mt][2], as_[mt][3], bb0, bb1);
                }
            }
        }
        __syncthreads();
    }

    #pragma unroll
    for (int mt = 0; mt < 4; mt++) {
        int m = wm*64 + mt*16 + r;
        float bv0 = sb[m], bv8 = sb[m + 8];
        #pragma unroll
        for (int nt = 0; nt < 8; nt++) {
            int n = pix0 + wn*64 + nt*8 + 2*cq;
            float* cf = C[mt*8 + nt];
            *(float2*)&d_xs[((size_t)(b*CCH + m))*NPIX + n]     = make_float2(cf[0]+bv0, cf[1]+bv0);
            *(float2*)&d_xs[((size_t)(b*CCH + m + 8))*NPIX + n] = make_float2(cf[2]+bv8, cf[3]+bv8);
        }
    }
}

// ---------------- GroupNorm partial sums ----------------------------------------
__global__ void gn_part_kernel(int which) {
    const float* src = which ? d_z : d_xs;
    float* part      = which ? d_part2 : d_part1;
    int blk = blockIdx.x;
    int bg = blk >> 4, ch = blk & 15;
    const float4* p = (const float4*)(src + (size_t)bg*GSIZE + ch*(GSIZE/16));
    float s = 0.f, s2 = 0.f;
    #pragma unroll
    for (int i = 0; i < 8; i++) {
        float4 v = p[threadIdx.x + i*256];
        s  += v.x + v.y + v.z + v.w;
        s2 += v.x*v.x + v.y*v.y + v.z*v.z + v.w*v.w;
    }
    #pragma unroll
    for (int off = 16; off > 0; off >>= 1) {
        s  += __shfl_xor_sync(0xffffffffu, s,  off);
        s2 += __shfl_xor_sync(0xffffffffu, s2, off);
    }
    __shared__ float sh[16];
    int wid = threadIdx.x >> 5, lid = threadIdx.x & 31;
    if (lid == 0) { sh[wid] = s; sh[wid + 8] = s2; }
    __syncthreads();
    if (threadIdx.x == 0) {
        float S = 0.f, S2 = 0.f;
        #pragma unroll
        for (int w = 0; w < 8; w++) { S += sh[w]; S2 += sh[w + 8]; }
        part[blk*2]     = S;
        part[blk*2 + 1] = S2;
    }
}

// ---------------- GN1 apply + ReLU; writes fp32 xs AND bf16 k-pair xsb ----------
__global__ void gn1_apply_kernel(const float* __restrict__ gw,
                                 const float* __restrict__ gb) {
    __shared__ float st[2];
    int b  = blockIdx.z;
    int kp = blockIdx.y;
    int c  = kp << 1;
    int bg = b*8 + (kp >> 4);
    if (threadIdx.x == 0) {
        float S = 0.f, S2 = 0.f;
        #pragma unroll
        for (int i = 0; i < 16; i++) {
            S  += d_part1[(bg*16 + i)*2];
            S2 += d_part1[(bg*16 + i)*2 + 1];
        }
        float mean = S / (float)GSIZE;
        st[0] = mean;
        st[1] = rsqrtf(S2 / (float)GSIZE - mean*mean + EPSV);
    }
    __syncthreads();
    float sc0 = st[1] * gw[c],   sh0 = gb[c]   - st[0]*sc0;
    float sc1 = st[1] * gw[c+1], sh1 = gb[c+1] - st[0]*sc1;
    int n = blockIdx.x*1024 + threadIdx.x*4;
    size_t base = ((size_t)(b*CCH + c))*NPIX + n;
    float4 v0 = *(float4*)&d_xs[base];
    float4 v1 = *(float4*)&d_xs[base + NPIX];
    v0.x = fmaxf(v0.x*sc0 + sh0, 0.f); v0.y = fmaxf(v0.y*sc0 + sh0, 0.f);
    v0.z = fmaxf(v0.z*sc0 + sh0, 0.f); v0.w = fmaxf(v0.w*sc0 + sh0, 0.f);
    v1.x = fmaxf(v1.x*sc1 + sh1, 0.f); v1.y = fmaxf(v1.y*sc1 + sh1, 0.f);
    v1.z = fmaxf(v1.z*sc1 + sh1, 0.f); v1.w = fmaxf(v1.w*sc1 + sh1, 0.f);
    *(float4*)&d_xs[base]        = v0;
    *(float4*)&d_xs[base + NPIX] = v1;
    uint4 pk;
    pk.x = pack_bf(v1.x, v0.x);
    pk.y = pack_bf(v1.y, v0.y);
    pk.z = pack_bf(v1.z, v0.z);
    pk.w = pack_bf(v1.w, v0.w);
    *(uint4*)&d_xsb[((size_t)(b*128 + kp))*NPIX + n] = pk;
}

// ---------------- bf16 1x1 GEMM -------------------------------------------------
template<int MODE>
__global__ void __launch_bounds__(256) gemm_bf_kernel(const float* __restrict__ bias0,
                                                      const float* __restrict__ bias1,
                                                      const float* __restrict__ bias2) {
    constexpr int K  = (MODE == 3) ? 128 : 256;
    constexpr int KP = K / 2;
    constexpr int NI = K / 32;
    const unsigned* Wp = d_wpk + (MODE == 3 ? 49152 : 0);
    const unsigned* Xall = (MODE == 3) ? d_yb : d_xsb;

    __shared__ unsigned Ws[2][64*20];
    __shared__ unsigned Xs[2][16*132];

    int b  = blockIdx.z;
    int n0 = blockIdx.x * 128;
    int m0 = blockIdx.y * 64;
    const unsigned* Xb = Xall + (size_t)b * KP * NPIX;

    int tid  = threadIdx.x;
    int lane = tid & 31;
    int wid  = tid >> 5;
    int wm = wid >> 2, wn = wid & 3;
    int r  = lane >> 2, cq = lane & 3;

    int wRow = tid >> 2, wSeg = tid & 3;
    int xRow = tid >> 5, xSeg = tid & 31;
    uint32_t wBase = smem_u32(Ws);
    uint32_t xBase = smem_u32(Xs);

    auto stage = [&](int s, int it) {
        int kp0 = it * 16;
        cp16(wBase + (uint32_t)((s*64*20 + wRow*20 + wSeg*4)*4),
             Wp + (size_t)(m0 + wRow)*KP + kp0 + wSeg*4);
        #pragma unroll
        for (int j = 0; j < 2; j++) {
            int k = xRow + j*8;
            cp16(xBase + (uint32_t)((s*16*132 + k*132 + xSeg*4)*4),
                 Xb + (size_t)(kp0 + k)*NPIX + n0 + xSeg*4);
        }
    };

    float C[8][4];
    #pragma unroll
    for (int i = 0; i < 8; i++)
        #pragma unroll
        for (int j = 0; j < 4; j++) C[i][j] = 0.f;

    stage(0, 0);
    cp_commit();

    for (int it = 0; it < NI; it++) {
        if (it < NI-1) { stage((it+1)&1, it+1); cp_commit(); cp_wait<1>(); }
        else cp_wait<0>();
        __syncthreads();

        const unsigned* Wt = Ws[it & 1];
        const unsigned* Xt = Xs[it & 1];

        #pragma unroll
        for (int ch = 0; ch < 2; ch++) {
            int ko = ch*8 + cq;
            unsigned a[2][4];
            #pragma unroll
            for (int mt = 0; mt < 2; mt++) {
                int mr = wm*32 + mt*16 + r;
                a[mt][0] = Wt[mr*20 + ko];
                a[mt][1] = Wt[(mr+8)*20 + ko];
                a[mt][2] = Wt[mr*20 + ko + 4];
                a[mt][3] = Wt[(mr+8)*20 + ko + 4];
            }
            #pragma unroll
            for (int nt = 0; nt < 4; nt++) {
                int nn = wn*32 + nt*8 + r;
                unsigned b0 = Xt[ko*132 + nn];
                unsigned b1 = Xt[(ko+4)*132 + nn];
                mma_bf16(C[nt],     a[0][0], a[0][1], a[0][2], a[0][3], b0, b1);
                mma_bf16(C[4 + nt], a[1][0], a[1][1], a[1][2], a[1][3], b0, b1);
            }
        }
        __syncthreads();
    }

    const float* bias = (MODE == 3) ? bias0
                      : (m0 < 128 ? bias0 : m0 < 256 ? bias1 : bias2);
    int mbase = (MODE == 3) ? m0 : (m0 & 127);
    __nv_bfloat16* Obf = nullptr;
    if (MODE != 3)
        Obf = (m0 < 128 ? d_thb : m0 < 256 ? d_phb : d_gb) + (size_t)b * CI * NPIX;

    #pragma unroll
    for (int mt = 0; mt < 2; mt++) {
        int ml = mbase + wm*32 + mt*16 + r;
        float bv0 = bias[ml], bv8 = bias[ml + 8];
        #pragma unroll
        for (int nt = 0; nt < 4; nt++) {
            int n = n0 + wn*32 + nt*8 + 2*cq;
            float* cf = C[mt*4 + nt];
            if (MODE == 3) {
                float* Ob = d_z + (size_t)b * CCH * NPIX;
                *(float2*)&Ob[(size_t)ml*NPIX + n]     = make_float2(cf[0]+bv0, cf[1]+bv0);
                *(float2*)&Ob[(size_t)(ml+8)*NPIX + n] = make_float2(cf[2]+bv8, cf[3]+bv8);
            } else {
                *(unsigned*)&Obf[(size_t)ml*NPIX + n]     = pack_bf(cf[1]+bv0, cf[0]+bv0);
                *(unsigned*)&Obf[(size_t)(ml+8)*NPIX + n] = pack_bf(cf[3]+bv8, cf[2]+bv8);
            }
        }
    }
}

// ---------------- bf16 flash attention (unchanged) -------------------------------
#define KS_STR 68
#define KS_STAGE (64*KS_STR)
#define GS_STR 36
#define GS_STAGE (128*GS_STR)
#define ATTN_SMEM ((2*KS_STAGE + 2*GS_STAGE)*4)

__global__ void __launch_bounds__(256) attention_tc_kernel() {
    extern __shared__ float smem[];
    float* sK = smem;
    float* sG = smem + 2*KS_STAGE;

    int b  = blockIdx.y;
    int n0 = blockIdx.x * 128;
    const __nv_bfloat16* Tt = d_ttb + (size_t)b * NPIX * CI;
    const __nv_bfloat16* Pt = d_ptb + (size_t)b * NPIX * CI;
    const __nv_bfloat16* Gp = d_gb  + (size_t)b * CI * NPIX;
    unsigned* Ybu = d_yb + (size_t)b * 64 * NPIX;

    int tid  = threadIdx.x;
    int lane = tid & 31;
    int wid  = tid >> 5;
    int qb   = wid * 16;
    int r    = lane >> 2;
    int cq   = lane & 3;

    uint32_t kBase = smem_u32(sK);
    uint32_t gBase = smem_u32(sG);

    auto stageK = [&](int s, int m0k) {
        #pragma unroll
        for (int j = 0; j < 4; j++) {
            int idx = tid + j*256;
            int row = idx >> 4, seg = idx & 15;
            cp16(kBase + (uint32_t)((s*KS_STAGE + row*KS_STR + seg*4)*4),
                 Pt + (size_t)(m0k + row)*CI + seg*8);
        }
    };
    auto stageG = [&](int s, int m0k) {
        #pragma unroll
        for (int j = 0; j < 4; j++) {
            int idx = tid + j*256;
            int row = idx >> 3, seg = idx & 7;
            cp16(gBase + (uint32_t)((s*GS_STAGE + row*GS_STR + seg*4)*4),
                 Gp + (size_t)row*NPIX + m0k + seg*8);
        }
    };

    // ---- Q prologue ----
    #pragma unroll
    for (int j = 0; j < 8; j++) {
        int idx = tid + j*256;
        int row = idx >> 4, seg = idx & 15;
        cp16(kBase + (uint32_t)((row*KS_STR + seg*4)*4),
             Tt + (size_t)(n0 + row)*CI + seg*8);
    }
    cp_commit();
    cp_wait<0>();
    __syncthreads();

    unsigned qa[8][4];
    #pragma unroll
    for (int ch = 0; ch < 8; ch++) {
        int ko = ch*8 + cq;
        qa[ch][0] = ldu(&sK[(qb + r)*KS_STR + ko]);
        qa[ch][1] = ldu(&sK[(qb + r + 8)*KS_STR + ko]);
        qa[ch][2] = ldu(&sK[(qb + r)*KS_STR + ko + 4]);
        qa[ch][3] = ldu(&sK[(qb + r + 8)*KS_STR + ko + 4]);
    }
    __syncthreads();

    stageK(0, 0); cp_commit();
    stageG(0, 0); cp_commit();

    float O[16][4];
    #pragma unroll
    for (int i = 0; i < 16; i++)
        #pragma unroll
        for (int j = 0; j < 4; j++) O[i][j] = 0.f;
    float Mx0 = -1e30f, Mx1 = -1e30f, L0 = 0.f, L1 = 0.f;
    const unsigned FULL = 0xffffffffu;

    for (int t = 0; t < 64; t++) {
        int s = t & 1;
        int m0 = t * 64;

        if (t < 63) { stageK(s^1, m0 + 64); cp_commit(); cp_wait<2>(); }
        else        cp_wait<1>();
        __syncthreads();

        const float* Kt = sK + s*KS_STAGE;
        float S[8][4];
        #pragma unroll
        for (int i = 0; i < 8; i++)
            #pragma unroll
            for (int j = 0; j < 4; j++) S[i][j] = 0.f;

        #pragma unroll
        for (int ch = 0; ch < 8; ch++) {
            int ko = ch*8 + cq;
            #pragma unroll
            for (int nt = 0; nt < 8; nt++) {
                unsigned b0 = ldu(&Kt[(nt*8 + r)*KS_STR + ko]);
                unsigned b1 = ldu(&Kt[(nt*8 + r)*KS_STR + ko + 4]);
                mma_bf16(S[nt], qa[ch][0], qa[ch][1], qa[ch][2], qa[ch][3], b0, b1);
            }
        }

        float rm0 = -1e30f, rm1 = -1e30f;
        #pragma unroll
        for (int nt = 0; nt < 8; nt++) {
            rm0 = fmaxf(rm0, fmaxf(S[nt][0], S[nt][1]));
            rm1 = fmaxf(rm1, fmaxf(S[nt][2], S[nt][3]));
        }
        rm0 = fmaxf(rm0, __shfl_xor_sync(FULL, rm0, 1));
        rm0 = fmaxf(rm0, __shfl_xor_sync(FULL, rm0, 2));
        rm1 = fmaxf(rm1, __shfl_xor_sync(FULL, rm1, 1));
        rm1 = fmaxf(rm1, __shfl_xor_sync(FULL, rm1, 2));

        float nm0 = fmaxf(Mx0, rm0), nm1 = fmaxf(Mx1, rm1);
        float sc0 = __expf(Mx0 - nm0), sc1 = __expf(Mx1 - nm1);
        Mx0 = nm0; Mx1 = nm1;

        float rs0 = 0.f, rs1 = 0.f;
        #pragma unroll
        for (int nt = 0; nt < 8; nt++) {
            S[nt][0] = __expf(S[nt][0] - nm0);
            S[nt][1] = __expf(S[nt][1] - nm0);
            S[nt][2] = __expf(S[nt][2] - nm1);
            S[nt][3] = __expf(S[nt][3] - nm1);
            rs0 += S[nt][0] + S[nt][1];
            rs1 += S[nt][2] + S[nt][3];
        }
        rs0 += __shfl_xor_sync(FULL, rs0, 1);
        rs0 += __shfl_xor_sync(FULL, rs0, 2);
        rs1 += __shfl_xor_sync(FULL, rs1, 1);
        rs1 += __shfl_xor_sync(FULL, rs1, 2);
        L0 = L0*sc0 + rs0;
        L1 = L1*sc1 + rs1;

        if (!__all_sync(FULL, (sc0 == 1.f) & (sc1 == 1.f))) {
            #pragma unroll
            for (int i = 0; i < 16; i++) {
                O[i][0] *= sc0; O[i][1] *= sc0;
                O[i][2] *= sc1; O[i][3] *= sc1;
            }
        }

        unsigned pa[4][4];
        #pragma unroll
        for (int kc = 0; kc < 4; kc++) {
            pa[kc][0] = pack_bf(S[2*kc][1],   S[2*kc][0]);
            pa[kc][1] = pack_bf(S[2*kc][3],   S[2*kc][2]);
            pa[kc][2] = pack_bf(S[2*kc+1][1], S[2*kc+1][0]);
            pa[kc][3] = pack_bf(S[2*kc+1][3], S[2*kc+1][2]);
        }

        if (t < 63) { stageG(s^1, m0 + 64); cp_commit(); cp_wait<2>(); }
        else        cp_wait<0>();
        __syncthreads();

        const float* Gt = sG + s*GS_STAGE;
        #pragma unroll
        for (int kc = 0; kc < 4; kc++) {
            int ko = kc*8 + cq;
            #pragma unroll
            for (int ct = 0; ct < 16; ct++) {
                unsigned b0 = ldu(&Gt[(ct*8 + r)*GS_STR + ko]);
                unsigned b1 = ldu(&Gt[(ct*8 + r)*GS_STR + ko + 4]);
                mma_bf16(O[ct], pa[kc][0], pa[kc][1], pa[kc][2], pa[kc][3], b0, b1);
            }
        }
    }

    float inv0 = 1.0f / L0, inv1 = 1.0f / L1;
    int q = n0 + qb + r;
    #pragma unroll
    for (int ct = 0; ct < 16; ct++) {
        int kp = ct*4 + cq;
        Ybu[(size_t)kp*NPIX + q]     = pack_bf(O[ct][1]*inv0, O[ct][0]*inv0);
        Ybu[(size_t)kp*NPIX + q + 8] = pack_bf(O[ct][3]*inv1, O[ct][2]*inv1);
    }
}

// ---------------- final: out = GN2(z)*0.1 + xs ----------------------------------
__global__ void final_apply_kernel(const float* __restrict__ gw,
                                   const float* __restrict__ gb,
                                   float* __restrict__ out) {
    __shared__ float st[2];
    int bg = blockIdx.x >> 7;
    if (threadIdx.x == 0) {
        float S = 0.f, S2 = 0.f;
        #pragma unroll
        for (int i = 0; i < 16; i++) {
            S  += d_part2[(bg*16 + i)*2];
            S2 += d_part2[(bg*16 + i)*2 + 1];
        }
        float mean = S / (float)GSIZE;
        st[0] = mean;
        st[1] = rsqrtf(S2 / (float)GSIZE - mean*mean + EPSV);
    }
    __syncthreads();
    int i4 = blockIdx.x * blockDim.x + threadIdx.x;
    int idx = i4 << 2;
    int c   = (idx >> 12) & 255;
    float sc = st[1] * gw[c];
    float sh = gb[c] - st[0] * sc;
    float4 z = ((const float4*)d_z)[i4];
    float4 xs = ((const float4*)d_xs)[i4];
    float4 o;
    o.x = (z.x*sc + sh)*0.1f + xs.x;
    o.y = (z.y*sc + sh)*0.1f + xs.y;
    o.z = (z.z*sc + sh)*0.1f + xs.z;
    o.w = (z.w*sc + sh)*0.1f + xs.w;
    ((float4*)out)[i4] = o;
}

// ---------------- launch ---------------------------------------------------------
extern "C" void kernel_launch(void* const* d_in, const int* in_sizes, int n_in,
                              void* d_out, int out_size) {
    const float* x    = (const float*)d_in[0];
    const float* sw   = (const float*)d_in[1];
    const float* sb   = (const float*)d_in[2];
    const float* gn1w = (const float*)d_in[3];
    const float* gn1b = (const float*)d_in[4];
    const float* g_w  = (const float*)d_in[5];
    const float* g_b  = (const float*)d_in[6];
    const float* th_w = (const float*)d_in[7];
    const float* th_b = (const float*)d_in[8];
    const float* ph_w = (const float*)d_in[9];
    const float* ph_b = (const float*)d_in[10];
    const float* w_w  = (const float*)d_in[11];
    const float* w_b  = (const float*)d_in[12];
    const float* gn2w = (const float*)d_in[13];
    const float* gn2b = (const float*)d_in[14];
    float* out = (float*)d_out;

    static int attrSet = 0;
    if (!attrSet) {
        cudaFuncSetAttribute(conv_tc_kernel,
                             cudaFuncAttributeMaxDynamicSharedMemorySize, CONV_SMEM);
        cudaFuncSetAttribute(attention_tc_kernel,
                             cudaFuncAttributeMaxDynamicSharedMemorySize, ATTN_SMEM);
        attrSet = 1;
    }

    pack_w_bf_kernel<<<dim3(9, 256), 256>>>(sw);
    prep_x_kernel<<<dim3(128, 8, 4), dim3(32, 8)>>>(x);
    pack_qkvw_kernel<<<256, 256>>>(th_w, ph_w, g_w, w_w);
    conv_tc_kernel<<<dim3(32, 4), 256, CONV_SMEM>>>(sb);
    gn_part_kernel<<<512, 256>>>(0);
    gn1_apply_kernel<<<dim3(4, 128, 4), 256>>>(gn1w, gn1b);

    gemm_bf_kernel<0><<<dim3(32, 6, 4), 256>>>(th_b, ph_b, g_b);
    prep_attn_kernel<<<dim3(128, 4, 8), dim3(32, 8)>>>();

    attention_tc_kernel<<<dim3(32, 4), 256, ATTN_SMEM>>>();

    gemm_bf_kernel<3><<<dim3(32, 4, 4), 256>>>(w_b, nullptr, nullptr);
    gn_part_kernel<<<512, 256>>>(1);
    final_apply_kernel<<<4096, 256>>>(gn2w, gn2b, out);

    (void)in_sizes; (void)n_in; (void)out_size;
}

// round 11
// speedup vs baseline: 5.7332x; 1.0411x over previous
#include <cuda_runtime.h>
#include <cuda_bf16.h>
#include <math.h>
#include <stdint.h>

#define BATCH 4
#define CCH   256
#define CI    128
#define NPIX  4096
#define GROUPS 8
#define CPG   32
#define GSIZE (CPG*NPIX)
#define EPSV  1e-5f
#define KCONV 2304            // 9 taps * 256 cin, tap-major

// ---------------- scratch ----------------------------------------------------
__device__ float d_xs   [BATCH*CCH*NPIX];
__device__ float d_z    [BATCH*CCH*NPIX];
__device__ unsigned d_xsb[BATCH*128*NPIX];
__device__ unsigned d_yb [BATCH*64*NPIX];
__device__ unsigned d_wpk[65536];
__device__ __nv_bfloat16 d_wb [CCH*KCONV];
__device__ __nv_bfloat16 d_ws [CCH*KCONV];
__device__ __nv_bfloat16 d_xtb[BATCH*NPIX*CCH];
__device__ __nv_bfloat16 d_xts[BATCH*NPIX*CCH];
__device__ __nv_bfloat16 d_thb[BATCH*CI*NPIX];
__device__ __nv_bfloat16 d_phb[BATCH*CI*NPIX];
__device__ __nv_bfloat16 d_ttb[BATCH*NPIX*CI];
__device__ __nv_bfloat16 d_ptb[BATCH*NPIX*CI];
__device__ __nv_bfloat16 d_gb [BATCH*CI*NPIX];
__device__ float d_part1[32*16*2];
__device__ float d_part2[32*16*2];

// ---------------- helpers -----------------------------------------------------
__device__ __forceinline__ void mma_bf16(float* c,
    unsigned a0, unsigned a1, unsigned a2, unsigned a3,
    unsigned b0, unsigned b1) {
    asm volatile(
        "mma.sync.aligned.m16n8k16.row.col.f32.bf16.bf16.f32 "
        "{%0,%1,%2,%3}, {%4,%5,%6,%7}, {%8,%9}, {%0,%1,%2,%3};"
        : "+f"(c[0]), "+f"(c[1]), "+f"(c[2]), "+f"(c[3])
        : "r"(a0), "r"(a1), "r"(a2), "r"(a3), "r"(b0), "r"(b1));
}
__device__ __forceinline__ unsigned pack_bf(float hi, float lo) {
    unsigned u;
    asm("cvt.rn.bf16x2.f32 %0, %1, %2;" : "=r"(u) : "f"(hi), "f"(lo));
    return u;
}
__device__ __forceinline__ void cp16(uint32_t dst, const void* src) {
    asm volatile("cp.async.cg.shared.global [%0], [%1], 16;" :: "r"(dst), "l"(src));
}
__device__ __forceinline__ void cp16z(uint32_t dst, const void* src, int srcsz) {
    asm volatile("cp.async.cg.shared.global [%0], [%1], 16, %2;"
                 :: "r"(dst), "l"(src), "r"(srcsz));
}
__device__ __forceinline__ void cp_commit() {
    asm volatile("cp.async.commit_group;");
}
template<int N>
__device__ __forceinline__ void cp_wait() {
    asm volatile("cp.async.wait_group %0;" :: "n"(N));
}
__device__ __forceinline__ uint32_t smem_u32(const void* p) {
    return (uint32_t)__cvta_generic_to_shared(p);
}
__device__ __forceinline__ unsigned ldu(const float* p) {
    return __float_as_uint(*p);
}

// ---------------- precompute: conv weight 2-term bf16 split --------------------
__global__ void pack_w_bf_kernel(const float* __restrict__ w) {
    int k = blockIdx.x * 256 + threadIdx.x;
    int m = blockIdx.y;
    int c = k & 255, tap = k >> 8;
    float f = w[m*(CCH*9) + c*9 + tap];
    __nv_bfloat16 big = __float2bfloat16(f);
    d_wb[(size_t)m*KCONV + k] = big;
    d_ws[(size_t)m*KCONV + k] = __float2bfloat16(f - __bfloat162float(big));
}

// ---------------- precompute: x transpose + split -> [b][pix][c] bf16 ---------
__global__ void prep_x_kernel(const float* __restrict__ x) {
    __shared__ float t[32][33];
    int b  = blockIdx.z;
    int p0 = blockIdx.x * 32;
    int c0 = blockIdx.y * 32;
    int tx = threadIdx.x, ty = threadIdx.y;
    #pragma unroll
    for (int i = 0; i < 4; i++)
        t[ty + i*8][tx] = x[(size_t)(b*CCH + c0 + ty + i*8)*NPIX + p0 + tx];
    __syncthreads();
    #pragma unroll
    for (int i = 0; i < 4; i++) {
        int p = ty + i*8;
        float f = t[tx][p];
        __nv_bfloat16 big = __float2bfloat16(f);
        size_t o = (size_t)(b*NPIX + p0 + p)*CCH + c0 + tx;
        d_xtb[o] = big;
        d_xts[o] = __float2bfloat16(f - __bfloat162float(big));
    }
}

// ---------------- precompute: pack qkv+w weights to bf16x2 k-pairs -------------
__global__ void pack_qkvw_kernel(const float* __restrict__ thw,
                                 const float* __restrict__ phw,
                                 const float* __restrict__ gw_,
                                 const float* __restrict__ ww) {
    int idx = blockIdx.x * 256 + threadIdx.x;
    const float* src;
    int off, loc, K;
    if (idx < 16384)      { src = thw; off = 0;     loc = idx;         K = 256; }
    else if (idx < 32768) { src = phw; off = 16384; loc = idx - 16384; K = 256; }
    else if (idx < 49152) { src = gw_; off = 32768; loc = idx - 32768; K = 256; }
    else                  { src = ww;  off = 49152; loc = idx - 49152; K = 128; }
    int kp = loc & (K/2 - 1);
    int m  = loc / (K/2);
    d_wpk[off + loc] = pack_bf(src[m*K + kp*2 + 1], src[m*K + kp*2]);
}

// ---------------- prep attention: transpose theta/phi bf16 -> [n][c] -----------
__global__ void prep_attn_kernel() {
    __shared__ __nv_bfloat16 t[32][34];
    int which = blockIdx.z & 1, b = blockIdx.z >> 1;
    const __nv_bfloat16* src = (which ? d_phb : d_thb) + (size_t)b*CI*NPIX;
    __nv_bfloat16* dst = (which ? d_ptb : d_ttb) + (size_t)b*NPIX*CI;
    int n0 = blockIdx.x * 32, c0 = blockIdx.y * 32;
    int tx = threadIdx.x, ty = threadIdx.y;
    #pragma unroll
    for (int i = 0; i < 4; i++)
        t[ty + i*8][tx] = src[(size_t)(c0 + ty + i*8)*NPIX + n0 + tx];
    __syncthreads();
    #pragma unroll
    for (int i = 0; i < 4; i++) {
        int n = ty + i*8;
        dst[(size_t)(n0 + n)*CI + c0 + tx] = t[tx][n];
    }
}

// ---------------- conv3x3 implicit GEMM, bf16 2-term, 256m x 128n block --------
// K-chunk 64; 3 separated product passes (no same-accumulator RAW chains).
// smem per stage (floats): Ab 256x36 | As 256x36 | Bb 128x36 | Bs 128x36
#define CV_ROW 36
#define CA_PLANE (256*CV_ROW)                 // 9216 floats
#define CB_PLANE (128*CV_ROW)                 // 4608 floats
#define CV_STAGE (2*CA_PLANE + 2*CB_PLANE)    // 27648 floats
#define CONV_SMEM (2*CV_STAGE*4)              // 221184 bytes

__global__ void __launch_bounds__(256, 1) conv_tc_kernel(const float* __restrict__ sb) {
    extern __shared__ float smem[];

    int b    = blockIdx.y;
    int pix0 = blockIdx.x * 128;
    int h0   = pix0 >> 6;

    int tid  = threadIdx.x;
    int lane = tid & 31;
    int wid  = tid >> 5;
    int wm = wid >> 1, wn = wid & 1;     // 4m x 2n warps, warp tile 64x64
    int r  = lane >> 2, cq = lane & 3;

    uint32_t base = smem_u32(smem);

    float C[32][4];
    #pragma unroll
    for (int i = 0; i < 32; i++)
        #pragma unroll
        for (int j = 0; j < 4; j++) C[i][j] = 0.f;

    // stage one 64-k chunk (within a single tap: 256/64 = 4 chunks per tap)
    auto stage = [&](int st, int kc) {
        int tap = kc >> 8;
        int c0  = kc & 255;
        int ky  = tap/3 - 1;
        int kx  = tap - (tap/3)*3 - 1;
        uint32_t sb0 = base + (uint32_t)(st*CV_STAGE*4);
        // A: 2 planes x 256 rows x 8 segs(16B) = 4096 cp16 -> 16/thread
        #pragma unroll
        for (int j = 0; j < 16; j++) {
            int idx = tid + j*256;
            int p   = idx >> 11;
            int rem = idx & 2047;
            int row = rem >> 3;
            int seg = rem & 7;
            const __nv_bfloat16* wsrc = (p ? d_ws : d_wb)
                + (size_t)row*KCONV + kc + seg*8;
            cp16(sb0 + (uint32_t)((p*CA_PLANE + row*CV_ROW + seg*4)*4), wsrc);
        }
        // B: 2 planes x 128 rows x 8 segs = 2048 cp16 -> 8/thread
        #pragma unroll
        for (int j = 0; j < 8; j++) {
            int idx = tid + j*256;
            int p   = idx >> 10;
            int rem = idx & 1023;
            int row = rem >> 3;
            int seg = rem & 7;
            int h = h0 + (row >> 6) + ky;
            int w = (row & 63) + kx;
            int valid = ((unsigned)h < 64u) & ((unsigned)w < 64u);
            int pix = valid ? (h*64 + w) : 0;
            const __nv_bfloat16* xsrc = (p ? d_xts : d_xtb)
                + (size_t)(b*NPIX + pix)*CCH + c0 + seg*8;
            cp16z(sb0 + (uint32_t)((2*CA_PLANE + p*CB_PLANE + row*CV_ROW + seg*4)*4),
                  xsrc, valid ? 16 : 0);
        }
    };

    stage(0, 0);
    cp_commit();

    for (int it = 0; it < 36; it++) {
        if (it < 35) { stage((it+1) & 1, (it+1)*64); cp_commit(); cp_wait<1>(); }
        else cp_wait<0>();
        __syncthreads();

        const float* St = smem + (it & 1)*CV_STAGE;
        const float* Ab = St;
        const float* Am = St + CA_PLANE;
        const float* Bb = St + 2*CA_PLANE;
        const float* Bm = St + 2*CA_PLANE + CB_PLANE;

        #pragma unroll
        for (int ch = 0; ch < 4; ch++) {
            int ko = ch*8 + cq;
            unsigned ab[4][4], as_[4][4];
            #pragma unroll
            for (int mt = 0; mt < 4; mt++) {
                int m = wm*64 + mt*16 + r;
                ab[mt][0] = ldu(&Ab[m*CV_ROW + ko]);
                ab[mt][1] = ldu(&Ab[(m+8)*CV_ROW + ko]);
                ab[mt][2] = ldu(&Ab[m*CV_ROW + ko + 4]);
                ab[mt][3] = ldu(&Ab[(m+8)*CV_ROW + ko + 4]);
                as_[mt][0] = ldu(&Am[m*CV_ROW + ko]);
                as_[mt][1] = ldu(&Am[(m+8)*CV_ROW + ko]);
                as_[mt][2] = ldu(&Am[m*CV_ROW + ko + 4]);
                as_[mt][3] = ldu(&Am[(m+8)*CV_ROW + ko + 4]);
            }
            unsigned bb[8][2], bs[8][2];
            #pragma unroll
            for (int nt = 0; nt < 8; nt++) {
                int n = wn*64 + nt*8 + r;
                bb[nt][0] = ldu(&Bb[n*CV_ROW + ko]);
                bb[nt][1] = ldu(&Bb[n*CV_ROW + ko + 4]);
                bs[nt][0] = ldu(&Bm[n*CV_ROW + ko]);
                bs[nt][1] = ldu(&Bm[n*CV_ROW + ko + 4]);
            }
            // pass 1: big*big (32 distinct accumulators -> no RAW chains)
            #pragma unroll
            for (int mt = 0; mt < 4; mt++)
                #pragma unroll
                for (int nt = 0; nt < 8; nt++)
                    mma_bf16(C[mt*8+nt], ab[mt][0], ab[mt][1], ab[mt][2], ab[mt][3],
                             bb[nt][0], bb[nt][1]);
            // pass 2: big*small
            #pragma unroll
            for (int mt = 0; mt < 4; mt++)
                #pragma unroll
                for (int nt = 0; nt < 8; nt++)
                    mma_bf16(C[mt*8+nt], ab[mt][0], ab[mt][1], ab[mt][2], ab[mt][3],
                             bs[nt][0], bs[nt][1]);
            // pass 3: small*big
            #pragma unroll
            for (int mt = 0; mt < 4; mt++)
                #pragma unroll
                for (int nt = 0; nt < 8; nt++)
                    mma_bf16(C[mt*8+nt], as_[mt][0], as_[mt][1], as_[mt][2], as_[mt][3],
                             bb[nt][0], bb[nt][1]);
        }
        __syncthreads();
    }

    #pragma unroll
    for (int mt = 0; mt < 4; mt++) {
        int m = wm*64 + mt*16 + r;
        float bv0 = sb[m], bv8 = sb[m + 8];
        #pragma unroll
        for (int nt = 0; nt < 8; nt++) {
            int n = pix0 + wn*64 + nt*8 + 2*cq;
            float* cf = C[mt*8 + nt];
            *(float2*)&d_xs[((size_t)(b*CCH + m))*NPIX + n]     = make_float2(cf[0]+bv0, cf[1]+bv0);
            *(float2*)&d_xs[((size_t)(b*CCH + m + 8))*NPIX + n] = make_float2(cf[2]+bv8, cf[3]+bv8);
        }
    }
}

// ---------------- GroupNorm partial sums ----------------------------------------
__global__ void gn_part_kernel(int which) {
    const float* src = which ? d_z : d_xs;
    float* part      = which ? d_part2 : d_part1;
    int blk = blockIdx.x;
    int bg = blk >> 4, ch = blk & 15;
    const float4* p = (const float4*)(src + (size_t)bg*GSIZE + ch*(GSIZE/16));
    float s = 0.f, s2 = 0.f;
    #pragma unroll
    for (int i = 0; i < 8; i++) {
        float4 v = p[threadIdx.x + i*256];
        s  += v.x + v.y + v.z + v.w;
        s2 += v.x*v.x + v.y*v.y + v.z*v.z + v.w*v.w;
    }
    #pragma unroll
    for (int off = 16; off > 0; off >>= 1) {
        s  += __shfl_xor_sync(0xffffffffu, s,  off);
        s2 += __shfl_xor_sync(0xffffffffu, s2, off);
    }
    __shared__ float sh[16];
    int wid = threadIdx.x >> 5, lid = threadIdx.x & 31;
    if (lid == 0) { sh[wid] = s; sh[wid + 8] = s2; }
    __syncthreads();
    if (threadIdx.x == 0) {
        float S = 0.f, S2 = 0.f;
        #pragma unroll
        for (int w = 0; w < 8; w++) { S += sh[w]; S2 += sh[w + 8]; }
        part[blk*2]     = S;
        part[blk*2 + 1] = S2;
    }
}

// ---------------- GN1 apply + ReLU ----------------------------------------------
__global__ void gn1_apply_kernel(const float* __restrict__ gw,
                                 const float* __restrict__ gb) {
    __shared__ float st[2];
    int b  = blockIdx.z;
    int kp = blockIdx.y;
    int c  = kp << 1;
    int bg = b*8 + (kp >> 4);
    if (threadIdx.x == 0) {
        float S = 0.f, S2 = 0.f;
        #pragma unroll
        for (int i = 0; i < 16; i++) {
            S  += d_part1[(bg*16 + i)*2];
            S2 += d_part1[(bg*16 + i)*2 + 1];
        }
        float mean = S / (float)GSIZE;
        st[0] = mean;
        st[1] = rsqrtf(S2 / (float)GSIZE - mean*mean + EPSV);
    }
    __syncthreads();
    float sc0 = st[1] * gw[c],   sh0 = gb[c]   - st[0]*sc0;
    float sc1 = st[1] * gw[c+1], sh1 = gb[c+1] - st[0]*sc1;
    int n = blockIdx.x*1024 + threadIdx.x*4;
    size_t base = ((size_t)(b*CCH + c))*NPIX + n;
    float4 v0 = *(float4*)&d_xs[base];
    float4 v1 = *(float4*)&d_xs[base + NPIX];
    v0.x = fmaxf(v0.x*sc0 + sh0, 0.f); v0.y = fmaxf(v0.y*sc0 + sh0, 0.f);
    v0.z = fmaxf(v0.z*sc0 + sh0, 0.f); v0.w = fmaxf(v0.w*sc0 + sh0, 0.f);
    v1.x = fmaxf(v1.x*sc1 + sh1, 0.f); v1.y = fmaxf(v1.y*sc1 + sh1, 0.f);
    v1.z = fmaxf(v1.z*sc1 + sh1, 0.f); v1.w = fmaxf(v1.w*sc1 + sh1, 0.f);
    *(float4*)&d_xs[base]        = v0;
    *(float4*)&d_xs[base + NPIX] = v1;
    uint4 pk;
    pk.x = pack_bf(v1.x, v0.x);
    pk.y = pack_bf(v1.y, v0.y);
    pk.z = pack_bf(v1.z, v0.z);
    pk.w = pack_bf(v1.w, v0.w);
    *(uint4*)&d_xsb[((size_t)(b*128 + kp))*NPIX + n] = pk;
}

// ---------------- bf16 1x1 GEMM (unchanged) ---------------------------------------
template<int MODE>
__global__ void __launch_bounds__(256) gemm_bf_kernel(const float* __restrict__ bias0,
                                                      const float* __restrict__ bias1,
                                                      const float* __restrict__ bias2) {
    constexpr int K  = (MODE == 3) ? 128 : 256;
    constexpr int KP = K / 2;
    constexpr int NI = K / 32;
    const unsigned* Wp = d_wpk + (MODE == 3 ? 49152 : 0);
    const unsigned* Xall = (MODE == 3) ? d_yb : d_xsb;

    __shared__ unsigned Ws[2][64*20];
    __shared__ unsigned Xs[2][16*132];

    int b  = blockIdx.z;
    int n0 = blockIdx.x * 128;
    int m0 = blockIdx.y * 64;
    const unsigned* Xb = Xall + (size_t)b * KP * NPIX;

    int tid  = threadIdx.x;
    int lane = tid & 31;
    int wid  = tid >> 5;
    int wm = wid >> 2, wn = wid & 3;
    int r  = lane >> 2, cq = lane & 3;

    int wRow = tid >> 2, wSeg = tid & 3;
    int xRow = tid >> 5, xSeg = tid & 31;
    uint32_t wBase = smem_u32(Ws);
    uint32_t xBase = smem_u32(Xs);

    auto stage = [&](int s, int it) {
        int kp0 = it * 16;
        cp16(wBase + (uint32_t)((s*64*20 + wRow*20 + wSeg*4)*4),
             Wp + (size_t)(m0 + wRow)*KP + kp0 + wSeg*4);
        #pragma unroll
        for (int j = 0; j < 2; j++) {
            int k = xRow + j*8;
            cp16(xBase + (uint32_t)((s*16*132 + k*132 + xSeg*4)*4),
                 Xb + (size_t)(kp0 + k)*NPIX + n0 + xSeg*4);
        }
    };

    float C[8][4];
    #pragma unroll
    for (int i = 0; i < 8; i++)
        #pragma unroll
        for (int j = 0; j < 4; j++) C[i][j] = 0.f;

    stage(0, 0);
    cp_commit();

    for (int it = 0; it < NI; it++) {
        if (it < NI-1) { stage((it+1)&1, it+1); cp_commit(); cp_wait<1>(); }
        else cp_wait<0>();
        __syncthreads();

        const unsigned* Wt = Ws[it & 1];
        const unsigned* Xt = Xs[it & 1];

        #pragma unroll
        for (int ch = 0; ch < 2; ch++) {
            int ko = ch*8 + cq;
            unsigned a[2][4];
            #pragma unroll
            for (int mt = 0; mt < 2; mt++) {
                int mr = wm*32 + mt*16 + r;
                a[mt][0] = Wt[mr*20 + ko];
                a[mt][1] = Wt[(mr+8)*20 + ko];
                a[mt][2] = Wt[mr*20 + ko + 4];
                a[mt][3] = Wt[(mr+8)*20 + ko + 4];
            }
            #pragma unroll
            for (int nt = 0; nt < 4; nt++) {
                int nn = wn*32 + nt*8 + r;
                unsigned b0 = Xt[ko*132 + nn];
                unsigned b1 = Xt[(ko+4)*132 + nn];
                mma_bf16(C[nt],     a[0][0], a[0][1], a[0][2], a[0][3], b0, b1);
                mma_bf16(C[4 + nt], a[1][0], a[1][1], a[1][2], a[1][3], b0, b1);
            }
        }
        __syncthreads();
    }

    const float* bias = (MODE == 3) ? bias0
                      : (m0 < 128 ? bias0 : m0 < 256 ? bias1 : bias2);
    int mbase = (MODE == 3) ? m0 : (m0 & 127);
    __nv_bfloat16* Obf = nullptr;
    if (MODE != 3)
        Obf = (m0 < 128 ? d_thb : m0 < 256 ? d_phb : d_gb) + (size_t)b * CI * NPIX;

    #pragma unroll
    for (int mt = 0; mt < 2; mt++) {
        int ml = mbase + wm*32 + mt*16 + r;
        float bv0 = bias[ml], bv8 = bias[ml + 8];
        #pragma unroll
        for (int nt = 0; nt < 4; nt++) {
            int n = n0 + wn*32 + nt*8 + 2*cq;
            float* cf = C[mt*4 + nt];
            if (MODE == 3) {
                float* Ob = d_z + (size_t)b * CCH * NPIX;
                *(float2*)&Ob[(size_t)ml*NPIX + n]     = make_float2(cf[0]+bv0, cf[1]+bv0);
                *(float2*)&Ob[(size_t)(ml+8)*NPIX + n] = make_float2(cf[2]+bv8, cf[3]+bv8);
            } else {
                *(unsigned*)&Obf[(size_t)ml*NPIX + n]     = pack_bf(cf[1]+bv0, cf[0]+bv0);
                *(unsigned*)&Obf[(size_t)(ml+8)*NPIX + n] = pack_bf(cf[3]+bv8, cf[2]+bv8);
            }
        }
    }
}

// ---------------- bf16 flash attention (unchanged) --------------------------------
#define KS_STR 68
#define KS_STAGE (64*KS_STR)
#define GS_STR 36
#define GS_STAGE (128*GS_STR)
#define ATTN_SMEM ((2*KS_STAGE + 2*GS_STAGE)*4)

__global__ void __launch_bounds__(256) attention_tc_kernel() {
    extern __shared__ float smem[];
    float* sK = smem;
    float* sG = smem + 2*KS_STAGE;

    int b  = blockIdx.y;
    int n0 = blockIdx.x * 128;
    const __nv_bfloat16* Tt = d_ttb + (size_t)b * NPIX * CI;
    const __nv_bfloat16* Pt = d_ptb + (size_t)b * NPIX * CI;
    const __nv_bfloat16* Gp = d_gb  + (size_t)b * CI * NPIX;
    unsigned* Ybu = d_yb + (size_t)b * 64 * NPIX;

    int tid  = threadIdx.x;
    int lane = tid & 31;
    int wid  = tid >> 5;
    int qb   = wid * 16;
    int r    = lane >> 2;
    int cq   = lane & 3;

    uint32_t kBase = smem_u32(sK);
    uint32_t gBase = smem_u32(sG);

    auto stageK = [&](int s, int m0k) {
        #pragma unroll
        for (int j = 0; j < 4; j++) {
            int idx = tid + j*256;
            int row = idx >> 4, seg = idx & 15;
            cp16(kBase + (uint32_t)((s*KS_STAGE + row*KS_STR + seg*4)*4),
                 Pt + (size_t)(m0k + row)*CI + seg*8);
        }
    };
    auto stageG = [&](int s, int m0k) {
        #pragma unroll
        for (int j = 0; j < 4; j++) {
            int idx = tid + j*256;
            int row = idx >> 3, seg = idx & 7;
            cp16(gBase + (uint32_t)((s*GS_STAGE + row*GS_STR + seg*4)*4),
                 Gp + (size_t)row*NPIX + m0k + seg*8);
        }
    };

    #pragma unroll
    for (int j = 0; j < 8; j++) {
        int idx = tid + j*256;
        int row = idx >> 4, seg = idx & 15;
        cp16(kBase + (uint32_t)((row*KS_STR + seg*4)*4),
             Tt + (size_t)(n0 + row)*CI + seg*8);
    }
    cp_commit();
    cp_wait<0>();
    __syncthreads();

    unsigned qa[8][4];
    #pragma unroll
    for (int ch = 0; ch < 8; ch++) {
        int ko = ch*8 + cq;
        qa[ch][0] = ldu(&sK[(qb + r)*KS_STR + ko]);
        qa[ch][1] = ldu(&sK[(qb + r + 8)*KS_STR + ko]);
        qa[ch][2] = ldu(&sK[(qb + r)*KS_STR + ko + 4]);
        qa[ch][3] = ldu(&sK[(qb + r + 8)*KS_STR + ko + 4]);
    }
    __syncthreads();

    stageK(0, 0); cp_commit();
    stageG(0, 0); cp_commit();

    float O[16][4];
    #pragma unroll
    for (int i = 0; i < 16; i++)
        #pragma unroll
        for (int j = 0; j < 4; j++) O[i][j] = 0.f;
    float Mx0 = -1e30f, Mx1 = -1e30f, L0 = 0.f, L1 = 0.f;
    const unsigned FULL = 0xffffffffu;

    for (int t = 0; t < 64; t++) {
        int s = t & 1;
        int m0 = t * 64;

        if (t < 63) { stageK(s^1, m0 + 64); cp_commit(); cp_wait<2>(); }
        else        cp_wait<1>();
        __syncthreads();

        const float* Kt = sK + s*KS_STAGE;
        float S[8][4];
        #pragma unroll
        for (int i = 0; i < 8; i++)
            #pragma unroll
            for (int j = 0; j < 4; j++) S[i][j] = 0.f;

        #pragma unroll
        for (int ch = 0; ch < 8; ch++) {
            int ko = ch*8 + cq;
            #pragma unroll
            for (int nt = 0; nt < 8; nt++) {
                unsigned b0 = ldu(&Kt[(nt*8 + r)*KS_STR + ko]);
                unsigned b1 = ldu(&Kt[(nt*8 + r)*KS_STR + ko + 4]);
                mma_bf16(S[nt], qa[ch][0], qa[ch][1], qa[ch][2], qa[ch][3], b0, b1);
            }
        }

        float rm0 = -1e30f, rm1 = -1e30f;
        #pragma unroll
        for (int nt = 0; nt < 8; nt++) {
            rm0 = fmaxf(rm0, fmaxf(S[nt][0], S[nt][1]));
            rm1 = fmaxf(rm1, fmaxf(S[nt][2], S[nt][3]));
        }
        rm0 = fmaxf(rm0, __shfl_xor_sync(FULL, rm0, 1));
        rm0 = fmaxf(rm0, __shfl_xor_sync(FULL, rm0, 2));
        rm1 = fmaxf(rm1, __shfl_xor_sync(FULL, rm1, 1));
        rm1 = fmaxf(rm1, __shfl_xor_sync(FULL, rm1, 2));

        float nm0 = fmaxf(Mx0, rm0), nm1 = fmaxf(Mx1, rm1);
        float sc0 = __expf(Mx0 - nm0), sc1 = __expf(Mx1 - nm1);
        Mx0 = nm0; Mx1 = nm1;

        float rs0 = 0.f, rs1 = 0.f;
        #pragma unroll
        for (int nt = 0; nt < 8; nt++) {
            S[nt][0] = __expf(S[nt][0] - nm0);
            S[nt][1] = __expf(S[nt][1] - nm0);
            S[nt][2] = __expf(S[nt][2] - nm1);
            S[nt][3] = __expf(S[nt][3] - nm1);
            rs0 += S[nt][0] + S[nt][1];
            rs1 += S[nt][2] + S[nt][3];
        }
        rs0 += __shfl_xor_sync(FULL, rs0, 1);
        rs0 += __shfl_xor_sync(FULL, rs0, 2);
        rs1 += __shfl_xor_sync(FULL, rs1, 1);
        rs1 += __shfl_xor_sync(FULL, rs1, 2);
        L0 = L0*sc0 + rs0;
        L1 = L1*sc1 + rs1;

        if (!__all_sync(FULL, (sc0 == 1.f) & (sc1 == 1.f))) {
            #pragma unroll
            for (int i = 0; i < 16; i++) {
                O[i][0] *= sc0; O[i][1] *= sc0;
                O[i][2] *= sc1; O[i][3] *= sc1;
            }
        }

        unsigned pa[4][4];
        #pragma unroll
        for (int kc = 0; kc < 4; kc++) {
            pa[kc][0] = pack_bf(S[2*kc][1],   S[2*kc][0]);
            pa[kc][1] = pack_bf(S[2*kc][3],   S[2*kc][2]);
            pa[kc][2] = pack_bf(S[2*kc+1][1], S[2*kc+1][0]);
            pa[kc][3] = pack_bf(S[2*kc+1][3], S[2*kc+1][2]);
        }

        if (t < 63) { stageG(s^1, m0 + 64); cp_commit(); cp_wait<2>(); }
        else        cp_wait<0>();
        __syncthreads();

        const float* Gt = sG + s*GS_STAGE;
        #pragma unroll
        for (int kc = 0; kc < 4; kc++) {
            int ko = kc*8 + cq;
            #pragma unroll
            for (int ct = 0; ct < 16; ct++) {
                unsigned b0 = ldu(&Gt[(ct*8 + r)*GS_STR + ko]);
                unsigned b1 = ldu(&Gt[(ct*8 + r)*GS_STR + ko + 4]);
                mma_bf16(O[ct], pa[kc][0], pa[kc][1], pa[kc][2], pa[kc][3], b0, b1);
            }
        }
    }

    float inv0 = 1.0f / L0, inv1 = 1.0f / L1;
    int q = n0 + qb + r;
    #pragma unroll
    for (int ct = 0; ct < 16; ct++) {
        int kp = ct*4 + cq;
        Ybu[(size_t)kp*NPIX + q]     = pack_bf(O[ct][1]*inv0, O[ct][0]*inv0);
        Ybu[(size_t)kp*NPIX + q + 8] = pack_bf(O[ct][3]*inv1, O[ct][2]*inv1);
    }
}

// ---------------- final: out = GN2(z)*0.1 + xs ------------------------------------
__global__ void final_apply_kernel(const float* __restrict__ gw,
                                   const float* __restrict__ gb,
                                   float* __restrict__ out) {
    __shared__ float st[2];
    int bg = blockIdx.x >> 7;
    if (threadIdx.x == 0) {
        float S = 0.f, S2 = 0.f;
        #pragma unroll
        for (int i = 0; i < 16; i++) {
            S  += d_part2[(bg*16 + i)*2];
            S2 += d_part2[(bg*16 + i)*2 + 1];
        }
        float mean = S / (float)GSIZE;
        st[0] = mean;
        st[1] = rsqrtf(S2 / (float)GSIZE - mean*mean + EPSV);
    }
    __syncthreads();
    int i4 = blockIdx.x * blockDim.x + threadIdx.x;
    int idx = i4 << 2;
    int c   = (idx >> 12) & 255;
    float sc = st[1] * gw[c];
    float sh = gb[c] - st[0] * sc;
    float4 z = ((const float4*)d_z)[i4];
    float4 xs = ((const float4*)d_xs)[i4];
    float4 o;
    o.x = (z.x*sc + sh)*0.1f + xs.x;
    o.y = (z.y*sc + sh)*0.1f + xs.y;
    o.z = (z.z*sc + sh)*0.1f + xs.z;
    o.w = (z.w*sc + sh)*0.1f + xs.w;
    ((float4*)out)[i4] = o;
}

// ---------------- launch -----------------------------------------------------------
extern "C" void kernel_launch(void* const* d_in, const int* in_sizes, int n_in,
                              void* d_out, int out_size) {
    const float* x    = (const float*)d_in[0];
    const float* sw   = (const float*)d_in[1];
    const float* sb   = (const float*)d_in[2];
    const float* gn1w = (const float*)d_in[3];
    const float* gn1b = (const float*)d_in[4];
    const float* g_w  = (const float*)d_in[5];
    const float* g_b  = (const float*)d_in[6];
    const float* th_w = (const float*)d_in[7];
    const float* th_b = (const float*)d_in[8];
    const float* ph_w = (const float*)d_in[9];
    const float* ph_b = (const float*)d_in[10];
    const float* w_w  = (const float*)d_in[11];
    const float* w_b  = (const float*)d_in[12];
    const float* gn2w = (const float*)d_in[13];
    const float* gn2b = (const float*)d_in[14];
    float* out = (float*)d_out;

    static int attrSet = 0;
    if (!attrSet) {
        cudaFuncSetAttribute(conv_tc_kernel,
                             cudaFuncAttributeMaxDynamicSharedMemorySize, CONV_SMEM);
        cudaFuncSetAttribute(attention_tc_kernel,
                             cudaFuncAttributeMaxDynamicSharedMemorySize, ATTN_SMEM);
        attrSet = 1;
    }

    pack_w_bf_kernel<<<dim3(9, 256), 256>>>(sw);
    prep_x_kernel<<<dim3(128, 8, 4), dim3(32, 8)>>>(x);
    pack_qkvw_kernel<<<256, 256>>>(th_w, ph_w, g_w, w_w);
    conv_tc_kernel<<<dim3(32, 4), 256, CONV_SMEM>>>(sb);
    gn_part_kernel<<<512, 256>>>(0);
    gn1_apply_kernel<<<dim3(4, 128, 4), 256>>>(gn1w, gn1b);

    gemm_bf_kernel<0><<<dim3(32, 6, 4), 256>>>(th_b, ph_b, g_b);
    prep_attn_kernel<<<dim3(128, 4, 8), dim3(32, 8)>>>();

    attention_tc_kernel<<<dim3(32, 4), 256, ATTN_SMEM>>>();

    gemm_bf_kernel<3><<<dim3(32, 4, 4), 256>>>(w_b, nullptr, nullptr);
    gn_part_kernel<<<512, 256>>>(1);
    final_apply_kernel<<<4096, 256>>>(gn2w, gn2b, out);

    (void)in_sizes; (void)n_in; (void)out_size;
}

// round 12
// speedup vs baseline: 5.7781x; 1.0078x over previous
#include <cuda_runtime.h>
#include <cuda_bf16.h>
#include <math.h>
#include <stdint.h>

#define BATCH 4
#define CCH   256
#define CI    128
#define NPIX  4096
#define GROUPS 8
#define CPG   32
#define GSIZE (CPG*NPIX)
#define EPSV  1e-5f
#define KCONV 2304            // 9 taps * 256 cin, tap-major

// ---------------- scratch ----------------------------------------------------
__device__ float d_xs   [BATCH*CCH*NPIX];
__device__ float d_z    [BATCH*CCH*NPIX];
__device__ unsigned d_xsb[BATCH*128*NPIX];
__device__ unsigned d_yb [BATCH*64*NPIX];
__device__ unsigned d_wpk[65536];
__device__ __nv_bfloat16 d_wb [CCH*KCONV];
__device__ __nv_bfloat16 d_ws [CCH*KCONV];
__device__ __nv_bfloat16 d_xtb[BATCH*NPIX*CCH];
__device__ __nv_bfloat16 d_xts[BATCH*NPIX*CCH];
__device__ __nv_bfloat16 d_thb[BATCH*CI*NPIX];
__device__ __nv_bfloat16 d_phb[BATCH*CI*NPIX];
__device__ __nv_bfloat16 d_ttb[BATCH*NPIX*CI];
__device__ __nv_bfloat16 d_ptb[BATCH*NPIX*CI];
__device__ __nv_bfloat16 d_gb [BATCH*CI*NPIX];
__device__ float d_part1[32*16*2];
__device__ float d_part2[32*16*2];

// ---------------- helpers -----------------------------------------------------
__device__ __forceinline__ void mma_bf16(float* c,
    unsigned a0, unsigned a1, unsigned a2, unsigned a3,
    unsigned b0, unsigned b1) {
    asm volatile(
        "mma.sync.aligned.m16n8k16.row.col.f32.bf16.bf16.f32 "
        "{%0,%1,%2,%3}, {%4,%5,%6,%7}, {%8,%9}, {%0,%1,%2,%3};"
        : "+f"(c[0]), "+f"(c[1]), "+f"(c[2]), "+f"(c[3])
        : "r"(a0), "r"(a1), "r"(a2), "r"(a3), "r"(b0), "r"(b1));
}
__device__ __forceinline__ void ldsm4(unsigned* r, uint32_t a) {
    asm volatile("ldmatrix.sync.aligned.m8n8.x4.shared.b16 {%0,%1,%2,%3}, [%4];"
        : "=r"(r[0]), "=r"(r[1]), "=r"(r[2]), "=r"(r[3]) : "r"(a));
}
__device__ __forceinline__ unsigned pack_bf(float hi, float lo) {
    unsigned u;
    asm("cvt.rn.bf16x2.f32 %0, %1, %2;" : "=r"(u) : "f"(hi), "f"(lo));
    return u;
}
__device__ __forceinline__ void cp16(uint32_t dst, const void* src) {
    asm volatile("cp.async.cg.shared.global [%0], [%1], 16;" :: "r"(dst), "l"(src));
}
__device__ __forceinline__ void cp16z(uint32_t dst, const void* src, int srcsz) {
    asm volatile("cp.async.cg.shared.global [%0], [%1], 16, %2;"
                 :: "r"(dst), "l"(src), "r"(srcsz));
}
__device__ __forceinline__ void cp_commit() {
    asm volatile("cp.async.commit_group;");
}
template<int N>
__device__ __forceinline__ void cp_wait() {
    asm volatile("cp.async.wait_group %0;" :: "n"(N));
}
__device__ __forceinline__ uint32_t smem_u32(const void* p) {
    return (uint32_t)__cvta_generic_to_shared(p);
}
__device__ __forceinline__ unsigned ldu(const float* p) {
    return __float_as_uint(*p);
}

// ---------------- precompute: conv weight 2-term bf16 split --------------------
__global__ void pack_w_bf_kernel(const float* __restrict__ w) {
    int k = blockIdx.x * 256 + threadIdx.x;
    int m = blockIdx.y;
    int c = k & 255, tap = k >> 8;
    float f = w[m*(CCH*9) + c*9 + tap];
    __nv_bfloat16 big = __float2bfloat16(f);
    d_wb[(size_t)m*KCONV + k] = big;
    d_ws[(size_t)m*KCONV + k] = __float2bfloat16(f - __bfloat162float(big));
}

// ---------------- precompute: x transpose + split -> [b][pix][c] bf16 ---------
__global__ void prep_x_kernel(const float* __restrict__ x) {
    __shared__ float t[32][33];
    int b  = blockIdx.z;
    int p0 = blockIdx.x * 32;
    int c0 = blockIdx.y * 32;
    int tx = threadIdx.x, ty = threadIdx.y;
    #pragma unroll
    for (int i = 0; i < 4; i++)
        t[ty + i*8][tx] = x[(size_t)(b*CCH + c0 + ty + i*8)*NPIX + p0 + tx];
    __syncthreads();
    #pragma unroll
    for (int i = 0; i < 4; i++) {
        int p = ty + i*8;
        float f = t[tx][p];
        __nv_bfloat16 big = __float2bfloat16(f);
        size_t o = (size_t)(b*NPIX + p0 + p)*CCH + c0 + tx;
        d_xtb[o] = big;
        d_xts[o] = __float2bfloat16(f - __bfloat162float(big));
    }
}

// ---------------- precompute: pack qkv+w weights to bf16x2 k-pairs -------------
__global__ void pack_qkvw_kernel(const float* __restrict__ thw,
                                 const float* __restrict__ phw,
                                 const float* __restrict__ gw_,
                                 const float* __restrict__ ww) {
    int idx = blockIdx.x * 256 + threadIdx.x;
    const float* src;
    int off, loc, K;
    if (idx < 16384)      { src = thw; off = 0;     loc = idx;         K = 256; }
    else if (idx < 32768) { src = phw; off = 16384; loc = idx - 16384; K = 256; }
    else if (idx < 49152) { src = gw_; off = 32768; loc = idx - 32768; K = 256; }
    else                  { src = ww;  off = 49152; loc = idx - 49152; K = 128; }
    int kp = loc & (K/2 - 1);
    int m  = loc / (K/2);
    d_wpk[off + loc] = pack_bf(src[m*K + kp*2 + 1], src[m*K + kp*2]);
}

// ---------------- prep attention: transpose theta/phi bf16 -> [n][c] -----------
__global__ void prep_attn_kernel() {
    __shared__ __nv_bfloat16 t[32][34];
    int which = blockIdx.z & 1, b = blockIdx.z >> 1;
    const __nv_bfloat16* src = (which ? d_phb : d_thb) + (size_t)b*CI*NPIX;
    __nv_bfloat16* dst = (which ? d_ptb : d_ttb) + (size_t)b*NPIX*CI;
    int n0 = blockIdx.x * 32, c0 = blockIdx.y * 32;
    int tx = threadIdx.x, ty = threadIdx.y;
    #pragma unroll
    for (int i = 0; i < 4; i++)
        t[ty + i*8][tx] = src[(size_t)(c0 + ty + i*8)*NPIX + n0 + tx];
    __syncthreads();
    #pragma unroll
    for (int i = 0; i < 4; i++) {
        int n = ty + i*8;
        dst[(size_t)(n0 + n)*CI + c0 + tx] = t[tx][n];
    }
}

// ---------------- conv3x3 implicit GEMM, bf16 2-term, ldmatrix fragments -------
#define CV_ROW 36
#define CA_PLANE (256*CV_ROW)
#define CB_PLANE (128*CV_ROW)
#define CV_STAGE (2*CA_PLANE + 2*CB_PLANE)
#define CONV_SMEM (2*CV_STAGE*4)              // 221184 bytes

__global__ void __launch_bounds__(256, 1) conv_tc_kernel(const float* __restrict__ sb) {
    extern __shared__ float smem[];

    int b    = blockIdx.y;
    int pix0 = blockIdx.x * 128;
    int h0   = pix0 >> 6;

    int tid  = threadIdx.x;
    int lane = tid & 31;
    int wid  = tid >> 5;
    int wm = wid >> 1, wn = wid & 1;     // 4m x 2n warps, warp tile 64x64
    int r  = lane >> 2, cq = lane & 3;

    uint32_t base = smem_u32(smem);

    // ldmatrix lane->address maps
    int aRowOff = (lane & 7) + ((lane >> 3) & 1) * 8;  // A: q={kh? no: m-block at q&1}
    int aKh     = lane >> 4;                           // A: k 16B-half at q>>1
    int bRowOff = (lane & 7) + ((lane >> 4) & 1) * 8;  // B: n-block at q>>1
    int bKh     = (lane >> 3) & 1;                     // B: k 16B-half at q&1

    float C[32][4];
    #pragma unroll
    for (int i = 0; i < 32; i++)
        #pragma unroll
        for (int j = 0; j < 4; j++) C[i][j] = 0.f;

    auto stage = [&](int st, int kc) {
        int tap = kc >> 8;
        int c0  = kc & 255;
        int ky  = tap/3 - 1;
        int kx  = tap - (tap/3)*3 - 1;
        uint32_t sb0 = base + (uint32_t)(st*CV_STAGE*4);
        #pragma unroll
        for (int j = 0; j < 16; j++) {
            int idx = tid + j*256;
            int p   = idx >> 11;
            int rem = idx & 2047;
            int row = rem >> 3;
            int seg = rem & 7;
            const __nv_bfloat16* wsrc = (p ? d_ws : d_wb)
                + (size_t)row*KCONV + kc + seg*8;
            cp16(sb0 + (uint32_t)((p*CA_PLANE + row*CV_ROW + seg*4)*4), wsrc);
        }
        #pragma unroll
        for (int j = 0; j < 8; j++) {
            int idx = tid + j*256;
            int p   = idx >> 10;
            int rem = idx & 1023;
            int row = rem >> 3;
            int seg = rem & 7;
            int h = h0 + (row >> 6) + ky;
            int w = (row & 63) + kx;
            int valid = ((unsigned)h < 64u) & ((unsigned)w < 64u);
            int pix = valid ? (h*64 + w) : 0;
            const __nv_bfloat16* xsrc = (p ? d_xts : d_xtb)
                + (size_t)(b*NPIX + pix)*CCH + c0 + seg*8;
            cp16z(sb0 + (uint32_t)((2*CA_PLANE + p*CB_PLANE + row*CV_ROW + seg*4)*4),
                  xsrc, valid ? 16 : 0);
        }
    };

    stage(0, 0);
    cp_commit();

    for (int it = 0; it < 36; it++) {
        if (it < 35) { stage((it+1) & 1, (it+1)*64); cp_commit(); cp_wait<1>(); }
        else cp_wait<0>();
        __syncthreads();

        uint32_t St  = base + (uint32_t)((it & 1)*CV_STAGE*4);
        uint32_t sAb = St;
        uint32_t sAm = St + CA_PLANE*4;
        uint32_t sBb = St + 2*CA_PLANE*4;
        uint32_t sBm = St + (2*CA_PLANE + CB_PLANE)*4;

        #pragma unroll
        for (int ch = 0; ch < 4; ch++) {
            unsigned ab[4][4], as_[4][4];
            #pragma unroll
            for (int mt = 0; mt < 4; mt++) {
                uint32_t off = (uint32_t)(((wm*64 + mt*16 + aRowOff)*CV_ROW
                                           + ch*8 + aKh*4)*4);
                ldsm4(ab[mt],  sAb + off);
                ldsm4(as_[mt], sAm + off);
            }
            unsigned bb[8][2], bs[8][2];
            #pragma unroll
            for (int np = 0; np < 4; np++) {
                uint32_t off = (uint32_t)(((wn*64 + np*16 + bRowOff)*CV_ROW
                                           + ch*8 + bKh*4)*4);
                unsigned t[4];
                ldsm4(t, sBb + off);
                bb[np*2][0] = t[0]; bb[np*2][1] = t[1];
                bb[np*2+1][0] = t[2]; bb[np*2+1][1] = t[3];
                ldsm4(t, sBm + off);
                bs[np*2][0] = t[0]; bs[np*2][1] = t[1];
                bs[np*2+1][0] = t[2]; bs[np*2+1][1] = t[3];
            }
            // pass 1: big*big
            #pragma unroll
            for (int mt = 0; mt < 4; mt++)
                #pragma unroll
                for (int nt = 0; nt < 8; nt++)
                    mma_bf16(C[mt*8+nt], ab[mt][0], ab[mt][1], ab[mt][2], ab[mt][3],
                             bb[nt][0], bb[nt][1]);
            // pass 2: big*small
            #pragma unroll
            for (int mt = 0; mt < 4; mt++)
                #pragma unroll
                for (int nt = 0; nt < 8; nt++)
                    mma_bf16(C[mt*8+nt], ab[mt][0], ab[mt][1], ab[mt][2], ab[mt][3],
                             bs[nt][0], bs[nt][1]);
            // pass 3: small*big
            #pragma unroll
            for (int mt = 0; mt < 4; mt++)
                #pragma unroll
                for (int nt = 0; nt < 8; nt++)
                    mma_bf16(C[mt*8+nt], as_[mt][0], as_[mt][1], as_[mt][2], as_[mt][3],
                             bb[nt][0], bb[nt][1]);
        }
        __syncthreads();
    }

    #pragma unroll
    for (int mt = 0; mt < 4; mt++) {
        int m = wm*64 + mt*16 + r;
        float bv0 = sb[m], bv8 = sb[m + 8];
        #pragma unroll
        for (int nt = 0; nt < 8; nt++) {
            int n = pix0 + wn*64 + nt*8 + 2*cq;
            float* cf = C[mt*8 + nt];
            *(float2*)&d_xs[((size_t)(b*CCH + m))*NPIX + n]     = make_float2(cf[0]+bv0, cf[1]+bv0);
            *(float2*)&d_xs[((size_t)(b*CCH + m + 8))*NPIX + n] = make_float2(cf[2]+bv8, cf[3]+bv8);
        }
    }
}

// ---------------- GroupNorm partial sums ----------------------------------------
__global__ void gn_part_kernel(int which) {
    const float* src = which ? d_z : d_xs;
    float* part      = which ? d_part2 : d_part1;
    int blk = blockIdx.x;
    int bg = blk >> 4, ch = blk & 15;
    const float4* p = (const float4*)(src + (size_t)bg*GSIZE + ch*(GSIZE/16));
    float s = 0.f, s2 = 0.f;
    #pragma unroll
    for (int i = 0; i < 8; i++) {
        float4 v = p[threadIdx.x + i*256];
        s  += v.x + v.y + v.z + v.w;
        s2 += v.x*v.x + v.y*v.y + v.z*v.z + v.w*v.w;
    }
    #pragma unroll
    for (int off = 16; off > 0; off >>= 1) {
        s  += __shfl_xor_sync(0xffffffffu, s,  off);
        s2 += __shfl_xor_sync(0xffffffffu, s2, off);
    }
    __shared__ float sh[16];
    int wid = threadIdx.x >> 5, lid = threadIdx.x & 31;
    if (lid == 0) { sh[wid] = s; sh[wid + 8] = s2; }
    __syncthreads();
    if (threadIdx.x == 0) {
        float S = 0.f, S2 = 0.f;
        #pragma unroll
        for (int w = 0; w < 8; w++) { S += sh[w]; S2 += sh[w + 8]; }
        part[blk*2]     = S;
        part[blk*2 + 1] = S2;
    }
}

// ---------------- GN1 apply + ReLU ----------------------------------------------
__global__ void gn1_apply_kernel(const float* __restrict__ gw,
                                 const float* __restrict__ gb) {
    __shared__ float st[2];
    int b  = blockIdx.z;
    int kp = blockIdx.y;
    int c  = kp << 1;
    int bg = b*8 + (kp >> 4);
    if (threadIdx.x == 0) {
        float S = 0.f, S2 = 0.f;
        #pragma unroll
        for (int i = 0; i < 16; i++) {
            S  += d_part1[(bg*16 + i)*2];
            S2 += d_part1[(bg*16 + i)*2 + 1];
        }
        float mean = S / (float)GSIZE;
        st[0] = mean;
        st[1] = rsqrtf(S2 / (float)GSIZE - mean*mean + EPSV);
    }
    __syncthreads();
    float sc0 = st[1] * gw[c],   sh0 = gb[c]   - st[0]*sc0;
    float sc1 = st[1] * gw[c+1], sh1 = gb[c+1] - st[0]*sc1;
    int n = blockIdx.x*1024 + threadIdx.x*4;
    size_t base = ((size_t)(b*CCH + c))*NPIX + n;
    float4 v0 = *(float4*)&d_xs[base];
    float4 v1 = *(float4*)&d_xs[base + NPIX];
    v0.x = fmaxf(v0.x*sc0 + sh0, 0.f); v0.y = fmaxf(v0.y*sc0 + sh0, 0.f);
    v0.z = fmaxf(v0.z*sc0 + sh0, 0.f); v0.w = fmaxf(v0.w*sc0 + sh0, 0.f);
    v1.x = fmaxf(v1.x*sc1 + sh1, 0.f); v1.y = fmaxf(v1.y*sc1 + sh1, 0.f);
    v1.z = fmaxf(v1.z*sc1 + sh1, 0.f); v1.w = fmaxf(v1.w*sc1 + sh1, 0.f);
    *(float4*)&d_xs[base]        = v0;
    *(float4*)&d_xs[base + NPIX] = v1;
    uint4 pk;
    pk.x = pack_bf(v1.x, v0.x);
    pk.y = pack_bf(v1.y, v0.y);
    pk.z = pack_bf(v1.z, v0.z);
    pk.w = pack_bf(v1.w, v0.w);
    *(uint4*)&d_xsb[((size_t)(b*128 + kp))*NPIX + n] = pk;
}

// ---------------- bf16 1x1 GEMM (unchanged) ---------------------------------------
template<int MODE>
__global__ void __launch_bounds__(256) gemm_bf_kernel(const float* __restrict__ bias0,
                                                      const float* __restrict__ bias1,
                                                      const float* __restrict__ bias2) {
    constexpr int K  = (MODE == 3) ? 128 : 256;
    constexpr int KP = K / 2;
    constexpr int NI = K / 32;
    const unsigned* Wp = d_wpk + (MODE == 3 ? 49152 : 0);
    const unsigned* Xall = (MODE == 3) ? d_yb : d_xsb;

    __shared__ unsigned Ws[2][64*20];
    __shared__ unsigned Xs[2][16*132];

    int b  = blockIdx.z;
    int n0 = blockIdx.x * 128;
    int m0 = blockIdx.y * 64;
    const unsigned* Xb = Xall + (size_t)b * KP * NPIX;

    int tid  = threadIdx.x;
    int lane = tid & 31;
    int wid  = tid >> 5;
    int wm = wid >> 2, wn = wid & 3;
    int r  = lane >> 2, cq = lane & 3;

    int wRow = tid >> 2, wSeg = tid & 3;
    int xRow = tid >> 5, xSeg = tid & 31;
    uint32_t wBase = smem_u32(Ws);
    uint32_t xBase = smem_u32(Xs);

    auto stage = [&](int s, int it) {
        int kp0 = it * 16;
        cp16(wBase + (uint32_t)((s*64*20 + wRow*20 + wSeg*4)*4),
             Wp + (size_t)(m0 + wRow)*KP + kp0 + wSeg*4);
        #pragma unroll
        for (int j = 0; j < 2; j++) {
            int k = xRow + j*8;
            cp16(xBase + (uint32_t)((s*16*132 + k*132 + xSeg*4)*4),
                 Xb + (size_t)(kp0 + k)*NPIX + n0 + xSeg*4);
        }
    };

    float C[8][4];
    #pragma unroll
    for (int i = 0; i < 8; i++)
        #pragma unroll
        for (int j = 0; j < 4; j++) C[i][j] = 0.f;

    stage(0, 0);
    cp_commit();

    for (int it = 0; it < NI; it++) {
        if (it < NI-1) { stage((it+1)&1, it+1); cp_commit(); cp_wait<1>(); }
        else cp_wait<0>();
        __syncthreads();

        const unsigned* Wt = Ws[it & 1];
        const unsigned* Xt = Xs[it & 1];

        #pragma unroll
        for (int ch = 0; ch < 2; ch++) {
            int ko = ch*8 + cq;
            unsigned a[2][4];
            #pragma unroll
            for (int mt = 0; mt < 2; mt++) {
                int mr = wm*32 + mt*16 + r;
                a[mt][0] = Wt[mr*20 + ko];
                a[mt][1] = Wt[(mr+8)*20 + ko];
                a[mt][2] = Wt[mr*20 + ko + 4];
                a[mt][3] = Wt[(mr+8)*20 + ko + 4];
            }
            #pragma unroll
            for (int nt = 0; nt < 4; nt++) {
                int nn = wn*32 + nt*8 + r;
                unsigned b0 = Xt[ko*132 + nn];
                unsigned b1 = Xt[(ko+4)*132 + nn];
                mma_bf16(C[nt],     a[0][0], a[0][1], a[0][2], a[0][3], b0, b1);
                mma_bf16(C[4 + nt], a[1][0], a[1][1], a[1][2], a[1][3], b0, b1);
            }
        }
        __syncthreads();
    }

    const float* bias = (MODE == 3) ? bias0
                      : (m0 < 128 ? bias0 : m0 < 256 ? bias1 : bias2);
    int mbase = (MODE == 3) ? m0 : (m0 & 127);
    __nv_bfloat16* Obf = nullptr;
    if (MODE != 3)
        Obf = (m0 < 128 ? d_thb : m0 < 256 ? d_phb : d_gb) + (size_t)b * CI * NPIX;

    #pragma unroll
    for (int mt = 0; mt < 2; mt++) {
        int ml = mbase + wm*32 + mt*16 + r;
        float bv0 = bias[ml], bv8 = bias[ml + 8];
        #pragma unroll
        for (int nt = 0; nt < 4; nt++) {
            int n = n0 + wn*32 + nt*8 + 2*cq;
            float* cf = C[mt*4 + nt];
            if (MODE == 3) {
                float* Ob = d_z + (size_t)b * CCH * NPIX;
                *(float2*)&Ob[(size_t)ml*NPIX + n]     = make_float2(cf[0]+bv0, cf[1]+bv0);
                *(float2*)&Ob[(size_t)(ml+8)*NPIX + n] = make_float2(cf[2]+bv8, cf[3]+bv8);
            } else {
                *(unsigned*)&Obf[(size_t)ml*NPIX + n]     = pack_bf(cf[1]+bv0, cf[0]+bv0);
                *(unsigned*)&Obf[(size_t)(ml+8)*NPIX + n] = pack_bf(cf[3]+bv8, cf[2]+bv8);
            }
        }
    }
}

// ---------------- bf16 flash attention (unchanged) --------------------------------
#define KS_STR 68
#define KS_STAGE (64*KS_STR)
#define GS_STR 36
#define GS_STAGE (128*GS_STR)
#define ATTN_SMEM ((2*KS_STAGE + 2*GS_STAGE)*4)

__global__ void __launch_bounds__(256) attention_tc_kernel() {
    extern __shared__ float smem[];
    float* sK = smem;
    float* sG = smem + 2*KS_STAGE;

    int b  = blockIdx.y;
    int n0 = blockIdx.x * 128;
    const __nv_bfloat16* Tt = d_ttb + (size_t)b * NPIX * CI;
    const __nv_bfloat16* Pt = d_ptb + (size_t)b * NPIX * CI;
    const __nv_bfloat16* Gp = d_gb  + (size_t)b * CI * NPIX;
    unsigned* Ybu = d_yb + (size_t)b * 64 * NPIX;

    int tid  = threadIdx.x;
    int lane = tid & 31;
    int wid  = tid >> 5;
    int qb   = wid * 16;
    int r    = lane >> 2;
    int cq   = lane & 3;

    uint32_t kBase = smem_u32(sK);
    uint32_t gBase = smem_u32(sG);

    auto stageK = [&](int s, int m0k) {
        #pragma unroll
        for (int j = 0; j < 4; j++) {
            int idx = tid + j*256;
            int row = idx >> 4, seg = idx & 15;
            cp16(kBase + (uint32_t)((s*KS_STAGE + row*KS_STR + seg*4)*4),
                 Pt + (size_t)(m0k + row)*CI + seg*8);
        }
    };
    auto stageG = [&](int s, int m0k) {
        #pragma unroll
        for (int j = 0; j < 4; j++) {
            int idx = tid + j*256;
            int row = idx >> 3, seg = idx & 7;
            cp16(gBase + (uint32_t)((s*GS_STAGE + row*GS_STR + seg*4)*4),
                 Gp + (size_t)row*NPIX + m0k + seg*8);
        }
    };

    #pragma unroll
    for (int j = 0; j < 8; j++) {
        int idx = tid + j*256;
        int row = idx >> 4, seg = idx & 15;
        cp16(kBase + (uint32_t)((row*KS_STR + seg*4)*4),
             Tt + (size_t)(n0 + row)*CI + seg*8);
    }
    cp_commit();
    cp_wait<0>();
    __syncthreads();

    unsigned qa[8][4];
    #pragma unroll
    for (int ch = 0; ch < 8; ch++) {
        int ko = ch*8 + cq;
        qa[ch][0] = ldu(&sK[(qb + r)*KS_STR + ko]);
        qa[ch][1] = ldu(&sK[(qb + r + 8)*KS_STR + ko]);
        qa[ch][2] = ldu(&sK[(qb + r)*KS_STR + ko + 4]);
        qa[ch][3] = ldu(&sK[(qb + r + 8)*KS_STR + ko + 4]);
    }
    __syncthreads();

    stageK(0, 0); cp_commit();
    stageG(0, 0); cp_commit();

    float O[16][4];
    #pragma unroll
    for (int i = 0; i < 16; i++)
        #pragma unroll
        for (int j = 0; j < 4; j++) O[i][j] = 0.f;
    float Mx0 = -1e30f, Mx1 = -1e30f, L0 = 0.f, L1 = 0.f;
    const unsigned FULL = 0xffffffffu;

    for (int t = 0; t < 64; t++) {
        int s = t & 1;
        int m0 = t * 64;

        if (t < 63) { stageK(s^1, m0 + 64); cp_commit(); cp_wait<2>(); }
        else        cp_wait<1>();
        __syncthreads();

        const float* Kt = sK + s*KS_STAGE;
        float S[8][4];
        #pragma unroll
        for (int i = 0; i < 8; i++)
            #pragma unroll
            for (int j = 0; j < 4; j++) S[i][j] = 0.f;

        #pragma unroll
        for (int ch = 0; ch < 8; ch++) {
            int ko = ch*8 + cq;
            #pragma unroll
            for (int nt = 0; nt < 8; nt++) {
                unsigned b0 = ldu(&Kt[(nt*8 + r)*KS_STR + ko]);
                unsigned b1 = ldu(&Kt[(nt*8 + r)*KS_STR + ko + 4]);
                mma_bf16(S[nt], qa[ch][0], qa[ch][1], qa[ch][2], qa[ch][3], b0, b1);
            }
        }

        float rm0 = -1e30f, rm1 = -1e30f;
        #pragma unroll
        for (int nt = 0; nt < 8; nt++) {
            rm0 = fmaxf(rm0, fmaxf(S[nt][0], S[nt][1]));
            rm1 = fmaxf(rm1, fmaxf(S[nt][2], S[nt][3]));
        }
        rm0 = fmaxf(rm0, __shfl_xor_sync(FULL, rm0, 1));
        rm0 = fmaxf(rm0, __shfl_xor_sync(FULL, rm0, 2));
        rm1 = fmaxf(rm1, __shfl_xor_sync(FULL, rm1, 1));
        rm1 = fmaxf(rm1, __shfl_xor_sync(FULL, rm1, 2));

        float nm0 = fmaxf(Mx0, rm0), nm1 = fmaxf(Mx1, rm1);
        float sc0 = __expf(Mx0 - nm0), sc1 = __expf(Mx1 - nm1);
        Mx0 = nm0; Mx1 = nm1;

        float rs0 = 0.f, rs1 = 0.f;
        #pragma unroll
        for (int nt = 0; nt < 8; nt++) {
            S[nt][0] = __expf(S[nt][0] - nm0);
            S[nt][1] = __expf(S[nt][1] - nm0);
            S[nt][2] = __expf(S[nt][2] - nm1);
            S[nt][3] = __expf(S[nt][3] - nm1);
            rs0 += S[nt][0] + S[nt][1];
            rs1 += S[nt][2] + S[nt][3];
        }
        rs0 += __shfl_xor_sync(FULL, rs0, 1);
        rs0 += __shfl_xor_sync(FULL, rs0, 2);
        rs1 += __shfl_xor_sync(FULL, rs1, 1);
        rs1 += __shfl_xor_sync(FULL, rs1, 2);
        L0 = L0*sc0 + rs0;
        L1 = L1*sc1 + rs1;

        if (!__all_sync(FULL, (sc0 == 1.f) & (sc1 == 1.f))) {
            #pragma unroll
            for (int i = 0; i < 16; i++) {
                O[i][0] *= sc0; O[i][1] *= sc0;
                O[i][2] *= sc1; O[i][3] *= sc1;
            }
        }

        unsigned pa[4][4];
        #pragma unroll
        for (int kc = 0; kc < 4; kc++) {
            pa[kc][0] = pack_bf(S[2*kc][1],   S[2*kc][0]);
            pa[kc][1] = pack_bf(S[2*kc][3],   S[2*kc][2]);
            pa[kc][2] = pack_bf(S[2*kc+1][1], S[2*kc+1][0]);
            pa[kc][3] = pack_bf(S[2*kc+1][3], S[2*kc+1][2]);
        }

        if (t < 63) { stageG(s^1, m0 + 64); cp_commit(); cp_wait<2>(); }
        else        cp_wait<0>();
        __syncthreads();

        const float* Gt = sG + s*GS_STAGE;
        #pragma unroll
        for (int kc = 0; kc < 4; kc++) {
            int ko = kc*8 + cq;
            #pragma unroll
            for (int ct = 0; ct < 16; ct++) {
                unsigned b0 = ldu(&Gt[(ct*8 + r)*GS_STR + ko]);
                unsigned b1 = ldu(&Gt[(ct*8 + r)*GS_STR + ko + 4]);
                mma_bf16(O[ct], pa[kc][0], pa[kc][1], pa[kc][2], pa[kc][3], b0, b1);
            }
        }
    }

    float inv0 = 1.0f / L0, inv1 = 1.0f / L1;
    int q = n0 + qb + r;
    #pragma unroll
    for (int ct = 0; ct < 16; ct++) {
        int kp = ct*4 + cq;
        Ybu[(size_t)kp*NPIX + q]     = pack_bf(O[ct][1]*inv0, O[ct][0]*inv0);
        Ybu[(size_t)kp*NPIX + q + 8] = pack_bf(O[ct][3]*inv1, O[ct][2]*inv1);
    }
}

// ---------------- final: out = GN2(z)*0.1 + xs ------------------------------------
__global__ void final_apply_kernel(const float* __restrict__ gw,
                                   const float* __restrict__ gb,
                                   float* __restrict__ out) {
    __shared__ float st[2];
    int bg = blockIdx.x >> 7;
    if (threadIdx.x == 0) {
        float S = 0.f, S2 = 0.f;
        #pragma unroll
        for (int i = 0; i < 16; i++) {
            S  += d_part2[(bg*16 + i)*2];
            S2 += d_part2[(bg*16 + i)*2 + 1];
        }
        float mean = S / (float)GSIZE;
        st[0] = mean;
        st[1] = rsqrtf(S2 / (float)GSIZE - mean*mean + EPSV);
    }
    __syncthreads();
    int i4 = blockIdx.x * blockDim.x + threadIdx.x;
    int idx = i4 << 2;
    int c   = (idx >> 12) & 255;
    float sc = st[1] * gw[c];
    float sh = gb[c] - st[0] * sc;
    float4 z = ((const float4*)d_z)[i4];
    float4 xs = ((const float4*)d_xs)[i4];
    float4 o;
    o.x = (z.x*sc + sh)*0.1f + xs.x;
    o.y = (z.y*sc + sh)*0.1f + xs.y;
    o.z = (z.z*sc + sh)*0.1f + xs.z;
    o.w = (z.w*sc + sh)*0.1f + xs.w;
    ((float4*)out)[i4] = o;
}

// ---------------- launch -----------------------------------------------------------
extern "C" void kernel_launch(void* const* d_in, const int* in_sizes, int n_in,
                              void* d_out, int out_size) {
    const float* x    = (const float*)d_in[0];
    const float* sw   = (const float*)d_in[1];
    const float* sb   = (const float*)d_in[2];
    const float* gn1w = (const float*)d_in[3];
    const float* gn1b = (const float*)d_in[4];
    const float* g_w  = (const float*)d_in[5];
    const float* g_b  = (const float*)d_in[6];
    const float* th_w = (const float*)d_in[7];
    const float* th_b = (const float*)d_in[8];
    const float* ph_w = (const float*)d_in[9];
    const float* ph_b = (const float*)d_in[10];
    const float* w_w  = (const float*)d_in[11];
    const float* w_b  = (const float*)d_in[12];
    const float* gn2w = (const float*)d_in[13];
    const float* gn2b = (const float*)d_in[14];
    float* out = (float*)d_out;

    static int attrSet = 0;
    if (!attrSet) {
        cudaFuncSetAttribute(conv_tc_kernel,
                             cudaFuncAttributeMaxDynamicSharedMemorySize, CONV_SMEM);
        cudaFuncSetAttribute(attention_tc_kernel,
                             cudaFuncAttributeMaxDynamicSharedMemorySize, ATTN_SMEM);
        attrSet = 1;
    }

    pack_w_bf_kernel<<<dim3(9, 256), 256>>>(sw);
    prep_x_kernel<<<dim3(128, 8, 4), dim3(32, 8)>>>(x);
    pack_qkvw_kernel<<<256, 256>>>(th_w, ph_w, g_w, w_w);
    conv_tc_kernel<<<dim3(32, 4), 256, CONV_SMEM>>>(sb);
    gn_part_kernel<<<512, 256>>>(0);
    gn1_apply_kernel<<<dim3(4, 128, 4), 256>>>(gn1w, gn1b);

    gemm_bf_kernel<0><<<dim3(32, 6, 4), 256>>>(th_b, ph_b, g_b);
    prep_attn_kernel<<<dim3(128, 4, 8), dim3(32, 8)>>>();

    attention_tc_kernel<<<dim3(32, 4), 256, ATTN_SMEM>>>();

    gemm_bf_kernel<3><<<dim3(32, 4, 4), 256>>>(w_b, nullptr, nullptr);
    gn_part_kernel<<<512, 256>>>(1);
    final_apply_kernel<<<4096, 256>>>(gn2w, gn2b, out);

    (void)in_sizes; (void)n_in; (void)out_size;
}

// round 13
// speedup vs baseline: 5.7935x; 1.0027x over previous
#include <cuda_runtime.h>
#include <cuda_bf16.h>
#include <math.h>
#include <stdint.h>

#define BATCH 4
#define CCH   256
#define CI    128
#define NPIX  4096
#define GROUPS 8
#define CPG   32
#define GSIZE (CPG*NPIX)
#define EPSV  1e-5f
#define KCONV 2304

// ---------------- scratch ----------------------------------------------------
__device__ float d_xs   [BATCH*CCH*NPIX];
__device__ float d_z    [BATCH*CCH*NPIX];
__device__ unsigned d_xsb[BATCH*128*NPIX];
__device__ unsigned d_yb [BATCH*64*NPIX];
__device__ unsigned d_wpk[65536];
__device__ __nv_bfloat16 d_wb [CCH*KCONV];
__device__ __nv_bfloat16 d_ws [CCH*KCONV];
__device__ __nv_bfloat16 d_xtb[BATCH*NPIX*CCH];
__device__ __nv_bfloat16 d_xts[BATCH*NPIX*CCH];
__device__ __nv_bfloat16 d_thb[BATCH*CI*NPIX];
__device__ __nv_bfloat16 d_phb[BATCH*CI*NPIX];
__device__ __nv_bfloat16 d_ttb[BATCH*NPIX*CI];
__device__ __nv_bfloat16 d_ptb[BATCH*NPIX*CI];
__device__ __nv_bfloat16 d_gb [BATCH*CI*NPIX];
__device__ float d_part1[32*16*2];
__device__ float d_part2[32*16*2];

// ---------------- helpers -----------------------------------------------------
__device__ __forceinline__ void mma_bf16(float* c,
    unsigned a0, unsigned a1, unsigned a2, unsigned a3,
    unsigned b0, unsigned b1) {
    asm volatile(
        "mma.sync.aligned.m16n8k16.row.col.f32.bf16.bf16.f32 "
        "{%0,%1,%2,%3}, {%4,%5,%6,%7}, {%8,%9}, {%0,%1,%2,%3};"
        : "+f"(c[0]), "+f"(c[1]), "+f"(c[2]), "+f"(c[3])
        : "r"(a0), "r"(a1), "r"(a2), "r"(a3), "r"(b0), "r"(b1));
}
__device__ __forceinline__ unsigned pack_bf(float hi, float lo) {
    unsigned u;
    asm("cvt.rn.bf16x2.f32 %0, %1, %2;" : "=r"(u) : "f"(hi), "f"(lo));
    return u;
}
__device__ __forceinline__ void cp16(uint32_t dst, const void* src) {
    asm volatile("cp.async.cg.shared.global [%0], [%1], 16;" :: "r"(dst), "l"(src));
}
__device__ __forceinline__ void cp16z(uint32_t dst, const void* src, int srcsz) {
    asm volatile("cp.async.cg.shared.global [%0], [%1], 16, %2;"
                 :: "r"(dst), "l"(src), "r"(srcsz));
}
__device__ __forceinline__ void cp_commit() {
    asm volatile("cp.async.commit_group;");
}
template<int N>
__device__ __forceinline__ void cp_wait() {
    asm volatile("cp.async.wait_group %0;" :: "n"(N));
}
__device__ __forceinline__ uint32_t smem_u32(const void* p) {
    return (uint32_t)__cvta_generic_to_shared(p);
}
__device__ __forceinline__ unsigned ldu(const float* p) {
    return __float_as_uint(*p);
}

// ---------------- precompute: conv weight 2-term bf16 split --------------------
__global__ void pack_w_bf_kernel(const float* __restrict__ w) {
    int k = blockIdx.x * 256 + threadIdx.x;
    int m = blockIdx.y;
    int c = k & 255, tap = k >> 8;
    float f = w[m*(CCH*9) + c*9 + tap];
    __nv_bfloat16 big = __float2bfloat16(f);
    d_wb[(size_t)m*KCONV + k] = big;
    d_ws[(size_t)m*KCONV + k] = __float2bfloat16(f - __bfloat162float(big));
}

// ---------------- precompute: x transpose + split -> [b][pix][c] bf16 ---------
__global__ void prep_x_kernel(const float* __restrict__ x) {
    __shared__ float t[32][33];
    int b  = blockIdx.z;
    int p0 = blockIdx.x * 32;
    int c0 = blockIdx.y * 32;
    int tx = threadIdx.x, ty = threadIdx.y;
    #pragma unroll
    for (int i = 0; i < 4; i++)
        t[ty + i*8][tx] = x[(size_t)(b*CCH + c0 + ty + i*8)*NPIX + p0 + tx];
    __syncthreads();
    #pragma unroll
    for (int i = 0; i < 4; i++) {
        int p = ty + i*8;
        float f = t[tx][p];
        __nv_bfloat16 big = __float2bfloat16(f);
        size_t o = (size_t)(b*NPIX + p0 + p)*CCH + c0 + tx;
        d_xtb[o] = big;
        d_xts[o] = __float2bfloat16(f - __bfloat162float(big));
    }
}

// ---------------- precompute: pack qkv+w weights -------------------------------
__global__ void pack_qkvw_kernel(const float* __restrict__ thw,
                                 const float* __restrict__ phw,
                                 const float* __restrict__ gw_,
                                 const float* __restrict__ ww) {
    int idx = blockIdx.x * 256 + threadIdx.x;
    const float* src;
    int off, loc, K;
    if (idx < 16384)      { src = thw; off = 0;     loc = idx;         K = 256; }
    else if (idx < 32768) { src = phw; off = 16384; loc = idx - 16384; K = 256; }
    else if (idx < 49152) { src = gw_; off = 32768; loc = idx - 32768; K = 256; }
    else                  { src = ww;  off = 49152; loc = idx - 49152; K = 128; }
    int kp = loc & (K/2 - 1);
    int m  = loc / (K/2);
    d_wpk[off + loc] = pack_bf(src[m*K + kp*2 + 1], src[m*K + kp*2]);
}

// ---------------- prep attention: transpose theta/phi bf16 -> [n][c] -----------
__global__ void prep_attn_kernel() {
    __shared__ __nv_bfloat16 t[32][34];
    int which = blockIdx.z & 1, b = blockIdx.z >> 1;
    const __nv_bfloat16* src = (which ? d_phb : d_thb) + (size_t)b*CI*NPIX;
    __nv_bfloat16* dst = (which ? d_ptb : d_ttb) + (size_t)b*NPIX*CI;
    int n0 = blockIdx.x * 32, c0 = blockIdx.y * 32;
    int tx = threadIdx.x, ty = threadIdx.y;
    #pragma unroll
    for (int i = 0; i < 4; i++)
        t[ty + i*8][tx] = src[(size_t)(c0 + ty + i*8)*NPIX + n0 + tx];
    __syncthreads();
    #pragma unroll
    for (int i = 0; i < 4; i++) {
        int n = ty + i*8;
        dst[(size_t)(n0 + n)*CI + c0 + tx] = t[tx][n];
    }
}

// ---------------- conv3x3 implicit GEMM (R11 version: scalar LDS) --------------
#define CV_ROW 36
#define CA_PLANE (256*CV_ROW)
#define CB_PLANE (128*CV_ROW)
#define CV_STAGE (2*CA_PLANE + 2*CB_PLANE)
#define CONV_SMEM (2*CV_STAGE*4)

__global__ void __launch_bounds__(256, 1) conv_tc_kernel(const float* __restrict__ sb) {
    extern __shared__ float smem[];

    int b    = blockIdx.y;
    int pix0 = blockIdx.x * 128;
    int h0   = pix0 >> 6;

    int tid  = threadIdx.x;
    int lane = tid & 31;
    int wid  = tid >> 5;
    int wm = wid >> 1, wn = wid & 1;
    int r  = lane >> 2, cq = lane & 3;

    uint32_t base = smem_u32(smem);

    float C[32][4];
    #pragma unroll
    for (int i = 0; i < 32; i++)
        #pragma unroll
        for (int j = 0; j < 4; j++) C[i][j] = 0.f;

    auto stage = [&](int st, int kc) {
        int tap = kc >> 8;
        int c0  = kc & 255;
        int ky  = tap/3 - 1;
        int kx  = tap - (tap/3)*3 - 1;
        uint32_t sb0 = base + (uint32_t)(st*CV_STAGE*4);
        #pragma unroll
        for (int j = 0; j < 16; j++) {
            int idx = tid + j*256;
            int p   = idx >> 11;
            int rem = idx & 2047;
            int row = rem >> 3;
            int seg = rem & 7;
            const __nv_bfloat16* wsrc = (p ? d_ws : d_wb)
                + (size_t)row*KCONV + kc + seg*8;
            cp16(sb0 + (uint32_t)((p*CA_PLANE + row*CV_ROW + seg*4)*4), wsrc);
        }
        #pragma unroll
        for (int j = 0; j < 8; j++) {
            int idx = tid + j*256;
            int p   = idx >> 10;
            int rem = idx & 1023;
            int row = rem >> 3;
            int seg = rem & 7;
            int h = h0 + (row >> 6) + ky;
            int w = (row & 63) + kx;
            int valid = ((unsigned)h < 64u) & ((unsigned)w < 64u);
            int pix = valid ? (h*64 + w) : 0;
            const __nv_bfloat16* xsrc = (p ? d_xts : d_xtb)
                + (size_t)(b*NPIX + pix)*CCH + c0 + seg*8;
            cp16z(sb0 + (uint32_t)((2*CA_PLANE + p*CB_PLANE + row*CV_ROW + seg*4)*4),
                  xsrc, valid ? 16 : 0);
        }
    };

    stage(0, 0);
    cp_commit();

    for (int it = 0; it < 36; it++) {
        if (it < 35) { stage((it+1) & 1, (it+1)*64); cp_commit(); cp_wait<1>(); }
        else cp_wait<0>();
        __syncthreads();

        const float* St = smem + (it & 1)*CV_STAGE;
        const float* Ab = St;
        const float* Am = St + CA_PLANE;
        const float* Bb = St + 2*CA_PLANE;
        const float* Bm = St + 2*CA_PLANE + CB_PLANE;

        #pragma unroll
        for (int ch = 0; ch < 4; ch++) {
            int ko = ch*8 + cq;
            unsigned ab[4][4], as_[4][4];
            #pragma unroll
            for (int mt = 0; mt < 4; mt++) {
                int m = wm*64 + mt*16 + r;
                ab[mt][0] = ldu(&Ab[m*CV_ROW + ko]);
                ab[mt][1] = ldu(&Ab[(m+8)*CV_ROW + ko]);
                ab[mt][2] = ldu(&Ab[m*CV_ROW + ko + 4]);
                ab[mt][3] = ldu(&Ab[(m+8)*CV_ROW + ko + 4]);
                as_[mt][0] = ldu(&Am[m*CV_ROW + ko]);
                as_[mt][1] = ldu(&Am[(m+8)*CV_ROW + ko]);
                as_[mt][2] = ldu(&Am[m*CV_ROW + ko + 4]);
                as_[mt][3] = ldu(&Am[(m+8)*CV_ROW + ko + 4]);
            }
            unsigned bb[8][2], bs[8][2];
            #pragma unroll
            for (int nt = 0; nt < 8; nt++) {
                int n = wn*64 + nt*8 + r;
                bb[nt][0] = ldu(&Bb[n*CV_ROW + ko]);
                bb[nt][1] = ldu(&Bb[n*CV_ROW + ko + 4]);
                bs[nt][0] = ldu(&Bm[n*CV_ROW + ko]);
                bs[nt][1] = ldu(&Bm[n*CV_ROW + ko + 4]);
            }
            #pragma unroll
            for (int mt = 0; mt < 4; mt++)
                #pragma unroll
                for (int nt = 0; nt < 8; nt++)
                    mma_bf16(C[mt*8+nt], ab[mt][0], ab[mt][1], ab[mt][2], ab[mt][3],
                             bb[nt][0], bb[nt][1]);
            #pragma unroll
            for (int mt = 0; mt < 4; mt++)
                #pragma unroll
                for (int nt = 0; nt < 8; nt++)
                    mma_bf16(C[mt*8+nt], ab[mt][0], ab[mt][1], ab[mt][2], ab[mt][3],
                             bs[nt][0], bs[nt][1]);
            #pragma unroll
            for (int mt = 0; mt < 4; mt++)
                #pragma unroll
                for (int nt = 0; nt < 8; nt++)
                    mma_bf16(C[mt*8+nt], as_[mt][0], as_[mt][1], as_[mt][2], as_[mt][3],
                             bb[nt][0], bb[nt][1]);
        }
        __syncthreads();
    }

    #pragma unroll
    for (int mt = 0; mt < 4; mt++) {
        int m = wm*64 + mt*16 + r;
        float bv0 = sb[m], bv8 = sb[m + 8];
        #pragma unroll
        for (int nt = 0; nt < 8; nt++) {
            int n = pix0 + wn*64 + nt*8 + 2*cq;
            float* cf = C[mt*8 + nt];
            *(float2*)&d_xs[((size_t)(b*CCH + m))*NPIX + n]     = make_float2(cf[0]+bv0, cf[1]+bv0);
            *(float2*)&d_xs[((size_t)(b*CCH + m + 8))*NPIX + n] = make_float2(cf[2]+bv8, cf[3]+bv8);
        }
    }
}

// ---------------- GroupNorm partial sums ----------------------------------------
__global__ void gn_part_kernel(int which) {
    const float* src = which ? d_z : d_xs;
    float* part      = which ? d_part2 : d_part1;
    int blk = blockIdx.x;
    int bg = blk >> 4, ch = blk & 15;
    const float4* p = (const float4*)(src + (size_t)bg*GSIZE + ch*(GSIZE/16));
    float s = 0.f, s2 = 0.f;
    #pragma unroll
    for (int i = 0; i < 8; i++) {
        float4 v = p[threadIdx.x + i*256];
        s  += v.x + v.y + v.z + v.w;
        s2 += v.x*v.x + v.y*v.y + v.z*v.z + v.w*v.w;
    }
    #pragma unroll
    for (int off = 16; off > 0; off >>= 1) {
        s  += __shfl_xor_sync(0xffffffffu, s,  off);
        s2 += __shfl_xor_sync(0xffffffffu, s2, off);
    }
    __shared__ float sh[16];
    int wid = threadIdx.x >> 5, lid = threadIdx.x & 31;
    if (lid == 0) { sh[wid] = s; sh[wid + 8] = s2; }
    __syncthreads();
    if (threadIdx.x == 0) {
        float S = 0.f, S2 = 0.f;
        #pragma unroll
        for (int w = 0; w < 8; w++) { S += sh[w]; S2 += sh[w + 8]; }
        part[blk*2]     = S;
        part[blk*2 + 1] = S2;
    }
}

// ---------------- GN1 apply + ReLU ----------------------------------------------
__global__ void gn1_apply_kernel(const float* __restrict__ gw,
                                 const float* __restrict__ gb) {
    __shared__ float st[2];
    int b  = blockIdx.z;
    int kp = blockIdx.y;
    int c  = kp << 1;
    int bg = b*8 + (kp >> 4);
    if (threadIdx.x == 0) {
        float S = 0.f, S2 = 0.f;
        #pragma unroll
        for (int i = 0; i < 16; i++) {
            S  += d_part1[(bg*16 + i)*2];
            S2 += d_part1[(bg*16 + i)*2 + 1];
        }
        float mean = S / (float)GSIZE;
        st[0] = mean;
        st[1] = rsqrtf(S2 / (float)GSIZE - mean*mean + EPSV);
    }
    __syncthreads();
    float sc0 = st[1] * gw[c],   sh0 = gb[c]   - st[0]*sc0;
    float sc1 = st[1] * gw[c+1], sh1 = gb[c+1] - st[0]*sc1;
    int n = blockIdx.x*1024 + threadIdx.x*4;
    size_t base = ((size_t)(b*CCH + c))*NPIX + n;
    float4 v0 = *(float4*)&d_xs[base];
    float4 v1 = *(float4*)&d_xs[base + NPIX];
    v0.x = fmaxf(v0.x*sc0 + sh0, 0.f); v0.y = fmaxf(v0.y*sc0 + sh0, 0.f);
    v0.z = fmaxf(v0.z*sc0 + sh0, 0.f); v0.w = fmaxf(v0.w*sc0 + sh0, 0.f);
    v1.x = fmaxf(v1.x*sc1 + sh1, 0.f); v1.y = fmaxf(v1.y*sc1 + sh1, 0.f);
    v1.z = fmaxf(v1.z*sc1 + sh1, 0.f); v1.w = fmaxf(v1.w*sc1 + sh1, 0.f);
    *(float4*)&d_xs[base]        = v0;
    *(float4*)&d_xs[base + NPIX] = v1;
    uint4 pk;
    pk.x = pack_bf(v1.x, v0.x);
    pk.y = pack_bf(v1.y, v0.y);
    pk.z = pack_bf(v1.z, v0.z);
    pk.w = pack_bf(v1.w, v0.w);
    *(uint4*)&d_xsb[((size_t)(b*128 + kp))*NPIX + n] = pk;
}

// ---------------- bf16 1x1 GEMM (unchanged) ---------------------------------------
template<int MODE>
__global__ void __launch_bounds__(256) gemm_bf_kernel(const float* __restrict__ bias0,
                                                      const float* __restrict__ bias1,
                                                      const float* __restrict__ bias2) {
    constexpr int K  = (MODE == 3) ? 128 : 256;
    constexpr int KP = K / 2;
    constexpr int NI = K / 32;
    const unsigned* Wp = d_wpk + (MODE == 3 ? 49152 : 0);
    const unsigned* Xall = (MODE == 3) ? d_yb : d_xsb;

    __shared__ unsigned Ws[2][64*20];
    __shared__ unsigned Xs[2][16*132];

    int b  = blockIdx.z;
    int n0 = blockIdx.x * 128;
    int m0 = blockIdx.y * 64;
    const unsigned* Xb = Xall + (size_t)b * KP * NPIX;

    int tid  = threadIdx.x;
    int lane = tid & 31;
    int wid  = tid >> 5;
    int wm = wid >> 2, wn = wid & 3;
    int r  = lane >> 2, cq = lane & 3;

    int wRow = tid >> 2, wSeg = tid & 3;
    int xRow = tid >> 5, xSeg = tid & 31;
    uint32_t wBase = smem_u32(Ws);
    uint32_t xBase = smem_u32(Xs);

    auto stage = [&](int s, int it) {
        int kp0 = it * 16;
        cp16(wBase + (uint32_t)((s*64*20 + wRow*20 + wSeg*4)*4),
             Wp + (size_t)(m0 + wRow)*KP + kp0 + wSeg*4);
        #pragma unroll
        for (int j = 0; j < 2; j++) {
            int k = xRow + j*8;
            cp16(xBase + (uint32_t)((s*16*132 + k*132 + xSeg*4)*4),
                 Xb + (size_t)(kp0 + k)*NPIX + n0 + xSeg*4);
        }
    };

    float C[8][4];
    #pragma unroll
    for (int i = 0; i < 8; i++)
        #pragma unroll
        for (int j = 0; j < 4; j++) C[i][j] = 0.f;

    stage(0, 0);
    cp_commit();

    for (int it = 0; it < NI; it++) {
        if (it < NI-1) { stage((it+1)&1, it+1); cp_commit(); cp_wait<1>(); }
        else cp_wait<0>();
        __syncthreads();

        const unsigned* Wt = Ws[it & 1];
        const unsigned* Xt = Xs[it & 1];

        #pragma unroll
        for (int ch = 0; ch < 2; ch++) {
            int ko = ch*8 + cq;
            unsigned a[2][4];
            #pragma unroll
            for (int mt = 0; mt < 2; mt++) {
                int mr = wm*32 + mt*16 + r;
                a[mt][0] = Wt[mr*20 + ko];
                a[mt][1] = Wt[(mr+8)*20 + ko];
                a[mt][2] = Wt[mr*20 + ko + 4];
                a[mt][3] = Wt[(mr+8)*20 + ko + 4];
            }
            #pragma unroll
            for (int nt = 0; nt < 4; nt++) {
                int nn = wn*32 + nt*8 + r;
                unsigned b0 = Xt[ko*132 + nn];
                unsigned b1 = Xt[(ko+4)*132 + nn];
                mma_bf16(C[nt],     a[0][0], a[0][1], a[0][2], a[0][3], b0, b1);
                mma_bf16(C[4 + nt], a[1][0], a[1][1], a[1][2], a[1][3], b0, b1);
            }
        }
        __syncthreads();
    }

    const float* bias = (MODE == 3) ? bias0
                      : (m0 < 128 ? bias0 : m0 < 256 ? bias1 : bias2);
    int mbase = (MODE == 3) ? m0 : (m0 & 127);
    __nv_bfloat16* Obf = nullptr;
    if (MODE != 3)
        Obf = (m0 < 128 ? d_thb : m0 < 256 ? d_phb : d_gb) + (size_t)b * CI * NPIX;

    #pragma unroll
    for (int mt = 0; mt < 2; mt++) {
        int ml = mbase + wm*32 + mt*16 + r;
        float bv0 = bias[ml], bv8 = bias[ml + 8];
        #pragma unroll
        for (int nt = 0; nt < 4; nt++) {
            int n = n0 + wn*32 + nt*8 + 2*cq;
            float* cf = C[mt*4 + nt];
            if (MODE == 3) {
                float* Ob = d_z + (size_t)b * CCH * NPIX;
                *(float2*)&Ob[(size_t)ml*NPIX + n]     = make_float2(cf[0]+bv0, cf[1]+bv0);
                *(float2*)&Ob[(size_t)(ml+8)*NPIX + n] = make_float2(cf[2]+bv8, cf[3]+bv8);
            } else {
                *(unsigned*)&Obf[(size_t)ml*NPIX + n]     = pack_bf(cf[1]+bv0, cf[0]+bv0);
                *(unsigned*)&Obf[(size_t)(ml+8)*NPIX + n] = pack_bf(cf[3]+bv8, cf[2]+bv8);
            }
        }
    }
}

// ---------------- bf16 flash attention: 64-q tiles, 128 threads, 2 blocks/SM -----
#define KS_STR 68
#define KS_STAGE (64*KS_STR)
#define GS_STR 36
#define GS_STAGE (128*GS_STR)
#define ATTN_SMEM ((2*KS_STAGE + 2*GS_STAGE)*4)   // 71680 B

__global__ void __launch_bounds__(128, 2) attention_tc_kernel() {
    extern __shared__ float smem[];
    float* sK = smem;
    float* sG = smem + 2*KS_STAGE;

    int b  = blockIdx.y;
    int n0 = blockIdx.x * 64;
    const __nv_bfloat16* Tt = d_ttb + (size_t)b * NPIX * CI;
    const __nv_bfloat16* Pt = d_ptb + (size_t)b * NPIX * CI;
    const __nv_bfloat16* Gp = d_gb  + (size_t)b * CI * NPIX;
    unsigned* Ybu = d_yb + (size_t)b * 64 * NPIX;

    int tid  = threadIdx.x;
    int lane = tid & 31;
    int wid  = tid >> 5;          // 0..3
    int qb   = wid * 16;
    int r    = lane >> 2;
    int cq   = lane & 3;

    uint32_t kBase = smem_u32(sK);
    uint32_t gBase = smem_u32(sG);

    auto stageK = [&](int s, int m0k) {
        #pragma unroll
        for (int j = 0; j < 8; j++) {
            int idx = tid + j*128;
            int row = idx >> 4, seg = idx & 15;
            cp16(kBase + (uint32_t)((s*KS_STAGE + row*KS_STR + seg*4)*4),
                 Pt + (size_t)(m0k + row)*CI + seg*8);
        }
    };
    auto stageG = [&](int s, int m0k) {
        #pragma unroll
        for (int j = 0; j < 8; j++) {
            int idx = tid + j*128;
            int row = idx >> 3, seg = idx & 7;
            cp16(gBase + (uint32_t)((s*GS_STAGE + row*GS_STR + seg*4)*4),
                 Gp + (size_t)row*NPIX + m0k + seg*8);
        }
    };

    // ---- Q prologue: 64 rows x 16 segs into sK stage 0 ----
    #pragma unroll
    for (int j = 0; j < 8; j++) {
        int idx = tid + j*128;
        int row = idx >> 4, seg = idx & 15;
        cp16(kBase + (uint32_t)((row*KS_STR + seg*4)*4),
             Tt + (size_t)(n0 + row)*CI + seg*8);
    }
    cp_commit();
    cp_wait<0>();
    __syncthreads();

    unsigned qa[8][4];
    #pragma unroll
    for (int ch = 0; ch < 8; ch++) {
        int ko = ch*8 + cq;
        qa[ch][0] = ldu(&sK[(qb + r)*KS_STR + ko]);
        qa[ch][1] = ldu(&sK[(qb + r + 8)*KS_STR + ko]);
        qa[ch][2] = ldu(&sK[(qb + r)*KS_STR + ko + 4]);
        qa[ch][3] = ldu(&sK[(qb + r + 8)*KS_STR + ko + 4]);
    }
    __syncthreads();

    stageK(0, 0); cp_commit();
    stageG(0, 0); cp_commit();

    float O[16][4];
    #pragma unroll
    for (int i = 0; i < 16; i++)
        #pragma unroll
        for (int j = 0; j < 4; j++) O[i][j] = 0.f;
    float Mx0 = -1e30f, Mx1 = -1e30f, L0 = 0.f, L1 = 0.f;
    const unsigned FULL = 0xffffffffu;

    for (int t = 0; t < 64; t++) {
        int s = t & 1;
        int m0 = t * 64;

        if (t < 63) { stageK(s^1, m0 + 64); cp_commit(); cp_wait<2>(); }
        else        cp_wait<1>();
        __syncthreads();

        const float* Kt = sK + s*KS_STAGE;
        float S[8][4];
        #pragma unroll
        for (int i = 0; i < 8; i++)
            #pragma unroll
            for (int j = 0; j < 4; j++) S[i][j] = 0.f;

        #pragma unroll
        for (int ch = 0; ch < 8; ch++) {
            int ko = ch*8 + cq;
            #pragma unroll
            for (int nt = 0; nt < 8; nt++) {
                unsigned b0 = ldu(&Kt[(nt*8 + r)*KS_STR + ko]);
                unsigned b1 = ldu(&Kt[(nt*8 + r)*KS_STR + ko + 4]);
                mma_bf16(S[nt], qa[ch][0], qa[ch][1], qa[ch][2], qa[ch][3], b0, b1);
            }
        }

        float rm0 = -1e30f, rm1 = -1e30f;
        #pragma unroll
        for (int nt = 0; nt < 8; nt++) {
            rm0 = fmaxf(rm0, fmaxf(S[nt][0], S[nt][1]));
            rm1 = fmaxf(rm1, fmaxf(S[nt][2], S[nt][3]));
        }
        rm0 = fmaxf(rm0, __shfl_xor_sync(FULL, rm0, 1));
        rm0 = fmaxf(rm0, __shfl_xor_sync(FULL, rm0, 2));
        rm1 = fmaxf(rm1, __shfl_xor_sync(FULL, rm1, 1));
        rm1 = fmaxf(rm1, __shfl_xor_sync(FULL, rm1, 2));

        float nm0 = fmaxf(Mx0, rm0), nm1 = fmaxf(Mx1, rm1);
        float sc0 = __expf(Mx0 - nm0), sc1 = __expf(Mx1 - nm1);
        Mx0 = nm0; Mx1 = nm1;

        float rs0 = 0.f, rs1 = 0.f;
        #pragma unroll
        for (int nt = 0; nt < 8; nt++) {
            S[nt][0] = __expf(S[nt][0] - nm0);
            S[nt][1] = __expf(S[nt][1] - nm0);
            S[nt][2] = __expf(S[nt][2] - nm1);
            S[nt][3] = __expf(S[nt][3] - nm1);
            rs0 += S[nt][0] + S[nt][1];
            rs1 += S[nt][2] + S[nt][3];
        }
        rs0 += __shfl_xor_sync(FULL, rs0, 1);
        rs0 += __shfl_xor_sync(FULL, rs0, 2);
        rs1 += __shfl_xor_sync(FULL, rs1, 1);
        rs1 += __shfl_xor_sync(FULL, rs1, 2);
        L0 = L0*sc0 + rs0;
        L1 = L1*sc1 + rs1;

        if (!__all_sync(FULL, (sc0 == 1.f) & (sc1 == 1.f))) {
            #pragma unroll
            for (int i = 0; i < 16; i++) {
                O[i][0] *= sc0; O[i][1] *= sc0;
                O[i][2] *= sc1; O[i][3] *= sc1;
            }
        }

        unsigned pa[4][4];
        #pragma unroll
        for (int kc = 0; kc < 4; kc++) {
            pa[kc][0] = pack_bf(S[2*kc][1],   S[2*kc][0]);
            pa[kc][1] = pack_bf(S[2*kc][3],   S[2*kc][2]);
            pa[kc][2] = pack_bf(S[2*kc+1][1], S[2*kc+1][0]);
            pa[kc][3] = pack_bf(S[2*kc+1][3], S[2*kc+1][2]);
        }

        if (t < 63) { stageG(s^1, m0 + 64); cp_commit(); cp_wait<2>(); }
        else        cp_wait<0>();
        __syncthreads();

        const float* Gt = sG + s*GS_STAGE;
        #pragma unroll
        for (int kc = 0; kc < 4; kc++) {
            int ko = kc*8 + cq;
            #pragma unroll
            for (int ct = 0; ct < 16; ct++) {
                unsigned b0 = ldu(&Gt[(ct*8 + r)*GS_STR + ko]);
                unsigned b1 = ldu(&Gt[(ct*8 + r)*GS_STR + ko + 4]);
                mma_bf16(O[ct], pa[kc][0], pa[kc][1], pa[kc][2], pa[kc][3], b0, b1);
            }
        }
    }

    float inv0 = 1.0f / L0, inv1 = 1.0f / L1;
    int q = n0 + qb + r;
    #pragma unroll
    for (int ct = 0; ct < 16; ct++) {
        int kp = ct*4 + cq;
        Ybu[(size_t)kp*NPIX + q]     = pack_bf(O[ct][1]*inv0, O[ct][0]*inv0);
        Ybu[(size_t)kp*NPIX + q + 8] = pack_bf(O[ct][3]*inv1, O[ct][2]*inv1);
    }
}

// ---------------- final: out = GN2(z)*0.1 + xs ------------------------------------
__global__ void final_apply_kernel(const float* __restrict__ gw,
                                   const float* __restrict__ gb,
                                   float* __restrict__ out) {
    __shared__ float st[2];
    int bg = blockIdx.x >> 7;
    if (threadIdx.x == 0) {
        float S = 0.f, S2 = 0.f;
        #pragma unroll
        for (int i = 0; i < 16; i++) {
            S  += d_part2[(bg*16 + i)*2];
            S2 += d_part2[(bg*16 + i)*2 + 1];
        }
        float mean = S / (float)GSIZE;
        st[0] = mean;
        st[1] = rsqrtf(S2 / (float)GSIZE - mean*mean + EPSV);
    }
    __syncthreads();
    int i4 = blockIdx.x * blockDim.x + threadIdx.x;
    int idx = i4 << 2;
    int c   = (idx >> 12) & 255;
    float sc = st[1] * gw[c];
    float sh = gb[c] - st[0] * sc;
    float4 z = ((const float4*)d_z)[i4];
    float4 xs = ((const float4*)d_xs)[i4];
    float4 o;
    o.x = (z.x*sc + sh)*0.1f + xs.x;
    o.y = (z.y*sc + sh)*0.1f + xs.y;
    o.z = (z.z*sc + sh)*0.1f + xs.z;
    o.w = (z.w*sc + sh)*0.1f + xs.w;
    ((float4*)out)[i4] = o;
}

// ---------------- launch -----------------------------------------------------------
extern "C" void kernel_launch(void* const* d_in, const int* in_sizes, int n_in,
                              void* d_out, int out_size) {
    const float* x    = (const float*)d_in[0];
    const float* sw   = (const float*)d_in[1];
    const float* sb   = (const float*)d_in[2];
    const float* gn1w = (const float*)d_in[3];
    const float* gn1b = (const float*)d_in[4];
    const float* g_w  = (const float*)d_in[5];
    const float* g_b  = (const float*)d_in[6];
    const float* th_w = (const float*)d_in[7];
    const float* th_b = (const float*)d_in[8];
    const float* ph_w = (const float*)d_in[9];
    const float* ph_b = (const float*)d_in[10];
    const float* w_w  = (const float*)d_in[11];
    const float* w_b  = (const float*)d_in[12];
    const float* gn2w = (const float*)d_in[13];
    const float* gn2b = (const float*)d_in[14];
    float* out = (float*)d_out;

    static int attrSet = 0;
    if (!attrSet) {
        cudaFuncSetAttribute(conv_tc_kernel,
                             cudaFuncAttributeMaxDynamicSharedMemorySize, CONV_SMEM);
        cudaFuncSetAttribute(attention_tc_kernel,
                             cudaFuncAttributeMaxDynamicSharedMemorySize, ATTN_SMEM);
        attrSet = 1;
    }

    pack_w_bf_kernel<<<dim3(9, 256), 256>>>(sw);
    prep_x_kernel<<<dim3(128, 8, 4), dim3(32, 8)>>>(x);
    pack_qkvw_kernel<<<256, 256>>>(th_w, ph_w, g_w, w_w);
    conv_tc_kernel<<<dim3(32, 4), 256, CONV_SMEM>>>(sb);
    gn_part_kernel<<<512, 256>>>(0);
    gn1_apply_kernel<<<dim3(4, 128, 4), 256>>>(gn1w, gn1b);

    gemm_bf_kernel<0><<<dim3(32, 6, 4), 256>>>(th_b, ph_b, g_b);
    prep_attn_kernel<<<dim3(128, 4, 8), dim3(32, 8)>>>();

    attention_tc_kernel<<<dim3(64, 4), 128, ATTN_SMEM>>>();

    gemm_bf_kernel<3><<<dim3(32, 4, 4), 256>>>(w_b, nullptr, nullptr);
    gn_part_kernel<<<512, 256>>>(1);
    final_apply_kernel<<<4096, 256>>>(gn2w, gn2b, out);

    (void)in_sizes; (void)n_in; (void)out_size;
}